// round 9
// baseline (speedup 1.0000x reference)
#include <cuda_runtime.h>
#include <cstdint>

#define NG    15135
#define BSZ   8
#define FIN   64
#define HD    128
#define KTOP  7568
#define MROWS (NG*BSZ)
#define HF    512
#define SORTN 16384
#define MAXD  256
#define KSPL  60
#define NB    148
#define SGB   64

__device__ float g_xT  [(size_t)NG*BSZ*FIN];
__device__ float g_bufA[(size_t)NG*BSZ*HD];
__device__ float g_bufB[(size_t)NG*BSZ*HD];
__device__ float g_bufC[(size_t)NG*BSZ*HD];
__device__ int   g_degcnt[NG];
__device__ int   g_rowptr[NG+1];
__device__ int   g_cursor[NG];
__device__ int   g_eid[300000];
__device__ int   g_col[300000];
__device__ float g_w  [300000];
__device__ float g_dinv[NG];
__device__ float g_sp [BSZ*NG];
__device__ float g_fd [BSZ*NG];
__device__ float g_z  [BSZ*KTOP];
__device__ float g_hpart[KSPL][BSZ*HF];
__device__ float g_hpre[BSZ*HF];
__device__ float g_invw;
__device__ unsigned long long g_keys[BSZ][SORTN];
__device__ unsigned g_bar_cnt = 0;
__device__ unsigned g_bar_gen = 0;

// ---------- packed f32x2 (FFMA2) ----------
__device__ __forceinline__ void upk2(unsigned long long v, float& lo, float& hi)
{
    asm("mov.b64 {%0,%1},%2;" : "=f"(lo), "=f"(hi) : "l"(v));
}
__device__ __forceinline__ void ffma2(unsigned long long& d, unsigned long long a,
                                      unsigned long long b)
{
    asm("fma.rn.f32x2 %0, %1, %2, %0;" : "+l"(d) : "l"(a), "l"(b));
}

// ---------- streaming / async copies ----------
__device__ __forceinline__ float4 ldg_cs4(const float4* p)
{
    float4 v;
    asm("ld.global.cs.v4.f32 {%0,%1,%2,%3},[%4];"
        : "=f"(v.x), "=f"(v.y), "=f"(v.z), "=f"(v.w) : "l"(p));
    return v;
}
__device__ __forceinline__ void stg_cs4(float4* p, float4 v)
{
    asm volatile("st.global.cs.v4.f32 [%0],{%1,%2,%3,%4};"
                 :: "l"(p), "f"(v.x), "f"(v.y), "f"(v.z), "f"(v.w));
}
__device__ __forceinline__ void cpa16(unsigned dst, const void* src)
{
    asm volatile("cp.async.cg.shared.global [%0], [%1], 16;" :: "r"(dst), "l"(src));
}
__device__ __forceinline__ void cpa_commit()
{
    asm volatile("cp.async.commit_group;" ::: "memory");
}
__device__ __forceinline__ void cpa_wait0()
{
    asm volatile("cp.async.wait_group 0;" ::: "memory");
}

// ---------- grid-wide barrier ----------
__device__ __forceinline__ void gsync(unsigned nb)
{
    __syncthreads();
    if (threadIdx.x == 0) {
        unsigned g = *(volatile unsigned*)&g_bar_gen;
        __threadfence();
        unsigned a = atomicAdd(&g_bar_cnt, 1u);
        if (a == nb - 1u) {
            g_bar_cnt = 0;
            __threadfence();
            *(volatile unsigned*)&g_bar_gen = g + 1u;
        } else {
            while (*(volatile unsigned*)&g_bar_gen == g) { }
        }
        __threadfence();
    }
    __syncthreads();
}

__global__ void k_nop() { }

// ---------- fused graph prep ----------
__global__ void __launch_bounds__(256) k_prep(const float* __restrict__ x,
                                              const int* __restrict__ ei,
                                              const float* __restrict__ tw, int E)
{
    int t = threadIdx.x, bid = blockIdx.x;
    int gt = bid*256 + t, gs = NB*256;

    for (int i = gt; i < BSZ*NG; i += gs) { g_sp[i] = 0.f; g_fd[i] = 0.f; }
    for (int i = gt; i < NG; i += gs)     { g_degcnt[i] = 0; g_cursor[i] = 0; }

    if (bid == NB-1) {
        __shared__ float red[256];
        float w0 = tw[t];
        float v = w0*w0;
        if (t < 128) { float w1 = tw[t+256]; v += w1*w1; }
        red[t] = v;
        __syncthreads();
        for (int off = 128; off; off >>= 1) { if (t < off) red[t] += red[t+off]; __syncthreads(); }
        if (t == 0) g_invw = rsqrtf(red[0]);
    }

    for (int idx = gt; idx < NG*BSZ*FIN; idx += gs) {
        int n = idx >> 9, r = idx & 511, b = r >> 6, f = r & 63;
        g_xT[idx] = x[((size_t)b*NG + n)*FIN + f];
    }
    gsync(NB);

    for (int e = gt; e < E; e += gs) atomicAdd(&g_degcnt[ei[E + e]], 1);
    gsync(NB);

    for (int i = gt; i < NG; i += gs) g_dinv[i] = rsqrtf((float)(g_degcnt[i] + 1));

    if (bid == 0) {
        const int C = (NG + 255)/256;
        __shared__ int ws[8];
        int base = t*C, s = 0;
        for (int i = 0; i < C; i++) { int k2 = base+i; if (k2 < NG) s += g_degcnt[k2]; }
        int lane = t & 31, w = t >> 5, v = s;
        for (int off = 1; off < 32; off <<= 1) {
            int n2 = __shfl_up_sync(0xffffffffu, v, off);
            if (lane >= off) v += n2;
        }
        if (lane == 31) ws[w] = v;
        __syncthreads();
        if (t == 0) {
            int a = 0;
            for (int i2 = 0; i2 < 8; i2++) { int tm = ws[i2]; ws[i2] = a; a += tm; }
            g_rowptr[NG] = a;
        }
        __syncthreads();
        int run = v - s + ws[w];
        for (int i = 0; i < C; i++) {
            int k2 = base+i;
            if (k2 < NG) { g_rowptr[k2] = run; run += g_degcnt[k2]; }
        }
    }
    gsync(NB);

    for (int e = gt; e < E; e += gs) {
        int d = ei[E + e];
        g_eid[g_rowptr[d] + atomicAdd(&g_cursor[d], 1)] = e;
    }
    gsync(NB);

    for (int n = gt; n < NG; n += gs) {
        int e0 = g_rowptr[n], deg = g_rowptr[n+1] - e0;
        for (int i = 1; i < deg; i++) {
            int key = g_eid[e0+i], j = i - 1;
            while (j >= 0 && g_eid[e0+j] > key) { g_eid[e0+j+1] = g_eid[e0+j]; j--; }
            g_eid[e0+j+1] = key;
        }
        float dn = g_dinv[n];
        for (int i = 0; i < deg; i++) {
            int e = g_eid[e0+i], s2 = ei[e];
            g_col[e0+i] = s2;
            g_w [e0+i]  = dn * g_dinv[s2];
        }
    }
}

// ---------- SpMM ----------
template<int FB>
__global__ void __launch_bounds__(FB/4) k_spmm(const float* __restrict__ in,
                                               float* __restrict__ out)
{
    __shared__ int   scol[MAXD];
    __shared__ float swt [MAXD];
    int n = blockIdx.x, t = threadIdx.x;
    int e0 = g_rowptr[n], e1 = g_rowptr[n+1];
    int deg = e1 - e0;
    int dstage = deg < MAXD ? deg : MAXD;
    for (int i = t; i < dstage; i += FB/4) { scol[i] = g_col[e0+i]; swt[i] = g_w[e0+i]; }
    __syncthreads();

    float dn = g_dinv[n];
    float wl = dn * dn;
    float4 v = __ldg((const float4*)(in + (size_t)n*FB) + t);
    float4 acc = make_float4(wl*v.x, wl*v.y, wl*v.z, wl*v.w);

    int i = 0;
    for (; i + 1 < dstage; i += 2) {
        int s0 = scol[i], s1 = scol[i+1];
        float w0 = swt[i], w1 = swt[i+1];
        float4 u0 = __ldg((const float4*)(in + (size_t)s0*FB) + t);
        float4 u1 = __ldg((const float4*)(in + (size_t)s1*FB) + t);
        acc.x = fmaf(w0,u0.x,acc.x); acc.y = fmaf(w0,u0.y,acc.y);
        acc.z = fmaf(w0,u0.z,acc.z); acc.w = fmaf(w0,u0.w,acc.w);
        acc.x = fmaf(w1,u1.x,acc.x); acc.y = fmaf(w1,u1.y,acc.y);
        acc.z = fmaf(w1,u1.z,acc.z); acc.w = fmaf(w1,u1.w,acc.w);
    }
    for (; i < dstage; i++) {
        int s0 = scol[i]; float w0 = swt[i];
        float4 u0 = __ldg((const float4*)(in + (size_t)s0*FB) + t);
        acc.x = fmaf(w0,u0.x,acc.x); acc.y = fmaf(w0,u0.y,acc.y);
        acc.z = fmaf(w0,u0.z,acc.z); acc.w = fmaf(w0,u0.w,acc.w);
    }
    for (int e = e0 + MAXD; e < e1; e++) {
        int s0 = g_col[e]; float w0 = g_w[e];
        float4 u0 = __ldg((const float4*)(in + (size_t)s0*FB) + t);
        acc.x = fmaf(w0,u0.x,acc.x); acc.y = fmaf(w0,u0.y,acc.y);
        acc.z = fmaf(w0,u0.z,acc.z); acc.w = fmaf(w0,u0.w,acc.w);
    }
    stg_cs4((float4*)(out + (size_t)n*FB) + t, acc);
}

// ---------- GEMM: duplicated-pair A smem (no pack MOVs), swizzled B ping-pong, FFMA2 ----------
#define LDB(f, kk, cur) do { \
    const char* _br = (const char*)&Bs[cur][kk][0]; \
    ulonglong2 _b0 = *(const ulonglong2*)(_br + swb0); \
    ulonglong2 _b1 = *(const ulonglong2*)(_br + swb1); \
    bp[f][0]=_b0.x; bp[f][1]=_b0.y; bp[f][2]=_b1.x; bp[f][3]=_b1.y; \
} while(0)

template<int KDIM, bool WRITEC>
__global__ void __launch_bounds__(256, 2) k_gemm(const float* __restrict__ A,
                                                 const float* __restrict__ W,
                                                 const float* __restrict__ bias,
                                                 float* __restrict__ C,
                                                 const float* __restrict__ tw,
                                                 const float* __restrict__ fw, int l)
{
    __shared__ float2 Asd[2][16][132];  // [k][m] duplicated pairs (a,a)
    __shared__ float  Bs [2][16][128];  // [k][j], 16B-granule XOR swizzle
    const int tid = threadIdx.x;
    const int bm  = blockIdx.x * 128;
    const int tx  = tid & 15, ty = tid >> 4;
    const int arow = tid >> 1, akc = (tid & 1) * 8;
    const int brow = tid >> 4, bgr  = (tid & 15) * 2;

    const int swb0 = (( 2*tx   ) ^ (( 2*tx   ) >> 3)) * 16;
    const int swb1 = (( 2*tx+1 ) ^ (( 2*tx+1 ) >> 3)) * 16;
    const int bgs0 = (bgr ^ (bgr >> 3)) * 16;
    const int bgs1 = ((bgr+1) ^ ((bgr+1) >> 3)) * 16;

    unsigned long long acc2[8][4];
#pragma unroll
    for (int i = 0; i < 8; i++)
#pragma unroll
        for (int j = 0; j < 4; j++) acc2[i][j] = 0ull;

    int am = bm + arow;
    if (am >= MROWS) am = MROWS - 1;   // clamp; masked in epilogue
    const float* Aptr = A + (size_t)am*KDIM + akc;
    const float* Wptr = W + (size_t)brow*HD + bgr*4;
    unsigned brow_sm[2];
    brow_sm[0] = (unsigned)__cvta_generic_to_shared(&Bs[0][brow][0]);
    brow_sm[1] = (unsigned)__cvta_generic_to_shared(&Bs[1][brow][0]);

    // stage tile 0
    {
        float4 va0 = ldg_cs4((const float4*)Aptr);
        float4 va1 = ldg_cs4((const float4*)(Aptr+4));
        cpa16(brow_sm[0]+bgs0, Wptr);
        cpa16(brow_sm[0]+bgs1, Wptr+4);
        cpa_commit();
        Asd[0][akc+0][arow]=make_float2(va0.x,va0.x);
        Asd[0][akc+1][arow]=make_float2(va0.y,va0.y);
        Asd[0][akc+2][arow]=make_float2(va0.z,va0.z);
        Asd[0][akc+3][arow]=make_float2(va0.w,va0.w);
        Asd[0][akc+4][arow]=make_float2(va1.x,va1.x);
        Asd[0][akc+5][arow]=make_float2(va1.y,va1.y);
        Asd[0][akc+6][arow]=make_float2(va1.z,va1.z);
        Asd[0][akc+7][arow]=make_float2(va1.w,va1.w);
        cpa_wait0();
    }
    __syncthreads();

    unsigned long long bp[2][4];
    LDB(0, 0, 0);

    const int ntiles = KDIM/16;
    for (int t = 0; t < ntiles; t++) {
        const int cur = t & 1, nxt = cur ^ 1;
        const bool pf = (t + 1 < ntiles);
        float4 va0, va1;
        if (pf) {
            const float* ap2 = Aptr + (t+1)*16;
            va0 = ldg_cs4((const float4*)ap2);
            va1 = ldg_cs4((const float4*)(ap2+4));
            const float* wp2 = Wptr + (size_t)(t+1)*16*HD;
            cpa16(brow_sm[nxt]+bgs0, wp2);
            cpa16(brow_sm[nxt]+bgs1, wp2+4);
            cpa_commit();
        }
#pragma unroll
        for (int kk = 0; kk < 16; kk++) {
            const int f = kk & 1;
            if (kk < 15) LDB(f^1, kk+1, cur);
            const ulonglong2* ar = (const ulonglong2*)&Asd[cur][kk][ty*8];
            ulonglong2 p0 = ar[0], p1 = ar[1], p2 = ar[2], p3 = ar[3];
#pragma unroll
            for (int j = 0; j < 4; j++) ffma2(acc2[0][j], p0.x, bp[f][j]);
#pragma unroll
            for (int j = 0; j < 4; j++) ffma2(acc2[1][j], p0.y, bp[f][j]);
#pragma unroll
            for (int j = 0; j < 4; j++) ffma2(acc2[2][j], p1.x, bp[f][j]);
#pragma unroll
            for (int j = 0; j < 4; j++) ffma2(acc2[3][j], p1.y, bp[f][j]);
#pragma unroll
            for (int j = 0; j < 4; j++) ffma2(acc2[4][j], p2.x, bp[f][j]);
#pragma unroll
            for (int j = 0; j < 4; j++) ffma2(acc2[5][j], p2.y, bp[f][j]);
#pragma unroll
            for (int j = 0; j < 4; j++) ffma2(acc2[6][j], p3.x, bp[f][j]);
#pragma unroll
            for (int j = 0; j < 4; j++) ffma2(acc2[7][j], p3.y, bp[f][j]);
        }
        if (pf) {
            Asd[nxt][akc+0][arow]=make_float2(va0.x,va0.x);
            Asd[nxt][akc+1][arow]=make_float2(va0.y,va0.y);
            Asd[nxt][akc+2][arow]=make_float2(va0.z,va0.z);
            Asd[nxt][akc+3][arow]=make_float2(va0.w,va0.w);
            Asd[nxt][akc+4][arow]=make_float2(va1.x,va1.x);
            Asd[nxt][akc+5][arow]=make_float2(va1.y,va1.y);
            Asd[nxt][akc+6][arow]=make_float2(va1.z,va1.z);
            Asd[nxt][akc+7][arow]=make_float2(va1.w,va1.w);
            cpa_wait0();
            __syncthreads();
            LDB(0, 0, nxt);
        }
    }

    float bv[8], twv[8], fwv[8];
#pragma unroll
    for (int j = 0; j < 8; j++) {
        int f = tx*8 + j;
        bv[j]  = bias[f];
        twv[j] = tw[f*3 + l];
        fwv[j] = fw[f*3 + l];
    }
#pragma unroll
    for (int i = 0; i < 8; i++) {
        int m = bm + ty*8 + i;
        float vj[8];
#pragma unroll
        for (int j = 0; j < 4; j++) {
            float lo, hi;
            upk2(acc2[i][j], lo, hi);
            vj[2*j]   = fmaxf(lo + bv[2*j],   0.f);
            vj[2*j+1] = fmaxf(hi + bv[2*j+1], 0.f);
        }
        float a = 0.f, c = 0.f;
#pragma unroll
        for (int j = 0; j < 8; j++) { a = fmaf(vj[j], twv[j], a); c = fmaf(vj[j], fwv[j], c); }
#pragma unroll
        for (int off = 8; off; off >>= 1) {
            a += __shfl_down_sync(0xffffffffu, a, off, 16);
            c += __shfl_down_sync(0xffffffffu, c, off, 16);
        }
        if (m < MROWS) {
            if (WRITEC) {
                *(float4*)(C + (size_t)m*HD + tx*8 + 0) = make_float4(vj[0],vj[1],vj[2],vj[3]);
                *(float4*)(C + (size_t)m*HD + tx*8 + 4) = make_float4(vj[4],vj[5],vj[6],vj[7]);
            }
            if (tx == 0) {
                int n = m >> 3, b = m & 7;
                g_sp[b*NG + n] += a;
                g_fd[b*NG + n] += c;
            }
        }
    }
}

// ---------- multi-block bitonic sort + z ----------
__global__ void __launch_bounds__(256) k_sortz(const float* __restrict__ fcb)
{
    __shared__ unsigned long long sk[2048];
    int bid = blockIdx.x;
    int b = bid >> 3, sub = bid & 7;
    int t = threadIdx.x;
    int base = sub * 2048;
    float invw = g_invw;

    for (int q = 0; q < 8; q++) {
        int li = q*256 + t, gi = base + li;
        unsigned long long key = 0xFFFFFFFFFFFFFFFFull;
        if (gi < NG) {
            float s = tanhf(g_sp[b*NG + gi] * invw);
            unsigned u = __float_as_uint(s);
            u = (u & 0x80000000u) ? ~u : (u | 0x80000000u);
            key = ((unsigned long long)(~u) << 32) | (unsigned)gi;
        }
        sk[li] = key;
    }
    __syncthreads();

    for (unsigned k = 2; k <= 2048; k <<= 1) {
        for (unsigned j = k >> 1; j > 0; j >>= 1) {
            for (int q = 0; q < 8; q++) {
                int li = q*256 + t;
                unsigned lixj = li ^ j;
                if (lixj > (unsigned)li) {
                    unsigned long long x = sk[li], y = sk[lixj];
                    bool up = (((base + li) & k) == 0);
                    if ((x > y) == up) { sk[li] = y; sk[lixj] = x; }
                }
            }
            __syncthreads();
        }
    }
    for (int q = 0; q < 8; q++) { int li = q*256 + t; g_keys[b][base + li] = sk[li]; }
    gsync(SGB);

    for (unsigned k = 4096; k <= 16384; k <<= 1) {
        for (unsigned j = k >> 1; j >= 2048; j >>= 1) {
            for (int q = 0; q < 8; q++) {
                int i = bid*256 + t;
                int bb = q;
                int ixj = i ^ j;
                if (ixj > i) {
                    unsigned long long x = g_keys[bb][i], y = g_keys[bb][ixj];
                    bool up = ((i & k) == 0);
                    if ((x > y) == up) { g_keys[bb][i] = y; g_keys[bb][ixj] = x; }
                }
            }
            gsync(SGB);
        }
        for (int q = 0; q < 8; q++) { int li = q*256 + t; sk[li] = g_keys[b][base + li]; }
        __syncthreads();
        for (unsigned j = 1024; j > 0; j >>= 1) {
            for (int q = 0; q < 8; q++) {
                int li = q*256 + t;
                unsigned lixj = li ^ j;
                if (lixj > (unsigned)li) {
                    unsigned long long x = sk[li], y = sk[lixj];
                    bool up = (((base + li) & k) == 0);
                    if ((x > y) == up) { sk[li] = y; sk[lixj] = x; }
                }
            }
            __syncthreads();
        }
        if (k < 16384) {
            for (int q = 0; q < 8; q++) { int li = q*256 + t; g_keys[b][base + li] = sk[li]; }
            gsync(SGB);
        }
    }

    float fb = fcb[0];
    for (int q = 0; q < 8; q++) {
        int li = q*256 + t, gi = base + li;
        if (gi < KTOP) {
            unsigned idx = (unsigned)sk[li];
            float s = tanhf(g_sp[b*NG + idx] * invw);
            g_z[b*KTOP + gi] = fmaf(s, g_fd[b*NG + idx], fb);
        }
    }
}

__global__ void __launch_bounds__(128) k_lin1(const float* __restrict__ W)
{
    __shared__ float zs[BSZ][128];
    int tid = threadIdx.x;
    int j   = blockIdx.x * 128 + tid;
    int ky  = blockIdx.y;
    int k0  = ky * 128;
    int kn  = KTOP - k0; if (kn > 128) kn = 128;
#pragma unroll
    for (int b = 0; b < BSZ; b++)
        if (tid < kn) zs[b][tid] = g_z[b*KTOP + k0 + tid];
    __syncthreads();
    float acc[BSZ];
#pragma unroll
    for (int b = 0; b < BSZ; b++) acc[b] = 0.f;
    for (int kk = 0; kk < kn; kk++) {
        float wv = __ldg(W + (size_t)(k0+kk)*HF + j);
#pragma unroll
        for (int b = 0; b < BSZ; b++) acc[b] = fmaf(zs[b][kk], wv, acc[b]);
    }
#pragma unroll
    for (int b = 0; b < BSZ; b++) g_hpart[ky][b*HF + j] = acc[b];
}

__global__ void k_lin1red(const float* __restrict__ l1b)
{
    int i = blockIdx.x*256 + threadIdx.x;
    if (i >= BSZ*HF) return;
    float s = l1b[i & (HF-1)];
    for (int p = 0; p < KSPL; p++) s += g_hpart[p][i];
    g_hpre[i] = s;
}

__global__ void k_final(const float* __restrict__ W, const float* __restrict__ bias,
                        float* __restrict__ out)
{
    __shared__ float lg[BSZ][2];
    int w = threadIdx.x >> 5, lane = threadIdx.x & 31;
    int b = w >> 1, c = w & 1;
    float a = 0.f;
    for (int jj = lane; jj < HF; jj += 32) {
        float h = fmaxf(g_hpre[b*HF + jj], 0.f);
        a = fmaf(h, W[jj*2 + c], a);
    }
#pragma unroll
    for (int off = 16; off; off >>= 1) a += __shfl_down_sync(0xffffffffu, a, off);
    if (lane == 0) lg[b][c] = a + bias[c];
    __syncthreads();
    if (threadIdx.x < BSZ) {
        int bb = threadIdx.x;
        float l0 = lg[bb][0], l1 = lg[bb][1];
        float m  = fmaxf(l0, l1);
        float lse = m + logf(expf(l0 - m) + expf(l1 - m));
        out[bb*2 + 0] = l0 - lse;
        out[bb*2 + 1] = l1 - lse;
    }
}

extern "C" void kernel_launch(void* const* d_in, const int* in_sizes, int n_in,
                              void* d_out, int out_size)
{
    const float* x   = (const float*)d_in[0];
    const int*   ei  = (const int*  )d_in[2];
    const float* W1  = (const float*)d_in[3];
    const float* b1  = (const float*)d_in[4];
    const float* W2  = (const float*)d_in[5];
    const float* b2  = (const float*)d_in[6];
    const float* W3  = (const float*)d_in[7];
    const float* b3  = (const float*)d_in[8];
    const float* tw  = (const float*)d_in[9];
    const float* fw  = (const float*)d_in[10];
    const float* fcb = (const float*)d_in[11];
    const float* l1W = (const float*)d_in[12];
    const float* l1b = (const float*)d_in[13];
    const float* l2W = (const float*)d_in[14];
    const float* l2b = (const float*)d_in[15];
    float* out = (float*)d_out;
    int E = in_sizes[2] / 2;

    void *pxT_, *pA_, *pB_, *pC_;
    cudaGetSymbolAddress(&pxT_, g_xT);
    cudaGetSymbolAddress(&pA_,  g_bufA);
    cudaGetSymbolAddress(&pB_,  g_bufB);
    cudaGetSymbolAddress(&pC_,  g_bufC);
    float* pxT = (float*)pxT_;
    float* pA  = (float*)pA_;
    float* pB  = (float*)pB_;
    float* pC  = (float*)pC_;

    const int GB = (MROWS + 127) / 128;

    k_nop <<<1, 32>>>();                                             // 1
    k_prep<<<NB, 256>>>(x, ei, tw, E);                               // 2

    k_spmm<BSZ*FIN><<<NG, (BSZ*FIN)/4>>>(pxT, pA);                   // 3
    k_gemm<FIN, true><<<GB, 256>>>(pA, W1, b1, pB, tw, fw, 0);       // 4

    k_spmm<BSZ*HD><<<NG, (BSZ*HD)/4>>>(pB, pC);                      // 5
    k_gemm<HD, true><<<GB, 256>>>(pC, W2, b2, pA, tw, fw, 1);        // 6 <- profile slot

    k_spmm<BSZ*HD><<<NG, (BSZ*HD)/4>>>(pA, pC);                      // 7
    k_gemm<HD, false><<<GB, 256>>>(pC, W3, b3, pB, tw, fw, 2);       // 8

    k_sortz<<<SGB, 256>>>(fcb);                                      // 9
    {
        dim3 g(HF/128, KSPL);
        k_lin1<<<g, 128>>>(l1W);                                     // 10
    }
    k_lin1red<<<(BSZ*HF + 255)/256, 256>>>(l1b);                     // 11
    k_final  <<<1, 512>>>(l2W, l2b, out);                            // 12
}

// round 10
// speedup vs baseline: 1.1481x; 1.1481x over previous
#include <cuda_runtime.h>
#include <cstdint>

#define NG    15135
#define BSZ   8
#define FIN   64
#define HD    128
#define KTOP  7568
#define MROWS (NG*BSZ)
#define HF    512
#define SORTN 16384
#define MAXD  256
#define KSPL  60
#define NB    148
#define SGB   64

__device__ float g_xT  [(size_t)NG*BSZ*FIN];
__device__ float g_bufA[(size_t)NG*BSZ*HD];
__device__ float g_bufB[(size_t)NG*BSZ*HD];
__device__ float g_bufC[(size_t)NG*BSZ*HD];
__device__ int   g_degcnt[NG];
__device__ int   g_rowptr[NG+1];
__device__ int   g_cursor[NG];
__device__ int   g_eid[300000];
__device__ int   g_col[300000];
__device__ float g_w  [300000];
__device__ float g_dinv[NG];
__device__ float g_sp [BSZ*NG];
__device__ float g_fd [BSZ*NG];
__device__ float g_z  [BSZ*KTOP];
__device__ float g_hpart[KSPL][BSZ*HF];
__device__ float g_hpre[BSZ*HF];
__device__ float g_invw;
__device__ unsigned long long g_keys[BSZ][SORTN];
__device__ unsigned g_bar_cnt = 0;
__device__ unsigned g_bar_gen = 0;

// ---------- packed f32x2 (FFMA2) ----------
__device__ __forceinline__ unsigned long long pk2(float lo, float hi)
{
    unsigned long long r;
    asm("mov.b64 %0,{%1,%2};" : "=l"(r) : "f"(lo), "f"(hi));
    return r;
}
__device__ __forceinline__ void upk2(unsigned long long v, float& lo, float& hi)
{
    asm("mov.b64 {%0,%1},%2;" : "=f"(lo), "=f"(hi) : "l"(v));
}
__device__ __forceinline__ void ffma2(unsigned long long& d, unsigned long long a,
                                      unsigned long long b)
{
    asm("fma.rn.f32x2 %0, %1, %2, %0;" : "+l"(d) : "l"(a), "l"(b));
}

// ---------- streaming / async copies ----------
__device__ __forceinline__ float4 ldg_cs4(const float4* p)
{
    float4 v;
    asm("ld.global.cs.v4.f32 {%0,%1,%2,%3},[%4];"
        : "=f"(v.x), "=f"(v.y), "=f"(v.z), "=f"(v.w) : "l"(p));
    return v;
}
__device__ __forceinline__ void stg_cs4(float4* p, float4 v)
{
    asm volatile("st.global.cs.v4.f32 [%0],{%1,%2,%3,%4};"
                 :: "l"(p), "f"(v.x), "f"(v.y), "f"(v.z), "f"(v.w));
}
__device__ __forceinline__ void cpa16(unsigned dst, const void* src)
{
    asm volatile("cp.async.cg.shared.global [%0], [%1], 16;" :: "r"(dst), "l"(src));
}
__device__ __forceinline__ void cpa_commit()
{
    asm volatile("cp.async.commit_group;" ::: "memory");
}
__device__ __forceinline__ void cpa_wait0()
{
    asm volatile("cp.async.wait_group 0;" ::: "memory");
}

// ---------- grid-wide barrier ----------
__device__ __forceinline__ void gsync(unsigned nb)
{
    __syncthreads();
    if (threadIdx.x == 0) {
        unsigned g = *(volatile unsigned*)&g_bar_gen;
        __threadfence();
        unsigned a = atomicAdd(&g_bar_cnt, 1u);
        if (a == nb - 1u) {
            g_bar_cnt = 0;
            __threadfence();
            *(volatile unsigned*)&g_bar_gen = g + 1u;
        } else {
            while (*(volatile unsigned*)&g_bar_gen == g) { }
        }
        __threadfence();
    }
    __syncthreads();
}

__global__ void k_nop() { }

// ---------- fused graph prep ----------
__global__ void __launch_bounds__(256) k_prep(const float* __restrict__ x,
                                              const int* __restrict__ ei,
                                              const float* __restrict__ tw, int E)
{
    int t = threadIdx.x, bid = blockIdx.x;
    int gt = bid*256 + t, gs = NB*256;

    for (int i = gt; i < BSZ*NG; i += gs) { g_sp[i] = 0.f; g_fd[i] = 0.f; }
    for (int i = gt; i < NG; i += gs)     { g_degcnt[i] = 0; g_cursor[i] = 0; }

    if (bid == NB-1) {
        __shared__ float red[256];
        float w0 = tw[t];
        float v = w0*w0;
        if (t < 128) { float w1 = tw[t+256]; v += w1*w1; }
        red[t] = v;
        __syncthreads();
        for (int off = 128; off; off >>= 1) { if (t < off) red[t] += red[t+off]; __syncthreads(); }
        if (t == 0) g_invw = rsqrtf(red[0]);
    }

    for (int idx = gt; idx < NG*BSZ*FIN; idx += gs) {
        int n = idx >> 9, r = idx & 511, b = r >> 6, f = r & 63;
        g_xT[idx] = x[((size_t)b*NG + n)*FIN + f];
    }
    gsync(NB);

    for (int e = gt; e < E; e += gs) atomicAdd(&g_degcnt[ei[E + e]], 1);
    gsync(NB);

    for (int i = gt; i < NG; i += gs) g_dinv[i] = rsqrtf((float)(g_degcnt[i] + 1));

    if (bid == 0) {
        const int C = (NG + 255)/256;
        __shared__ int ws[8];
        int base = t*C, s = 0;
        for (int i = 0; i < C; i++) { int k2 = base+i; if (k2 < NG) s += g_degcnt[k2]; }
        int lane = t & 31, w = t >> 5, v = s;
        for (int off = 1; off < 32; off <<= 1) {
            int n2 = __shfl_up_sync(0xffffffffu, v, off);
            if (lane >= off) v += n2;
        }
        if (lane == 31) ws[w] = v;
        __syncthreads();
        if (t == 0) {
            int a = 0;
            for (int i2 = 0; i2 < 8; i2++) { int tm = ws[i2]; ws[i2] = a; a += tm; }
            g_rowptr[NG] = a;
        }
        __syncthreads();
        int run = v - s + ws[w];
        for (int i = 0; i < C; i++) {
            int k2 = base+i;
            if (k2 < NG) { g_rowptr[k2] = run; run += g_degcnt[k2]; }
        }
    }
    gsync(NB);

    for (int e = gt; e < E; e += gs) {
        int d = ei[E + e];
        g_eid[g_rowptr[d] + atomicAdd(&g_cursor[d], 1)] = e;
    }
    gsync(NB);

    for (int n = gt; n < NG; n += gs) {
        int e0 = g_rowptr[n], deg = g_rowptr[n+1] - e0;
        for (int i = 1; i < deg; i++) {
            int key = g_eid[e0+i], j = i - 1;
            while (j >= 0 && g_eid[e0+j] > key) { g_eid[e0+j+1] = g_eid[e0+j]; j--; }
            g_eid[e0+j+1] = key;
        }
        float dn = g_dinv[n];
        for (int i = 0; i < deg; i++) {
            int e = g_eid[e0+i], s2 = ei[e];
            g_col[e0+i] = s2;
            g_w [e0+i]  = dn * g_dinv[s2];
        }
    }
}

// ---------- SpMM ----------
template<int FB>
__global__ void __launch_bounds__(FB/4) k_spmm(const float* __restrict__ in,
                                               float* __restrict__ out)
{
    __shared__ int   scol[MAXD];
    __shared__ float swt [MAXD];
    int n = blockIdx.x, t = threadIdx.x;
    int e0 = g_rowptr[n], e1 = g_rowptr[n+1];
    int deg = e1 - e0;
    int dstage = deg < MAXD ? deg : MAXD;
    for (int i = t; i < dstage; i += FB/4) { scol[i] = g_col[e0+i]; swt[i] = g_w[e0+i]; }
    __syncthreads();

    float dn = g_dinv[n];
    float wl = dn * dn;
    float4 v = __ldg((const float4*)(in + (size_t)n*FB) + t);
    float4 acc = make_float4(wl*v.x, wl*v.y, wl*v.z, wl*v.w);

    int i = 0;
    for (; i + 1 < dstage; i += 2) {
        int s0 = scol[i], s1 = scol[i+1];
        float w0 = swt[i], w1 = swt[i+1];
        float4 u0 = __ldg((const float4*)(in + (size_t)s0*FB) + t);
        float4 u1 = __ldg((const float4*)(in + (size_t)s1*FB) + t);
        acc.x = fmaf(w0,u0.x,acc.x); acc.y = fmaf(w0,u0.y,acc.y);
        acc.z = fmaf(w0,u0.z,acc.z); acc.w = fmaf(w0,u0.w,acc.w);
        acc.x = fmaf(w1,u1.x,acc.x); acc.y = fmaf(w1,u1.y,acc.y);
        acc.z = fmaf(w1,u1.z,acc.z); acc.w = fmaf(w1,u1.w,acc.w);
    }
    for (; i < dstage; i++) {
        int s0 = scol[i]; float w0 = swt[i];
        float4 u0 = __ldg((const float4*)(in + (size_t)s0*FB) + t);
        acc.x = fmaf(w0,u0.x,acc.x); acc.y = fmaf(w0,u0.y,acc.y);
        acc.z = fmaf(w0,u0.z,acc.z); acc.w = fmaf(w0,u0.w,acc.w);
    }
    for (int e = e0 + MAXD; e < e1; e++) {
        int s0 = g_col[e]; float w0 = g_w[e];
        float4 u0 = __ldg((const float4*)(in + (size_t)s0*FB) + t);
        acc.x = fmaf(w0,u0.x,acc.x); acc.y = fmaf(w0,u0.y,acc.y);
        acc.z = fmaf(w0,u0.z,acc.z); acc.w = fmaf(w0,u0.w,acc.w);
    }
    stg_cs4((float4*)(out + (size_t)n*FB) + t, acc);
}

// ---------- GEMM: 64x128 tile, 4x8/thread, 3 CTA/SM, swizzled-B ping-pong, FFMA2 ----------
#define LDB(f, kk, cur) do { \
    const char* _br = (const char*)&Bs[cur][kk][0]; \
    ulonglong2 _b0 = *(const ulonglong2*)(_br + swb0); \
    ulonglong2 _b1 = *(const ulonglong2*)(_br + swb1); \
    bp[f][0]=_b0.x; bp[f][1]=_b0.y; bp[f][2]=_b1.x; bp[f][3]=_b1.y; \
} while(0)

template<int KDIM, bool WRITEC>
__global__ void __launch_bounds__(256, 3) k_gemm(const float* __restrict__ A,
                                                 const float* __restrict__ W,
                                                 const float* __restrict__ bias,
                                                 float* __restrict__ C,
                                                 const float* __restrict__ tw,
                                                 const float* __restrict__ fw, int l)
{
    __shared__ __align__(16) float As[2][16][68];   // [k][m] (64 + 4 pad)
    __shared__ __align__(16) float Bs[2][16][128];  // [k][j], 16B-granule XOR swizzle
    const int tid = threadIdx.x;
    const int bm  = blockIdx.x * 64;
    const int tx  = tid & 15, ty = tid >> 4;        // ty 0..15 -> 4 rows each
    const int arow = tid >> 2, akc = (tid & 3) * 4; // A: 1 ldg_cs4 -> 4 STS transpose
    const int brow = tid >> 4, bgr  = (tid & 15) * 2;

    const int swb0 = (( 2*tx   ) ^ (( 2*tx   ) >> 3)) * 16;
    const int swb1 = (( 2*tx+1 ) ^ (( 2*tx+1 ) >> 3)) * 16;
    const int bgs0 = (bgr ^ (bgr >> 3)) * 16;
    const int bgs1 = ((bgr+1) ^ ((bgr+1) >> 3)) * 16;

    unsigned long long acc2[4][4];
#pragma unroll
    for (int i = 0; i < 4; i++)
#pragma unroll
        for (int j = 0; j < 4; j++) acc2[i][j] = 0ull;

    int am = bm + arow;
    if (am >= MROWS) am = MROWS - 1;   // clamp; masked in epilogue
    const float* Aptr = A + (size_t)am*KDIM + akc;
    const float* Wptr = W + (size_t)brow*HD + bgr*4;
    unsigned brow_sm[2];
    brow_sm[0] = (unsigned)__cvta_generic_to_shared(&Bs[0][brow][0]);
    brow_sm[1] = (unsigned)__cvta_generic_to_shared(&Bs[1][brow][0]);

    // stage tile 0
    {
        float4 va = ldg_cs4((const float4*)Aptr);
        cpa16(brow_sm[0]+bgs0, Wptr);
        cpa16(brow_sm[0]+bgs1, Wptr+4);
        cpa_commit();
        As[0][akc+0][arow]=va.x; As[0][akc+1][arow]=va.y;
        As[0][akc+2][arow]=va.z; As[0][akc+3][arow]=va.w;
        cpa_wait0();
    }
    __syncthreads();

    unsigned long long bp[2][4];
    LDB(0, 0, 0);

    const int ntiles = KDIM/16;
    for (int t = 0; t < ntiles; t++) {
        const int cur = t & 1, nxt = cur ^ 1;
        const bool pf = (t + 1 < ntiles);
        float4 va;
        if (pf) {
            va = ldg_cs4((const float4*)(Aptr + (t+1)*16));
            const float* wp2 = Wptr + (size_t)(t+1)*16*HD;
            cpa16(brow_sm[nxt]+bgs0, wp2);
            cpa16(brow_sm[nxt]+bgs1, wp2+4);
            cpa_commit();
        }
#pragma unroll
        for (int kk = 0; kk < 16; kk++) {
            const int f = kk & 1;
            if (kk < 15) LDB(f^1, kk+1, cur);
            const float4* ar = (const float4*)&As[cur][kk][ty*4];
            float4 av = ar[0];
            unsigned long long a0 = pk2(av.x, av.x);
            unsigned long long a1 = pk2(av.y, av.y);
            unsigned long long a2 = pk2(av.z, av.z);
            unsigned long long a3 = pk2(av.w, av.w);
#pragma unroll
            for (int j = 0; j < 4; j++) ffma2(acc2[0][j], a0, bp[f][j]);
#pragma unroll
            for (int j = 0; j < 4; j++) ffma2(acc2[1][j], a1, bp[f][j]);
#pragma unroll
            for (int j = 0; j < 4; j++) ffma2(acc2[2][j], a2, bp[f][j]);
#pragma unroll
            for (int j = 0; j < 4; j++) ffma2(acc2[3][j], a3, bp[f][j]);
        }
        if (pf) {
            As[nxt][akc+0][arow]=va.x; As[nxt][akc+1][arow]=va.y;
            As[nxt][akc+2][arow]=va.z; As[nxt][akc+3][arow]=va.w;
            cpa_wait0();
            __syncthreads();
            LDB(0, 0, nxt);
        }
    }

    float bv[8], twv[8], fwv[8];
#pragma unroll
    for (int j = 0; j < 8; j++) {
        int f = tx*8 + j;
        bv[j]  = bias[f];
        twv[j] = tw[f*3 + l];
        fwv[j] = fw[f*3 + l];
    }
#pragma unroll
    for (int i = 0; i < 4; i++) {
        int m = bm + ty*4 + i;
        float vj[8];
#pragma unroll
        for (int j = 0; j < 4; j++) {
            float lo, hi;
            upk2(acc2[i][j], lo, hi);
            vj[2*j]   = fmaxf(lo + bv[2*j],   0.f);
            vj[2*j+1] = fmaxf(hi + bv[2*j+1], 0.f);
        }
        float a = 0.f, c = 0.f;
#pragma unroll
        for (int j = 0; j < 8; j++) { a = fmaf(vj[j], twv[j], a); c = fmaf(vj[j], fwv[j], c); }
#pragma unroll
        for (int off = 8; off; off >>= 1) {
            a += __shfl_down_sync(0xffffffffu, a, off, 16);
            c += __shfl_down_sync(0xffffffffu, c, off, 16);
        }
        if (m < MROWS) {
            if (WRITEC) {
                *(float4*)(C + (size_t)m*HD + tx*8 + 0) = make_float4(vj[0],vj[1],vj[2],vj[3]);
                *(float4*)(C + (size_t)m*HD + tx*8 + 4) = make_float4(vj[4],vj[5],vj[6],vj[7]);
            }
            if (tx == 0) {
                int n = m >> 3, b = m & 7;
                g_sp[b*NG + n] += a;
                g_fd[b*NG + n] += c;
            }
        }
    }
}

// ---------- multi-block bitonic sort + z ----------
__global__ void __launch_bounds__(256) k_sortz(const float* __restrict__ fcb)
{
    __shared__ unsigned long long sk[2048];
    int bid = blockIdx.x;
    int b = bid >> 3, sub = bid & 7;
    int t = threadIdx.x;
    int base = sub * 2048;
    float invw = g_invw;

    for (int q = 0; q < 8; q++) {
        int li = q*256 + t, gi = base + li;
        unsigned long long key = 0xFFFFFFFFFFFFFFFFull;
        if (gi < NG) {
            float s = tanhf(g_sp[b*NG + gi] * invw);
            unsigned u = __float_as_uint(s);
            u = (u & 0x80000000u) ? ~u : (u | 0x80000000u);
            key = ((unsigned long long)(~u) << 32) | (unsigned)gi;
        }
        sk[li] = key;
    }
    __syncthreads();

    for (unsigned k = 2; k <= 2048; k <<= 1) {
        for (unsigned j = k >> 1; j > 0; j >>= 1) {
            for (int q = 0; q < 8; q++) {
                int li = q*256 + t;
                unsigned lixj = li ^ j;
                if (lixj > (unsigned)li) {
                    unsigned long long x = sk[li], y = sk[lixj];
                    bool up = (((base + li) & k) == 0);
                    if ((x > y) == up) { sk[li] = y; sk[lixj] = x; }
                }
            }
            __syncthreads();
        }
    }
    for (int q = 0; q < 8; q++) { int li = q*256 + t; g_keys[b][base + li] = sk[li]; }
    gsync(SGB);

    for (unsigned k = 4096; k <= 16384; k <<= 1) {
        for (unsigned j = k >> 1; j >= 2048; j >>= 1) {
            for (int q = 0; q < 8; q++) {
                int i = bid*256 + t;
                int bb = q;
                int ixj = i ^ j;
                if (ixj > i) {
                    unsigned long long x = g_keys[bb][i], y = g_keys[bb][ixj];
                    bool up = ((i & k) == 0);
                    if ((x > y) == up) { g_keys[bb][i] = y; g_keys[bb][ixj] = x; }
                }
            }
            gsync(SGB);
        }
        for (int q = 0; q < 8; q++) { int li = q*256 + t; sk[li] = g_keys[b][base + li]; }
        __syncthreads();
        for (unsigned j = 1024; j > 0; j >>= 1) {
            for (int q = 0; q < 8; q++) {
                int li = q*256 + t;
                unsigned lixj = li ^ j;
                if (lixj > (unsigned)li) {
                    unsigned long long x = sk[li], y = sk[lixj];
                    bool up = (((base + li) & k) == 0);
                    if ((x > y) == up) { sk[li] = y; sk[lixj] = x; }
                }
            }
            __syncthreads();
        }
        if (k < 16384) {
            for (int q = 0; q < 8; q++) { int li = q*256 + t; g_keys[b][base + li] = sk[li]; }
            gsync(SGB);
        }
    }

    float fb = fcb[0];
    for (int q = 0; q < 8; q++) {
        int li = q*256 + t, gi = base + li;
        if (gi < KTOP) {
            unsigned idx = (unsigned)sk[li];
            float s = tanhf(g_sp[b*NG + idx] * invw);
            g_z[b*KTOP + gi] = fmaf(s, g_fd[b*NG + idx], fb);
        }
    }
}

__global__ void __launch_bounds__(128) k_lin1(const float* __restrict__ W)
{
    __shared__ float zs[BSZ][128];
    int tid = threadIdx.x;
    int j   = blockIdx.x * 128 + tid;
    int ky  = blockIdx.y;
    int k0  = ky * 128;
    int kn  = KTOP - k0; if (kn > 128) kn = 128;
#pragma unroll
    for (int b = 0; b < BSZ; b++)
        if (tid < kn) zs[b][tid] = g_z[b*KTOP + k0 + tid];
    __syncthreads();
    float acc[BSZ];
#pragma unroll
    for (int b = 0; b < BSZ; b++) acc[b] = 0.f;
    for (int kk = 0; kk < kn; kk++) {
        float wv = __ldg(W + (size_t)(k0+kk)*HF + j);
#pragma unroll
        for (int b = 0; b < BSZ; b++) acc[b] = fmaf(zs[b][kk], wv, acc[b]);
    }
#pragma unroll
    for (int b = 0; b < BSZ; b++) g_hpart[ky][b*HF + j] = acc[b];
}

__global__ void k_lin1red(const float* __restrict__ l1b)
{
    int i = blockIdx.x*256 + threadIdx.x;
    if (i >= BSZ*HF) return;
    float s = l1b[i & (HF-1)];
    for (int p = 0; p < KSPL; p++) s += g_hpart[p][i];
    g_hpre[i] = s;
}

__global__ void k_final(const float* __restrict__ W, const float* __restrict__ bias,
                        float* __restrict__ out)
{
    __shared__ float lg[BSZ][2];
    int w = threadIdx.x >> 5, lane = threadIdx.x & 31;
    int b = w >> 1, c = w & 1;
    float a = 0.f;
    for (int jj = lane; jj < HF; jj += 32) {
        float h = fmaxf(g_hpre[b*HF + jj], 0.f);
        a = fmaf(h, W[jj*2 + c], a);
    }
#pragma unroll
    for (int off = 16; off; off >>= 1) a += __shfl_down_sync(0xffffffffu, a, off);
    if (lane == 0) lg[b][c] = a + bias[c];
    __syncthreads();
    if (threadIdx.x < BSZ) {
        int bb = threadIdx.x;
        float l0 = lg[bb][0], l1 = lg[bb][1];
        float m  = fmaxf(l0, l1);
        float lse = m + logf(expf(l0 - m) + expf(l1 - m));
        out[bb*2 + 0] = l0 - lse;
        out[bb*2 + 1] = l1 - lse;
    }
}

extern "C" void kernel_launch(void* const* d_in, const int* in_sizes, int n_in,
                              void* d_out, int out_size)
{
    const float* x   = (const float*)d_in[0];
    const int*   ei  = (const int*  )d_in[2];
    const float* W1  = (const float*)d_in[3];
    const float* b1  = (const float*)d_in[4];
    const float* W2  = (const float*)d_in[5];
    const float* b2  = (const float*)d_in[6];
    const float* W3  = (const float*)d_in[7];
    const float* b3  = (const float*)d_in[8];
    const float* tw  = (const float*)d_in[9];
    const float* fw  = (const float*)d_in[10];
    const float* fcb = (const float*)d_in[11];
    const float* l1W = (const float*)d_in[12];
    const float* l1b = (const float*)d_in[13];
    const float* l2W = (const float*)d_in[14];
    const float* l2b = (const float*)d_in[15];
    float* out = (float*)d_out;
    int E = in_sizes[2] / 2;

    void *pxT_, *pA_, *pB_, *pC_;
    cudaGetSymbolAddress(&pxT_, g_xT);
    cudaGetSymbolAddress(&pA_,  g_bufA);
    cudaGetSymbolAddress(&pB_,  g_bufB);
    cudaGetSymbolAddress(&pC_,  g_bufC);
    float* pxT = (float*)pxT_;
    float* pA  = (float*)pA_;
    float* pB  = (float*)pB_;
    float* pC  = (float*)pC_;

    const int GB = (MROWS + 63) / 64;

    k_nop <<<1, 32>>>();                                             // 1
    k_prep<<<NB, 256>>>(x, ei, tw, E);                               // 2

    k_spmm<BSZ*FIN><<<NG, (BSZ*FIN)/4>>>(pxT, pA);                   // 3
    k_gemm<FIN, true><<<GB, 256>>>(pA, W1, b1, pB, tw, fw, 0);       // 4

    k_spmm<BSZ*HD><<<NG, (BSZ*HD)/4>>>(pB, pC);                      // 5
    k_gemm<HD, true><<<GB, 256>>>(pC, W2, b2, pA, tw, fw, 1);        // 6

    k_spmm<BSZ*HD><<<NG, (BSZ*HD)/4>>>(pA, pC);                      // 7
    k_gemm<HD, false><<<GB, 256>>>(pC, W3, b3, pB, tw, fw, 2);       // 8

    k_sortz<<<SGB, 256>>>(fcb);                                      // 9
    {
        dim3 g(HF/128, KSPL);
        k_lin1<<<g, 128>>>(l1W);                                     // 10
    }
    k_lin1red<<<(BSZ*HF + 255)/256, 256>>>(l1b);                     // 11
    k_final  <<<1, 512>>>(l2W, l2b, out);                            // 12
}

// round 11
// speedup vs baseline: 1.1680x; 1.0174x over previous
#include <cuda_runtime.h>
#include <cstdint>

#define NG    15135
#define BSZ   8
#define FIN   64
#define HD    128
#define KTOP  7568
#define MROWS (NG*BSZ)
#define HF    512
#define SORTN 16384
#define MAXD  256
#define KSPL  60
#define NB    148
#define SGB   64

__device__ float g_xT  [(size_t)NG*BSZ*FIN];
__device__ float g_bufA[(size_t)NG*BSZ*HD];
__device__ float g_bufB[(size_t)NG*BSZ*HD];
__device__ float g_bufC[(size_t)NG*BSZ*HD];
__device__ int   g_degcnt[NG];
__device__ int   g_rowptr[NG+1];
__device__ int   g_cursor[NG];
__device__ int   g_eid[300000];
__device__ int   g_col[300000];
__device__ float g_w  [300000];
__device__ float g_dinv[NG];
__device__ float g_sp [BSZ*NG];
__device__ float g_fd [BSZ*NG];
__device__ float g_z  [BSZ*KTOP];
__device__ float g_hpart[KSPL][BSZ*HF];
__device__ float g_hpre[BSZ*HF];
__device__ float g_invw;
__device__ unsigned long long g_keys[BSZ][SORTN];
__device__ unsigned g_bar_cnt = 0;
__device__ unsigned g_bar_gen = 0;

// ---------- packed f32x2 (FFMA2) ----------
__device__ __forceinline__ unsigned long long pk2(float lo, float hi)
{
    unsigned long long r;
    asm("mov.b64 %0,{%1,%2};" : "=l"(r) : "f"(lo), "f"(hi));
    return r;
}
__device__ __forceinline__ void upk2(unsigned long long v, float& lo, float& hi)
{
    asm("mov.b64 {%0,%1},%2;" : "=f"(lo), "=f"(hi) : "l"(v));
}
__device__ __forceinline__ void ffma2(unsigned long long& d, unsigned long long a,
                                      unsigned long long b)
{
    asm("fma.rn.f32x2 %0, %1, %2, %0;" : "+l"(d) : "l"(a), "l"(b));
}

// ---------- streaming / async copies ----------
__device__ __forceinline__ float4 ldg_cs4(const float4* p)
{
    float4 v;
    asm("ld.global.cs.v4.f32 {%0,%1,%2,%3},[%4];"
        : "=f"(v.x), "=f"(v.y), "=f"(v.z), "=f"(v.w) : "l"(p));
    return v;
}
__device__ __forceinline__ void stg_cs4(float4* p, float4 v)
{
    asm volatile("st.global.cs.v4.f32 [%0],{%1,%2,%3,%4};"
                 :: "l"(p), "f"(v.x), "f"(v.y), "f"(v.z), "f"(v.w));
}
__device__ __forceinline__ void cpa16(unsigned dst, const void* src)
{
    asm volatile("cp.async.cg.shared.global [%0], [%1], 16;" :: "r"(dst), "l"(src));
}
__device__ __forceinline__ void cpa_commit()
{
    asm volatile("cp.async.commit_group;" ::: "memory");
}
__device__ __forceinline__ void cpa_wait0()
{
    asm volatile("cp.async.wait_group 0;" ::: "memory");
}

// ---------- grid-wide barrier ----------
__device__ __forceinline__ void gsync(unsigned nb)
{
    __syncthreads();
    if (threadIdx.x == 0) {
        unsigned g = *(volatile unsigned*)&g_bar_gen;
        __threadfence();
        unsigned a = atomicAdd(&g_bar_cnt, 1u);
        if (a == nb - 1u) {
            g_bar_cnt = 0;
            __threadfence();
            *(volatile unsigned*)&g_bar_gen = g + 1u;
        } else {
            while (*(volatile unsigned*)&g_bar_gen == g) { }
        }
        __threadfence();
    }
    __syncthreads();
}

__global__ void k_nop() { }

// ---------- fused graph prep ----------
__global__ void __launch_bounds__(256) k_prep(const float* __restrict__ x,
                                              const int* __restrict__ ei,
                                              const float* __restrict__ tw, int E)
{
    int t = threadIdx.x, bid = blockIdx.x;
    int gt = bid*256 + t, gs = NB*256;

    for (int i = gt; i < BSZ*NG; i += gs) { g_sp[i] = 0.f; g_fd[i] = 0.f; }
    for (int i = gt; i < NG; i += gs)     { g_degcnt[i] = 0; g_cursor[i] = 0; }

    if (bid == NB-1) {
        __shared__ float red[256];
        float w0 = tw[t];
        float v = w0*w0;
        if (t < 128) { float w1 = tw[t+256]; v += w1*w1; }
        red[t] = v;
        __syncthreads();
        for (int off = 128; off; off >>= 1) { if (t < off) red[t] += red[t+off]; __syncthreads(); }
        if (t == 0) g_invw = rsqrtf(red[0]);
    }

    for (int idx = gt; idx < NG*BSZ*FIN; idx += gs) {
        int n = idx >> 9, r = idx & 511, b = r >> 6, f = r & 63;
        g_xT[idx] = x[((size_t)b*NG + n)*FIN + f];
    }
    gsync(NB);

    for (int e = gt; e < E; e += gs) atomicAdd(&g_degcnt[ei[E + e]], 1);
    gsync(NB);

    for (int i = gt; i < NG; i += gs) g_dinv[i] = rsqrtf((float)(g_degcnt[i] + 1));

    if (bid == 0) {
        const int C = (NG + 255)/256;
        __shared__ int ws[8];
        int base = t*C, s = 0;
        for (int i = 0; i < C; i++) { int k2 = base+i; if (k2 < NG) s += g_degcnt[k2]; }
        int lane = t & 31, w = t >> 5, v = s;
        for (int off = 1; off < 32; off <<= 1) {
            int n2 = __shfl_up_sync(0xffffffffu, v, off);
            if (lane >= off) v += n2;
        }
        if (lane == 31) ws[w] = v;
        __syncthreads();
        if (t == 0) {
            int a = 0;
            for (int i2 = 0; i2 < 8; i2++) { int tm = ws[i2]; ws[i2] = a; a += tm; }
            g_rowptr[NG] = a;
        }
        __syncthreads();
        int run = v - s + ws[w];
        for (int i = 0; i < C; i++) {
            int k2 = base+i;
            if (k2 < NG) { g_rowptr[k2] = run; run += g_degcnt[k2]; }
        }
    }
    gsync(NB);

    for (int e = gt; e < E; e += gs) {
        int d = ei[E + e];
        g_eid[g_rowptr[d] + atomicAdd(&g_cursor[d], 1)] = e;
    }
    gsync(NB);

    for (int n = gt; n < NG; n += gs) {
        int e0 = g_rowptr[n], deg = g_rowptr[n+1] - e0;
        for (int i = 1; i < deg; i++) {
            int key = g_eid[e0+i], j = i - 1;
            while (j >= 0 && g_eid[e0+j] > key) { g_eid[e0+j+1] = g_eid[e0+j]; j--; }
            g_eid[e0+j+1] = key;
        }
        float dn = g_dinv[n];
        for (int i = 0; i < deg; i++) {
            int e = g_eid[e0+i], s2 = ei[e];
            g_col[e0+i] = s2;
            g_w [e0+i]  = dn * g_dinv[s2];
        }
    }
}

// ---------- SpMM ----------
template<int FB>
__global__ void __launch_bounds__(FB/4) k_spmm(const float* __restrict__ in,
                                               float* __restrict__ out)
{
    __shared__ int   scol[MAXD];
    __shared__ float swt [MAXD];
    int n = blockIdx.x, t = threadIdx.x;
    int e0 = g_rowptr[n], e1 = g_rowptr[n+1];
    int deg = e1 - e0;
    int dstage = deg < MAXD ? deg : MAXD;
    for (int i = t; i < dstage; i += FB/4) { scol[i] = g_col[e0+i]; swt[i] = g_w[e0+i]; }
    __syncthreads();

    float dn = g_dinv[n];
    float wl = dn * dn;
    float4 v = __ldg((const float4*)(in + (size_t)n*FB) + t);
    float4 acc = make_float4(wl*v.x, wl*v.y, wl*v.z, wl*v.w);

    int i = 0;
    for (; i + 1 < dstage; i += 2) {
        int s0 = scol[i], s1 = scol[i+1];
        float w0 = swt[i], w1 = swt[i+1];
        float4 u0 = __ldg((const float4*)(in + (size_t)s0*FB) + t);
        float4 u1 = __ldg((const float4*)(in + (size_t)s1*FB) + t);
        acc.x = fmaf(w0,u0.x,acc.x); acc.y = fmaf(w0,u0.y,acc.y);
        acc.z = fmaf(w0,u0.z,acc.z); acc.w = fmaf(w0,u0.w,acc.w);
        acc.x = fmaf(w1,u1.x,acc.x); acc.y = fmaf(w1,u1.y,acc.y);
        acc.z = fmaf(w1,u1.z,acc.z); acc.w = fmaf(w1,u1.w,acc.w);
    }
    for (; i < dstage; i++) {
        int s0 = scol[i]; float w0 = swt[i];
        float4 u0 = __ldg((const float4*)(in + (size_t)s0*FB) + t);
        acc.x = fmaf(w0,u0.x,acc.x); acc.y = fmaf(w0,u0.y,acc.y);
        acc.z = fmaf(w0,u0.z,acc.z); acc.w = fmaf(w0,u0.w,acc.w);
    }
    for (int e = e0 + MAXD; e < e1; e++) {
        int s0 = g_col[e]; float w0 = g_w[e];
        float4 u0 = __ldg((const float4*)(in + (size_t)s0*FB) + t);
        acc.x = fmaf(w0,u0.x,acc.x); acc.y = fmaf(w0,u0.y,acc.y);
        acc.z = fmaf(w0,u0.z,acc.z); acc.w = fmaf(w0,u0.w,acc.w);
    }
    stg_cs4((float4*)(out + (size_t)n*FB) + t, acc);
}

// ---------- GEMM A: 64x128 tile, 4x8/thread, 3 CTA/SM (best for KDIM=64) ----------
#define LDB64(f, kk, cur) do { \
    const char* _br = (const char*)&Bs[cur][kk][0]; \
    ulonglong2 _b0 = *(const ulonglong2*)(_br + swb0); \
    ulonglong2 _b1 = *(const ulonglong2*)(_br + swb1); \
    bp[f][0]=_b0.x; bp[f][1]=_b0.y; bp[f][2]=_b1.x; bp[f][3]=_b1.y; \
} while(0)

template<int KDIM, bool WRITEC>
__global__ void __launch_bounds__(256, 3) k_gemm64t(const float* __restrict__ A,
                                                    const float* __restrict__ W,
                                                    const float* __restrict__ bias,
                                                    float* __restrict__ C,
                                                    const float* __restrict__ tw,
                                                    const float* __restrict__ fw, int l)
{
    __shared__ __align__(16) float As[2][16][68];
    __shared__ __align__(16) float Bs[2][16][128];
    const int tid = threadIdx.x;
    const int bm  = blockIdx.x * 64;
    const int tx  = tid & 15, ty = tid >> 4;
    const int arow = tid >> 2, akc = (tid & 3) * 4;
    const int brow = tid >> 4, bgr  = (tid & 15) * 2;

    const int swb0 = (( 2*tx   ) ^ (( 2*tx   ) >> 3)) * 16;
    const int swb1 = (( 2*tx+1 ) ^ (( 2*tx+1 ) >> 3)) * 16;
    const int bgs0 = (bgr ^ (bgr >> 3)) * 16;
    const int bgs1 = ((bgr+1) ^ ((bgr+1) >> 3)) * 16;

    unsigned long long acc2[4][4];
#pragma unroll
    for (int i = 0; i < 4; i++)
#pragma unroll
        for (int j = 0; j < 4; j++) acc2[i][j] = 0ull;

    int am = bm + arow;
    if (am >= MROWS) am = MROWS - 1;
    const float* Aptr = A + (size_t)am*KDIM + akc;
    const float* Wptr = W + (size_t)brow*HD + bgr*4;
    unsigned brow_sm[2];
    brow_sm[0] = (unsigned)__cvta_generic_to_shared(&Bs[0][brow][0]);
    brow_sm[1] = (unsigned)__cvta_generic_to_shared(&Bs[1][brow][0]);

    {
        float4 va = ldg_cs4((const float4*)Aptr);
        cpa16(brow_sm[0]+bgs0, Wptr);
        cpa16(brow_sm[0]+bgs1, Wptr+4);
        cpa_commit();
        As[0][akc+0][arow]=va.x; As[0][akc+1][arow]=va.y;
        As[0][akc+2][arow]=va.z; As[0][akc+3][arow]=va.w;
        cpa_wait0();
    }
    __syncthreads();

    unsigned long long bp[2][4];
    LDB64(0, 0, 0);

    const int ntiles = KDIM/16;
    for (int t = 0; t < ntiles; t++) {
        const int cur = t & 1, nxt = cur ^ 1;
        const bool pf = (t + 1 < ntiles);
        float4 va;
        if (pf) {
            va = ldg_cs4((const float4*)(Aptr + (t+1)*16));
            const float* wp2 = Wptr + (size_t)(t+1)*16*HD;
            cpa16(brow_sm[nxt]+bgs0, wp2);
            cpa16(brow_sm[nxt]+bgs1, wp2+4);
            cpa_commit();
        }
#pragma unroll
        for (int kk = 0; kk < 16; kk++) {
            const int f = kk & 1;
            if (kk < 15) LDB64(f^1, kk+1, cur);
            float4 av = *(const float4*)&As[cur][kk][ty*4];
            unsigned long long a0 = pk2(av.x, av.x);
            unsigned long long a1 = pk2(av.y, av.y);
            unsigned long long a2 = pk2(av.z, av.z);
            unsigned long long a3 = pk2(av.w, av.w);
#pragma unroll
            for (int j = 0; j < 4; j++) ffma2(acc2[0][j], a0, bp[f][j]);
#pragma unroll
            for (int j = 0; j < 4; j++) ffma2(acc2[1][j], a1, bp[f][j]);
#pragma unroll
            for (int j = 0; j < 4; j++) ffma2(acc2[2][j], a2, bp[f][j]);
#pragma unroll
            for (int j = 0; j < 4; j++) ffma2(acc2[3][j], a3, bp[f][j]);
        }
        if (pf) {
            As[nxt][akc+0][arow]=va.x; As[nxt][akc+1][arow]=va.y;
            As[nxt][akc+2][arow]=va.z; As[nxt][akc+3][arow]=va.w;
            cpa_wait0();
            __syncthreads();
            LDB64(0, 0, nxt);
        }
    }

    float bv[8], twv[8], fwv[8];
#pragma unroll
    for (int j = 0; j < 8; j++) {
        int f = tx*8 + j;
        bv[j]  = bias[f];
        twv[j] = tw[f*3 + l];
        fwv[j] = fw[f*3 + l];
    }
#pragma unroll
    for (int i = 0; i < 4; i++) {
        int m = bm + ty*4 + i;
        float vj[8];
#pragma unroll
        for (int j = 0; j < 4; j++) {
            float lo, hi;
            upk2(acc2[i][j], lo, hi);
            vj[2*j]   = fmaxf(lo + bv[2*j],   0.f);
            vj[2*j+1] = fmaxf(hi + bv[2*j+1], 0.f);
        }
        float a = 0.f, c = 0.f;
#pragma unroll
        for (int j = 0; j < 8; j++) { a = fmaf(vj[j], twv[j], a); c = fmaf(vj[j], fwv[j], c); }
#pragma unroll
        for (int off = 8; off; off >>= 1) {
            a += __shfl_down_sync(0xffffffffu, a, off, 16);
            c += __shfl_down_sync(0xffffffffu, c, off, 16);
        }
        if (m < MROWS) {
            if (WRITEC) {
                *(float4*)(C + (size_t)m*HD + tx*8 + 0) = make_float4(vj[0],vj[1],vj[2],vj[3]);
                *(float4*)(C + (size_t)m*HD + tx*8 + 4) = make_float4(vj[4],vj[5],vj[6],vj[7]);
            }
            if (tx == 0) {
                int n = m >> 3, b = m & 7;
                g_sp[b*NG + n] += a;
                g_fd[b*NG + n] += c;
            }
        }
    }
}

// ---------- GEMM B: 128x128 tile, 8x8/thread, 2 CTA/SM (best for KDIM=128) ----------
#define LDFRAG128(f, kk, cur) do { \
    const float4* _a = (const float4*)&As[cur][kk][ty*8]; \
    float4 _v0 = _a[0], _v1 = _a[1]; \
    af[f][0]=_v0.x; af[f][1]=_v0.y; af[f][2]=_v0.z; af[f][3]=_v0.w; \
    af[f][4]=_v1.x; af[f][5]=_v1.y; af[f][6]=_v1.z; af[f][7]=_v1.w; \
    const char* _br = (const char*)&Bs[cur][kk][0]; \
    ulonglong2 _b0 = *(const ulonglong2*)(_br + swb0); \
    ulonglong2 _b1 = *(const ulonglong2*)(_br + swb1); \
    bp[f][0]=_b0.x; bp[f][1]=_b0.y; bp[f][2]=_b1.x; bp[f][3]=_b1.y; \
} while(0)

template<int KDIM, bool WRITEC>
__global__ void __launch_bounds__(256, 2) k_gemm128t(const float* __restrict__ A,
                                                     const float* __restrict__ W,
                                                     const float* __restrict__ bias,
                                                     float* __restrict__ C,
                                                     const float* __restrict__ tw,
                                                     const float* __restrict__ fw, int l)
{
    __shared__ float As[2][16][136];
    __shared__ float Bs[2][16][128];
    const int tid = threadIdx.x;
    const int bm  = blockIdx.x * 128;
    const int tx  = tid & 15, ty = tid >> 4;
    const int arow = tid >> 1, akc = (tid & 1) * 8;
    const int brow = tid >> 4, bgr  = (tid & 15) * 2;

    const int swb0 = (( 2*tx   ) ^ (( 2*tx   ) >> 3)) * 16;
    const int swb1 = (( 2*tx+1 ) ^ (( 2*tx+1 ) >> 3)) * 16;
    const int bgs0 = (bgr ^ (bgr >> 3)) * 16;
    const int bgs1 = ((bgr+1) ^ ((bgr+1) >> 3)) * 16;

    unsigned long long acc2[8][4];
#pragma unroll
    for (int i = 0; i < 8; i++)
#pragma unroll
        for (int j = 0; j < 4; j++) acc2[i][j] = 0ull;

    int am = bm + arow;
    if (am >= MROWS) am = MROWS - 1;
    const float* Aptr = A + (size_t)am*KDIM + akc;
    const float* Wptr = W + (size_t)brow*HD + bgr*4;
    unsigned brow_sm[2];
    brow_sm[0] = (unsigned)__cvta_generic_to_shared(&Bs[0][brow][0]);
    brow_sm[1] = (unsigned)__cvta_generic_to_shared(&Bs[1][brow][0]);

    {
        float4 va0 = ldg_cs4((const float4*)Aptr);
        float4 va1 = ldg_cs4((const float4*)(Aptr+4));
        cpa16(brow_sm[0]+bgs0, Wptr);
        cpa16(brow_sm[0]+bgs1, Wptr+4);
        cpa_commit();
        As[0][akc+0][arow]=va0.x; As[0][akc+1][arow]=va0.y;
        As[0][akc+2][arow]=va0.z; As[0][akc+3][arow]=va0.w;
        As[0][akc+4][arow]=va1.x; As[0][akc+5][arow]=va1.y;
        As[0][akc+6][arow]=va1.z; As[0][akc+7][arow]=va1.w;
        cpa_wait0();
    }
    __syncthreads();

    float af[2][8];
    unsigned long long bp[2][4];
    LDFRAG128(0, 0, 0);

    const int ntiles = KDIM/16;
    for (int t = 0; t < ntiles; t++) {
        const int cur = t & 1, nxt = cur ^ 1;
        const bool pf = (t + 1 < ntiles);
        float4 va0, va1;
        if (pf) {
            const float* ap2 = Aptr + (t+1)*16;
            va0 = ldg_cs4((const float4*)ap2);
            va1 = ldg_cs4((const float4*)(ap2+4));
            const float* wp2 = Wptr + (size_t)(t+1)*16*HD;
            cpa16(brow_sm[nxt]+bgs0, wp2);
            cpa16(brow_sm[nxt]+bgs1, wp2+4);
            cpa_commit();
        }
#pragma unroll
        for (int kk = 0; kk < 16; kk++) {
            const int f = kk & 1;
            if (kk < 15) LDFRAG128(f^1, kk+1, cur);
#pragma unroll
            for (int i = 0; i < 8; i++) {
                unsigned long long ap = pk2(af[f][i], af[f][i]);
#pragma unroll
                for (int j = 0; j < 4; j++) ffma2(acc2[i][j], ap, bp[f][j]);
            }
        }
        if (pf) {
            As[nxt][akc+0][arow]=va0.x; As[nxt][akc+1][arow]=va0.y;
            As[nxt][akc+2][arow]=va0.z; As[nxt][akc+3][arow]=va0.w;
            As[nxt][akc+4][arow]=va1.x; As[nxt][akc+5][arow]=va1.y;
            As[nxt][akc+6][arow]=va1.z; As[nxt][akc+7][arow]=va1.w;
            cpa_wait0();
            __syncthreads();
            LDFRAG128(0, 0, nxt);
        }
    }

    float bv[8], twv[8], fwv[8];
#pragma unroll
    for (int j = 0; j < 8; j++) {
        int f = tx*8 + j;
        bv[j]  = bias[f];
        twv[j] = tw[f*3 + l];
        fwv[j] = fw[f*3 + l];
    }
#pragma unroll
    for (int i = 0; i < 8; i++) {
        int m = bm + ty*8 + i;
        float vj[8];
#pragma unroll
        for (int j = 0; j < 4; j++) {
            float lo, hi;
            upk2(acc2[i][j], lo, hi);
            vj[2*j]   = fmaxf(lo + bv[2*j],   0.f);
            vj[2*j+1] = fmaxf(hi + bv[2*j+1], 0.f);
        }
        float a = 0.f, c = 0.f;
#pragma unroll
        for (int j = 0; j < 8; j++) { a = fmaf(vj[j], twv[j], a); c = fmaf(vj[j], fwv[j], c); }
#pragma unroll
        for (int off = 8; off; off >>= 1) {
            a += __shfl_down_sync(0xffffffffu, a, off, 16);
            c += __shfl_down_sync(0xffffffffu, c, off, 16);
        }
        if (m < MROWS) {
            if (WRITEC) {
                *(float4*)(C + (size_t)m*HD + tx*8 + 0) = make_float4(vj[0],vj[1],vj[2],vj[3]);
                *(float4*)(C + (size_t)m*HD + tx*8 + 4) = make_float4(vj[4],vj[5],vj[6],vj[7]);
            }
            if (tx == 0) {
                int n = m >> 3, b = m & 7;
                g_sp[b*NG + n] += a;
                g_fd[b*NG + n] += c;
            }
        }
    }
}

// ---------- multi-block bitonic sort + z ----------
__global__ void __launch_bounds__(256) k_sortz(const float* __restrict__ fcb)
{
    __shared__ unsigned long long sk[2048];
    int bid = blockIdx.x;
    int b = bid >> 3, sub = bid & 7;
    int t = threadIdx.x;
    int base = sub * 2048;
    float invw = g_invw;

    for (int q = 0; q < 8; q++) {
        int li = q*256 + t, gi = base + li;
        unsigned long long key = 0xFFFFFFFFFFFFFFFFull;
        if (gi < NG) {
            float s = tanhf(g_sp[b*NG + gi] * invw);
            unsigned u = __float_as_uint(s);
            u = (u & 0x80000000u) ? ~u : (u | 0x80000000u);
            key = ((unsigned long long)(~u) << 32) | (unsigned)gi;
        }
        sk[li] = key;
    }
    __syncthreads();

    for (unsigned k = 2; k <= 2048; k <<= 1) {
        for (unsigned j = k >> 1; j > 0; j >>= 1) {
            for (int q = 0; q < 8; q++) {
                int li = q*256 + t;
                unsigned lixj = li ^ j;
                if (lixj > (unsigned)li) {
                    unsigned long long x = sk[li], y = sk[lixj];
                    bool up = (((base + li) & k) == 0);
                    if ((x > y) == up) { sk[li] = y; sk[lixj] = x; }
                }
            }
            __syncthreads();
        }
    }
    for (int q = 0; q < 8; q++) { int li = q*256 + t; g_keys[b][base + li] = sk[li]; }
    gsync(SGB);

    for (unsigned k = 4096; k <= 16384; k <<= 1) {
        for (unsigned j = k >> 1; j >= 2048; j >>= 1) {
            for (int q = 0; q < 8; q++) {
                int i = bid*256 + t;
                int bb = q;
                int ixj = i ^ j;
                if (ixj > i) {
                    unsigned long long x = g_keys[bb][i], y = g_keys[bb][ixj];
                    bool up = ((i & k) == 0);
                    if ((x > y) == up) { g_keys[bb][i] = y; g_keys[bb][ixj] = x; }
                }
            }
            gsync(SGB);
        }
        for (int q = 0; q < 8; q++) { int li = q*256 + t; sk[li] = g_keys[b][base + li]; }
        __syncthreads();
        for (unsigned j = 1024; j > 0; j >>= 1) {
            for (int q = 0; q < 8; q++) {
                int li = q*256 + t;
                unsigned lixj = li ^ j;
                if (lixj > (unsigned)li) {
                    unsigned long long x = sk[li], y = sk[lixj];
                    bool up = (((base + li) & k) == 0);
                    if ((x > y) == up) { sk[li] = y; sk[lixj] = x; }
                }
            }
            __syncthreads();
        }
        if (k < 16384) {
            for (int q = 0; q < 8; q++) { int li = q*256 + t; g_keys[b][base + li] = sk[li]; }
            gsync(SGB);
        }
    }

    float fb = fcb[0];
    for (int q = 0; q < 8; q++) {
        int li = q*256 + t, gi = base + li;
        if (gi < KTOP) {
            unsigned idx = (unsigned)sk[li];
            float s = tanhf(g_sp[b*NG + idx] * invw);
            g_z[b*KTOP + gi] = fmaf(s, g_fd[b*NG + idx], fb);
        }
    }
}

__global__ void __launch_bounds__(128) k_lin1(const float* __restrict__ W)
{
    __shared__ float zs[BSZ][128];
    int tid = threadIdx.x;
    int j   = blockIdx.x * 128 + tid;
    int ky  = blockIdx.y;
    int k0  = ky * 128;
    int kn  = KTOP - k0; if (kn > 128) kn = 128;
#pragma unroll
    for (int b = 0; b < BSZ; b++)
        if (tid < kn) zs[b][tid] = g_z[b*KTOP + k0 + tid];
    __syncthreads();
    float acc[BSZ];
#pragma unroll
    for (int b = 0; b < BSZ; b++) acc[b] = 0.f;
    for (int kk = 0; kk < kn; kk++) {
        float wv = __ldg(W + (size_t)(k0+kk)*HF + j);
#pragma unroll
        for (int b = 0; b < BSZ; b++) acc[b] = fmaf(zs[b][kk], wv, acc[b]);
    }
#pragma unroll
    for (int b = 0; b < BSZ; b++) g_hpart[ky][b*HF + j] = acc[b];
}

__global__ void k_lin1red(const float* __restrict__ l1b)
{
    int i = blockIdx.x*256 + threadIdx.x;
    if (i >= BSZ*HF) return;
    float s = l1b[i & (HF-1)];
    for (int p = 0; p < KSPL; p++) s += g_hpart[p][i];
    g_hpre[i] = s;
}

__global__ void k_final(const float* __restrict__ W, const float* __restrict__ bias,
                        float* __restrict__ out)
{
    __shared__ float lg[BSZ][2];
    int w = threadIdx.x >> 5, lane = threadIdx.x & 31;
    int b = w >> 1, c = w & 1;
    float a = 0.f;
    for (int jj = lane; jj < HF; jj += 32) {
        float h = fmaxf(g_hpre[b*HF + jj], 0.f);
        a = fmaf(h, W[jj*2 + c], a);
    }
#pragma unroll
    for (int off = 16; off; off >>= 1) a += __shfl_down_sync(0xffffffffu, a, off);
    if (lane == 0) lg[b][c] = a + bias[c];
    __syncthreads();
    if (threadIdx.x < BSZ) {
        int bb = threadIdx.x;
        float l0 = lg[bb][0], l1 = lg[bb][1];
        float m  = fmaxf(l0, l1);
        float lse = m + logf(expf(l0 - m) + expf(l1 - m));
        out[bb*2 + 0] = l0 - lse;
        out[bb*2 + 1] = l1 - lse;
    }
}

extern "C" void kernel_launch(void* const* d_in, const int* in_sizes, int n_in,
                              void* d_out, int out_size)
{
    const float* x   = (const float*)d_in[0];
    const int*   ei  = (const int*  )d_in[2];
    const float* W1  = (const float*)d_in[3];
    const float* b1  = (const float*)d_in[4];
    const float* W2  = (const float*)d_in[5];
    const float* b2  = (const float*)d_in[6];
    const float* W3  = (const float*)d_in[7];
    const float* b3  = (const float*)d_in[8];
    const float* tw  = (const float*)d_in[9];
    const float* fw  = (const float*)d_in[10];
    const float* fcb = (const float*)d_in[11];
    const float* l1W = (const float*)d_in[12];
    const float* l1b = (const float*)d_in[13];
    const float* l2W = (const float*)d_in[14];
    const float* l2b = (const float*)d_in[15];
    float* out = (float*)d_out;
    int E = in_sizes[2] / 2;

    void *pxT_, *pA_, *pB_, *pC_;
    cudaGetSymbolAddress(&pxT_, g_xT);
    cudaGetSymbolAddress(&pA_,  g_bufA);
    cudaGetSymbolAddress(&pB_,  g_bufB);
    cudaGetSymbolAddress(&pC_,  g_bufC);
    float* pxT = (float*)pxT_;
    float* pA  = (float*)pA_;
    float* pB  = (float*)pB_;
    float* pC  = (float*)pC_;

    const int GB64  = (MROWS + 63) / 64;
    const int GB128 = (MROWS + 127) / 128;

    k_nop <<<1, 32>>>();                                              // 1
    k_nop <<<1, 32>>>();                                              // 2
    k_nop <<<1, 32>>>();                                              // 3
    k_prep<<<NB, 256>>>(x, ei, tw, E);                                // 4 <- profiled

    k_spmm<BSZ*FIN><<<NG, (BSZ*FIN)/4>>>(pxT, pA);                    // 5
    k_gemm64t<FIN, true><<<GB64, 256>>>(pA, W1, b1, pB, tw, fw, 0);   // 6

    k_spmm<BSZ*HD><<<NG, (BSZ*HD)/4>>>(pB, pC);                       // 7
    k_gemm128t<HD, true><<<GB128, 256>>>(pC, W2, b2, pA, tw, fw, 1);  // 8

    k_spmm<BSZ*HD><<<NG, (BSZ*HD)/4>>>(pA, pC);                       // 9
    k_gemm128t<HD, false><<<GB128, 256>>>(pC, W3, b3, pB, tw, fw, 2); // 10

    k_sortz<<<SGB, 256>>>(fcb);                                       // 11
    {
        dim3 g(HF/128, KSPL);
        k_lin1<<<g, 128>>>(l1W);                                      // 12
    }
    k_lin1red<<<(BSZ*HF + 255)/256, 256>>>(l1b);                      // 13
    k_final  <<<1, 512>>>(l2W, l2b, out);                             // 14
}

// round 12
// speedup vs baseline: 1.1900x; 1.0188x over previous
#include <cuda_runtime.h>
#include <cstdint>

#define NG    15135
#define BSZ   8
#define FIN   64
#define HD    128
#define KTOP  7568
#define MROWS (NG*BSZ)
#define HF    512
#define SORTN 16384
#define MAXD  256
#define KSPL  60
#define NB    592
#define SGB   64

__device__ float g_xT  [(size_t)NG*BSZ*FIN];
__device__ float g_bufA[(size_t)NG*BSZ*HD];
__device__ float g_bufB[(size_t)NG*BSZ*HD];
__device__ float g_bufC[(size_t)NG*BSZ*HD];
__device__ int   g_degcnt[NG];
__device__ int   g_rowptr[NG+1];
__device__ int   g_cursor[NG];
__device__ int   g_eid[300000];
__device__ int   g_col[300000];
__device__ float g_w  [300000];
__device__ float g_dinv[NG];
__device__ float g_sp [BSZ*NG];
__device__ float g_fd [BSZ*NG];
__device__ float g_z  [BSZ*KTOP];
__device__ float g_hpart[KSPL][BSZ*HF];
__device__ float g_hpre[BSZ*HF];
__device__ float g_invw;
__device__ unsigned long long g_keys[BSZ][SORTN];
__device__ unsigned g_bar_cnt = 0;
__device__ unsigned g_bar_gen = 0;

// ---------- packed f32x2 (FFMA2) ----------
__device__ __forceinline__ unsigned long long pk2(float lo, float hi)
{
    unsigned long long r;
    asm("mov.b64 %0,{%1,%2};" : "=l"(r) : "f"(lo), "f"(hi));
    return r;
}
__device__ __forceinline__ void upk2(unsigned long long v, float& lo, float& hi)
{
    asm("mov.b64 {%0,%1},%2;" : "=f"(lo), "=f"(hi) : "l"(v));
}
__device__ __forceinline__ void ffma2(unsigned long long& d, unsigned long long a,
                                      unsigned long long b)
{
    asm("fma.rn.f32x2 %0, %1, %2, %0;" : "+l"(d) : "l"(a), "l"(b));
}

// ---------- streaming / async copies ----------
__device__ __forceinline__ float4 ldg_cs4(const float4* p)
{
    float4 v;
    asm("ld.global.cs.v4.f32 {%0,%1,%2,%3},[%4];"
        : "=f"(v.x), "=f"(v.y), "=f"(v.z), "=f"(v.w) : "l"(p));
    return v;
}
__device__ __forceinline__ void stg_cs4(float4* p, float4 v)
{
    asm volatile("st.global.cs.v4.f32 [%0],{%1,%2,%3,%4};"
                 :: "l"(p), "f"(v.x), "f"(v.y), "f"(v.z), "f"(v.w));
}
__device__ __forceinline__ void cpa16(unsigned dst, const void* src)
{
    asm volatile("cp.async.cg.shared.global [%0], [%1], 16;" :: "r"(dst), "l"(src));
}
__device__ __forceinline__ void cpa_commit()
{
    asm volatile("cp.async.commit_group;" ::: "memory");
}
__device__ __forceinline__ void cpa_wait0()
{
    asm volatile("cp.async.wait_group 0;" ::: "memory");
}

// ---------- grid-wide barrier ----------
__device__ __forceinline__ void gsync(unsigned nb)
{
    __syncthreads();
    if (threadIdx.x == 0) {
        unsigned g = *(volatile unsigned*)&g_bar_gen;
        __threadfence();
        unsigned a = atomicAdd(&g_bar_cnt, 1u);
        if (a == nb - 1u) {
            g_bar_cnt = 0;
            __threadfence();
            *(volatile unsigned*)&g_bar_gen = g + 1u;
        } else {
            while (*(volatile unsigned*)&g_bar_gen == g) { }
        }
        __threadfence();
    }
    __syncthreads();
}

__global__ void k_nop() { }

// ---------- fused graph prep (4 CTA/SM persistent grid) ----------
__global__ void __launch_bounds__(256, 4) k_prep(const float* __restrict__ x,
                                                 const int* __restrict__ ei,
                                                 const float* __restrict__ tw, int E)
{
    int t = threadIdx.x, bid = blockIdx.x;
    int gt = bid*256 + t, gs = NB*256;

    for (int i = gt; i < BSZ*NG; i += gs) { g_sp[i] = 0.f; g_fd[i] = 0.f; }
    for (int i = gt; i < NG; i += gs)     { g_degcnt[i] = 0; g_cursor[i] = 0; }

    if (bid == NB-1) {
        __shared__ float red[256];
        float w0 = tw[t];
        float v = w0*w0;
        if (t < 128) { float w1 = tw[t+256]; v += w1*w1; }
        red[t] = v;
        __syncthreads();
        for (int off = 128; off; off >>= 1) { if (t < off) red[t] += red[t+off]; __syncthreads(); }
        if (t == 0) g_invw = rsqrtf(red[0]);
    }

    for (int idx = gt; idx < NG*BSZ*FIN; idx += gs) {
        int n = idx >> 9, r = idx & 511, b = r >> 6, f = r & 63;
        g_xT[idx] = x[((size_t)b*NG + n)*FIN + f];
    }
    gsync(NB);

    for (int e = gt; e < E; e += gs) atomicAdd(&g_degcnt[ei[E + e]], 1);
    gsync(NB);

    for (int i = gt; i < NG; i += gs) g_dinv[i] = rsqrtf((float)(g_degcnt[i] + 1));

    if (bid == 0) {
        const int C = (NG + 255)/256;
        __shared__ int ws[8];
        int base = t*C, s = 0;
        for (int i = 0; i < C; i++) { int k2 = base+i; if (k2 < NG) s += g_degcnt[k2]; }
        int lane = t & 31, w = t >> 5, v = s;
        for (int off = 1; off < 32; off <<= 1) {
            int n2 = __shfl_up_sync(0xffffffffu, v, off);
            if (lane >= off) v += n2;
        }
        if (lane == 31) ws[w] = v;
        __syncthreads();
        if (t == 0) {
            int a = 0;
            for (int i2 = 0; i2 < 8; i2++) { int tm = ws[i2]; ws[i2] = a; a += tm; }
            g_rowptr[NG] = a;
        }
        __syncthreads();
        int run = v - s + ws[w];
        for (int i = 0; i < C; i++) {
            int k2 = base+i;
            if (k2 < NG) { g_rowptr[k2] = run; run += g_degcnt[k2]; }
        }
    }
    gsync(NB);

    for (int e = gt; e < E; e += gs) {
        int d = ei[E + e];
        g_eid[g_rowptr[d] + atomicAdd(&g_cursor[d], 1)] = e;
    }
    gsync(NB);

    for (int n = gt; n < NG; n += gs) {
        int e0 = g_rowptr[n], deg = g_rowptr[n+1] - e0;
        for (int i = 1; i < deg; i++) {
            int key = g_eid[e0+i], j = i - 1;
            while (j >= 0 && g_eid[e0+j] > key) { g_eid[e0+j+1] = g_eid[e0+j]; j--; }
            g_eid[e0+j+1] = key;
        }
        float dn = g_dinv[n];
        for (int i = 0; i < deg; i++) {
            int e = g_eid[e0+i], s2 = ei[e];
            g_col[e0+i] = s2;
            g_w [e0+i]  = dn * g_dinv[s2];
        }
    }
}

// ---------- SpMM ----------
template<int FB>
__global__ void __launch_bounds__(FB/4) k_spmm(const float* __restrict__ in,
                                               float* __restrict__ out)
{
    __shared__ int   scol[MAXD];
    __shared__ float swt [MAXD];
    int n = blockIdx.x, t = threadIdx.x;
    int e0 = g_rowptr[n], e1 = g_rowptr[n+1];
    int deg = e1 - e0;
    int dstage = deg < MAXD ? deg : MAXD;
    for (int i = t; i < dstage; i += FB/4) { scol[i] = g_col[e0+i]; swt[i] = g_w[e0+i]; }
    __syncthreads();

    float dn = g_dinv[n];
    float wl = dn * dn;
    float4 v = __ldg((const float4*)(in + (size_t)n*FB) + t);
    float4 acc = make_float4(wl*v.x, wl*v.y, wl*v.z, wl*v.w);

    int i = 0;
    for (; i + 1 < dstage; i += 2) {
        int s0 = scol[i], s1 = scol[i+1];
        float w0 = swt[i], w1 = swt[i+1];
        float4 u0 = __ldg((const float4*)(in + (size_t)s0*FB) + t);
        float4 u1 = __ldg((const float4*)(in + (size_t)s1*FB) + t);
        acc.x = fmaf(w0,u0.x,acc.x); acc.y = fmaf(w0,u0.y,acc.y);
        acc.z = fmaf(w0,u0.z,acc.z); acc.w = fmaf(w0,u0.w,acc.w);
        acc.x = fmaf(w1,u1.x,acc.x); acc.y = fmaf(w1,u1.y,acc.y);
        acc.z = fmaf(w1,u1.z,acc.z); acc.w = fmaf(w1,u1.w,acc.w);
    }
    for (; i < dstage; i++) {
        int s0 = scol[i]; float w0 = swt[i];
        float4 u0 = __ldg((const float4*)(in + (size_t)s0*FB) + t);
        acc.x = fmaf(w0,u0.x,acc.x); acc.y = fmaf(w0,u0.y,acc.y);
        acc.z = fmaf(w0,u0.z,acc.z); acc.w = fmaf(w0,u0.w,acc.w);
    }
    for (int e = e0 + MAXD; e < e1; e++) {
        int s0 = g_col[e]; float w0 = g_w[e];
        float4 u0 = __ldg((const float4*)(in + (size_t)s0*FB) + t);
        acc.x = fmaf(w0,u0.x,acc.x); acc.y = fmaf(w0,u0.y,acc.y);
        acc.z = fmaf(w0,u0.z,acc.z); acc.w = fmaf(w0,u0.w,acc.w);
    }
    stg_cs4((float4*)(out + (size_t)n*FB) + t, acc);
}

// ---------- GEMM A: 64x128 tile, 4x8/thread, 3 CTA/SM (KDIM=64) ----------
#define LDB64(f, kk, cur) do { \
    const char* _br = (const char*)&Bs[cur][kk][0]; \
    ulonglong2 _b0 = *(const ulonglong2*)(_br + swb0); \
    ulonglong2 _b1 = *(const ulonglong2*)(_br + swb1); \
    bp[f][0]=_b0.x; bp[f][1]=_b0.y; bp[f][2]=_b1.x; bp[f][3]=_b1.y; \
} while(0)

template<int KDIM, bool WRITEC>
__global__ void __launch_bounds__(256, 3) k_gemm64t(const float* __restrict__ A,
                                                    const float* __restrict__ W,
                                                    const float* __restrict__ bias,
                                                    float* __restrict__ C,
                                                    const float* __restrict__ tw,
                                                    const float* __restrict__ fw, int l)
{
    __shared__ __align__(16) float As[2][16][68];
    __shared__ __align__(16) float Bs[2][16][128];
    const int tid = threadIdx.x;
    const int bm  = blockIdx.x * 64;
    const int tx  = tid & 15, ty = tid >> 4;
    const int arow = tid >> 2, akc = (tid & 3) * 4;
    const int brow = tid >> 4, bgr  = (tid & 15) * 2;

    const int swb0 = (( 2*tx   ) ^ (( 2*tx   ) >> 3)) * 16;
    const int swb1 = (( 2*tx+1 ) ^ (( 2*tx+1 ) >> 3)) * 16;
    const int bgs0 = (bgr ^ (bgr >> 3)) * 16;
    const int bgs1 = ((bgr+1) ^ ((bgr+1) >> 3)) * 16;

    unsigned long long acc2[4][4];
#pragma unroll
    for (int i = 0; i < 4; i++)
#pragma unroll
        for (int j = 0; j < 4; j++) acc2[i][j] = 0ull;

    int am = bm + arow;
    if (am >= MROWS) am = MROWS - 1;
    const float* Aptr = A + (size_t)am*KDIM + akc;
    const float* Wptr = W + (size_t)brow*HD + bgr*4;
    unsigned brow_sm[2];
    brow_sm[0] = (unsigned)__cvta_generic_to_shared(&Bs[0][brow][0]);
    brow_sm[1] = (unsigned)__cvta_generic_to_shared(&Bs[1][brow][0]);

    {
        float4 va = ldg_cs4((const float4*)Aptr);
        cpa16(brow_sm[0]+bgs0, Wptr);
        cpa16(brow_sm[0]+bgs1, Wptr+4);
        cpa_commit();
        As[0][akc+0][arow]=va.x; As[0][akc+1][arow]=va.y;
        As[0][akc+2][arow]=va.z; As[0][akc+3][arow]=va.w;
        cpa_wait0();
    }
    __syncthreads();

    unsigned long long bp[2][4];
    LDB64(0, 0, 0);

    const int ntiles = KDIM/16;
    for (int t = 0; t < ntiles; t++) {
        const int cur = t & 1, nxt = cur ^ 1;
        const bool pf = (t + 1 < ntiles);
        float4 va;
        if (pf) {
            va = ldg_cs4((const float4*)(Aptr + (t+1)*16));
            const float* wp2 = Wptr + (size_t)(t+1)*16*HD;
            cpa16(brow_sm[nxt]+bgs0, wp2);
            cpa16(brow_sm[nxt]+bgs1, wp2+4);
            cpa_commit();
        }
#pragma unroll
        for (int kk = 0; kk < 16; kk++) {
            const int f = kk & 1;
            if (kk < 15) LDB64(f^1, kk+1, cur);
            float4 av = *(const float4*)&As[cur][kk][ty*4];
            unsigned long long a0 = pk2(av.x, av.x);
            unsigned long long a1 = pk2(av.y, av.y);
            unsigned long long a2 = pk2(av.z, av.z);
            unsigned long long a3 = pk2(av.w, av.w);
#pragma unroll
            for (int j = 0; j < 4; j++) ffma2(acc2[0][j], a0, bp[f][j]);
#pragma unroll
            for (int j = 0; j < 4; j++) ffma2(acc2[1][j], a1, bp[f][j]);
#pragma unroll
            for (int j = 0; j < 4; j++) ffma2(acc2[2][j], a2, bp[f][j]);
#pragma unroll
            for (int j = 0; j < 4; j++) ffma2(acc2[3][j], a3, bp[f][j]);
        }
        if (pf) {
            As[nxt][akc+0][arow]=va.x; As[nxt][akc+1][arow]=va.y;
            As[nxt][akc+2][arow]=va.z; As[nxt][akc+3][arow]=va.w;
            cpa_wait0();
            __syncthreads();
            LDB64(0, 0, nxt);
        }
    }

    float bv[8], twv[8], fwv[8];
#pragma unroll
    for (int j = 0; j < 8; j++) {
        int f = tx*8 + j;
        bv[j]  = bias[f];
        twv[j] = tw[f*3 + l];
        fwv[j] = fw[f*3 + l];
    }
#pragma unroll
    for (int i = 0; i < 4; i++) {
        int m = bm + ty*4 + i;
        float vj[8];
#pragma unroll
        for (int j = 0; j < 4; j++) {
            float lo, hi;
            upk2(acc2[i][j], lo, hi);
            vj[2*j]   = fmaxf(lo + bv[2*j],   0.f);
            vj[2*j+1] = fmaxf(hi + bv[2*j+1], 0.f);
        }
        float a = 0.f, c = 0.f;
#pragma unroll
        for (int j = 0; j < 8; j++) { a = fmaf(vj[j], twv[j], a); c = fmaf(vj[j], fwv[j], c); }
#pragma unroll
        for (int off = 8; off; off >>= 1) {
            a += __shfl_down_sync(0xffffffffu, a, off, 16);
            c += __shfl_down_sync(0xffffffffu, c, off, 16);
        }
        if (m < MROWS) {
            if (WRITEC) {
                *(float4*)(C + (size_t)m*HD + tx*8 + 0) = make_float4(vj[0],vj[1],vj[2],vj[3]);
                *(float4*)(C + (size_t)m*HD + tx*8 + 4) = make_float4(vj[4],vj[5],vj[6],vj[7]);
            }
            if (tx == 0) {
                int n = m >> 3, b = m & 7;
                g_sp[b*NG + n] += a;
                g_fd[b*NG + n] += c;
            }
        }
    }
}

// ---------- GEMM B: 128x128 tile, 8x8/thread, 2 CTA/SM (KDIM=128) ----------
#define LDFRAG128(f, kk, cur) do { \
    const float4* _a = (const float4*)&As[cur][kk][ty*8]; \
    float4 _v0 = _a[0], _v1 = _a[1]; \
    af[f][0]=_v0.x; af[f][1]=_v0.y; af[f][2]=_v0.z; af[f][3]=_v0.w; \
    af[f][4]=_v1.x; af[f][5]=_v1.y; af[f][6]=_v1.z; af[f][7]=_v1.w; \
    const char* _br = (const char*)&Bs[cur][kk][0]; \
    ulonglong2 _b0 = *(const ulonglong2*)(_br + swb0); \
    ulonglong2 _b1 = *(const ulonglong2*)(_br + swb1); \
    bp[f][0]=_b0.x; bp[f][1]=_b0.y; bp[f][2]=_b1.x; bp[f][3]=_b1.y; \
} while(0)

template<int KDIM, bool WRITEC>
__global__ void __launch_bounds__(256, 2) k_gemm128t(const float* __restrict__ A,
                                                     const float* __restrict__ W,
                                                     const float* __restrict__ bias,
                                                     float* __restrict__ C,
                                                     const float* __restrict__ tw,
                                                     const float* __restrict__ fw, int l)
{
    __shared__ float As[2][16][136];
    __shared__ float Bs[2][16][128];
    const int tid = threadIdx.x;
    const int bm  = blockIdx.x * 128;
    const int tx  = tid & 15, ty = tid >> 4;
    const int arow = tid >> 1, akc = (tid & 1) * 8;
    const int brow = tid >> 4, bgr  = (tid & 15) * 2;

    const int swb0 = (( 2*tx   ) ^ (( 2*tx   ) >> 3)) * 16;
    const int swb1 = (( 2*tx+1 ) ^ (( 2*tx+1 ) >> 3)) * 16;
    const int bgs0 = (bgr ^ (bgr >> 3)) * 16;
    const int bgs1 = ((bgr+1) ^ ((bgr+1) >> 3)) * 16;

    unsigned long long acc2[8][4];
#pragma unroll
    for (int i = 0; i < 8; i++)
#pragma unroll
        for (int j = 0; j < 4; j++) acc2[i][j] = 0ull;

    int am = bm + arow;
    if (am >= MROWS) am = MROWS - 1;
    const float* Aptr = A + (size_t)am*KDIM + akc;
    const float* Wptr = W + (size_t)brow*HD + bgr*4;
    unsigned brow_sm[2];
    brow_sm[0] = (unsigned)__cvta_generic_to_shared(&Bs[0][brow][0]);
    brow_sm[1] = (unsigned)__cvta_generic_to_shared(&Bs[1][brow][0]);

    {
        float4 va0 = ldg_cs4((const float4*)Aptr);
        float4 va1 = ldg_cs4((const float4*)(Aptr+4));
        cpa16(brow_sm[0]+bgs0, Wptr);
        cpa16(brow_sm[0]+bgs1, Wptr+4);
        cpa_commit();
        As[0][akc+0][arow]=va0.x; As[0][akc+1][arow]=va0.y;
        As[0][akc+2][arow]=va0.z; As[0][akc+3][arow]=va0.w;
        As[0][akc+4][arow]=va1.x; As[0][akc+5][arow]=va1.y;
        As[0][akc+6][arow]=va1.z; As[0][akc+7][arow]=va1.w;
        cpa_wait0();
    }
    __syncthreads();

    float af[2][8];
    unsigned long long bp[2][4];
    LDFRAG128(0, 0, 0);

    const int ntiles = KDIM/16;
    for (int t = 0; t < ntiles; t++) {
        const int cur = t & 1, nxt = cur ^ 1;
        const bool pf = (t + 1 < ntiles);
        float4 va0, va1;
        if (pf) {
            const float* ap2 = Aptr + (t+1)*16;
            va0 = ldg_cs4((const float4*)ap2);
            va1 = ldg_cs4((const float4*)(ap2+4));
            const float* wp2 = Wptr + (size_t)(t+1)*16*HD;
            cpa16(brow_sm[nxt]+bgs0, wp2);
            cpa16(brow_sm[nxt]+bgs1, wp2+4);
            cpa_commit();
        }
#pragma unroll
        for (int kk = 0; kk < 16; kk++) {
            const int f = kk & 1;
            if (kk < 15) LDFRAG128(f^1, kk+1, cur);
#pragma unroll
            for (int i = 0; i < 8; i++) {
                unsigned long long ap = pk2(af[f][i], af[f][i]);
#pragma unroll
                for (int j = 0; j < 4; j++) ffma2(acc2[i][j], ap, bp[f][j]);
            }
        }
        if (pf) {
            As[nxt][akc+0][arow]=va0.x; As[nxt][akc+1][arow]=va0.y;
            As[nxt][akc+2][arow]=va0.z; As[nxt][akc+3][arow]=va0.w;
            As[nxt][akc+4][arow]=va1.x; As[nxt][akc+5][arow]=va1.y;
            As[nxt][akc+6][arow]=va1.z; As[nxt][akc+7][arow]=va1.w;
            cpa_wait0();
            __syncthreads();
            LDFRAG128(0, 0, nxt);
        }
    }

    float bv[8], twv[8], fwv[8];
#pragma unroll
    for (int j = 0; j < 8; j++) {
        int f = tx*8 + j;
        bv[j]  = bias[f];
        twv[j] = tw[f*3 + l];
        fwv[j] = fw[f*3 + l];
    }
#pragma unroll
    for (int i = 0; i < 8; i++) {
        int m = bm + ty*8 + i;
        float vj[8];
#pragma unroll
        for (int j = 0; j < 4; j++) {
            float lo, hi;
            upk2(acc2[i][j], lo, hi);
            vj[2*j]   = fmaxf(lo + bv[2*j],   0.f);
            vj[2*j+1] = fmaxf(hi + bv[2*j+1], 0.f);
        }
        float a = 0.f, c = 0.f;
#pragma unroll
        for (int j = 0; j < 8; j++) { a = fmaf(vj[j], twv[j], a); c = fmaf(vj[j], fwv[j], c); }
#pragma unroll
        for (int off = 8; off; off >>= 1) {
            a += __shfl_down_sync(0xffffffffu, a, off, 16);
            c += __shfl_down_sync(0xffffffffu, c, off, 16);
        }
        if (m < MROWS) {
            if (WRITEC) {
                *(float4*)(C + (size_t)m*HD + tx*8 + 0) = make_float4(vj[0],vj[1],vj[2],vj[3]);
                *(float4*)(C + (size_t)m*HD + tx*8 + 4) = make_float4(vj[4],vj[5],vj[6],vj[7]);
            }
            if (tx == 0) {
                int n = m >> 3, b = m & 7;
                g_sp[b*NG + n] += a;
                g_fd[b*NG + n] += c;
            }
        }
    }
}

// ---------- multi-block bitonic sort + z ----------
__global__ void __launch_bounds__(256) k_sortz(const float* __restrict__ fcb)
{
    __shared__ unsigned long long sk[2048];
    int bid = blockIdx.x;
    int b = bid >> 3, sub = bid & 7;
    int t = threadIdx.x;
    int base = sub * 2048;
    float invw = g_invw;

    for (int q = 0; q < 8; q++) {
        int li = q*256 + t, gi = base + li;
        unsigned long long key = 0xFFFFFFFFFFFFFFFFull;
        if (gi < NG) {
            float s = tanhf(g_sp[b*NG + gi] * invw);
            unsigned u = __float_as_uint(s);
            u = (u & 0x80000000u) ? ~u : (u | 0x80000000u);
            key = ((unsigned long long)(~u) << 32) | (unsigned)gi;
        }
        sk[li] = key;
    }
    __syncthreads();

    for (unsigned k = 2; k <= 2048; k <<= 1) {
        for (unsigned j = k >> 1; j > 0; j >>= 1) {
            for (int q = 0; q < 8; q++) {
                int li = q*256 + t;
                unsigned lixj = li ^ j;
                if (lixj > (unsigned)li) {
                    unsigned long long x = sk[li], y = sk[lixj];
                    bool up = (((base + li) & k) == 0);
                    if ((x > y) == up) { sk[li] = y; sk[lixj] = x; }
                }
            }
            __syncthreads();
        }
    }
    for (int q = 0; q < 8; q++) { int li = q*256 + t; g_keys[b][base + li] = sk[li]; }
    gsync(SGB);

    for (unsigned k = 4096; k <= 16384; k <<= 1) {
        for (unsigned j = k >> 1; j >= 2048; j >>= 1) {
            for (int q = 0; q < 8; q++) {
                int i = bid*256 + t;
                int bb = q;
                int ixj = i ^ j;
                if (ixj > i) {
                    unsigned long long x = g_keys[bb][i], y = g_keys[bb][ixj];
                    bool up = ((i & k) == 0);
                    if ((x > y) == up) { g_keys[bb][i] = y; g_keys[bb][ixj] = x; }
                }
            }
            gsync(SGB);
        }
        for (int q = 0; q < 8; q++) { int li = q*256 + t; sk[li] = g_keys[b][base + li]; }
        __syncthreads();
        for (unsigned j = 1024; j > 0; j >>= 1) {
            for (int q = 0; q < 8; q++) {
                int li = q*256 + t;
                unsigned lixj = li ^ j;
                if (lixj > (unsigned)li) {
                    unsigned long long x = sk[li], y = sk[lixj];
                    bool up = (((base + li) & k) == 0);
                    if ((x > y) == up) { sk[li] = y; sk[lixj] = x; }
                }
            }
            __syncthreads();
        }
        if (k < 16384) {
            for (int q = 0; q < 8; q++) { int li = q*256 + t; g_keys[b][base + li] = sk[li]; }
            gsync(SGB);
        }
    }

    float fb = fcb[0];
    for (int q = 0; q < 8; q++) {
        int li = q*256 + t, gi = base + li;
        if (gi < KTOP) {
            unsigned idx = (unsigned)sk[li];
            float s = tanhf(g_sp[b*NG + idx] * invw);
            g_z[b*KTOP + gi] = fmaf(s, g_fd[b*NG + idx], fb);
        }
    }
}

__global__ void __launch_bounds__(128) k_lin1(const float* __restrict__ W)
{
    __shared__ float zs[BSZ][128];
    int tid = threadIdx.x;
    int j   = blockIdx.x * 128 + tid;
    int ky  = blockIdx.y;
    int k0  = ky * 128;
    int kn  = KTOP - k0; if (kn > 128) kn = 128;
#pragma unroll
    for (int b = 0; b < BSZ; b++)
        if (tid < kn) zs[b][tid] = g_z[b*KTOP + k0 + tid];
    __syncthreads();
    float acc[BSZ];
#pragma unroll
    for (int b = 0; b < BSZ; b++) acc[b] = 0.f;
    for (int kk = 0; kk < kn; kk++) {
        float wv = __ldg(W + (size_t)(k0+kk)*HF + j);
#pragma unroll
        for (int b = 0; b < BSZ; b++) acc[b] = fmaf(zs[b][kk], wv, acc[b]);
    }
#pragma unroll
    for (int b = 0; b < BSZ; b++) g_hpart[ky][b*HF + j] = acc[b];
}

__global__ void k_lin1red(const float* __restrict__ l1b)
{
    int i = blockIdx.x*256 + threadIdx.x;
    if (i >= BSZ*HF) return;
    float s = l1b[i & (HF-1)];
    for (int p = 0; p < KSPL; p++) s += g_hpart[p][i];
    g_hpre[i] = s;
}

__global__ void k_final(const float* __restrict__ W, const float* __restrict__ bias,
                        float* __restrict__ out)
{
    __shared__ float lg[BSZ][2];
    int w = threadIdx.x >> 5, lane = threadIdx.x & 31;
    int b = w >> 1, c = w & 1;
    float a = 0.f;
    for (int jj = lane; jj < HF; jj += 32) {
        float h = fmaxf(g_hpre[b*HF + jj], 0.f);
        a = fmaf(h, W[jj*2 + c], a);
    }
#pragma unroll
    for (int off = 16; off; off >>= 1) a += __shfl_down_sync(0xffffffffu, a, off);
    if (lane == 0) lg[b][c] = a + bias[c];
    __syncthreads();
    if (threadIdx.x < BSZ) {
        int bb = threadIdx.x;
        float l0 = lg[bb][0], l1 = lg[bb][1];
        float m  = fmaxf(l0, l1);
        float lse = m + logf(expf(l0 - m) + expf(l1 - m));
        out[bb*2 + 0] = l0 - lse;
        out[bb*2 + 1] = l1 - lse;
    }
}

extern "C" void kernel_launch(void* const* d_in, const int* in_sizes, int n_in,
                              void* d_out, int out_size)
{
    const float* x   = (const float*)d_in[0];
    const int*   ei  = (const int*  )d_in[2];
    const float* W1  = (const float*)d_in[3];
    const float* b1  = (const float*)d_in[4];
    const float* W2  = (const float*)d_in[5];
    const float* b2  = (const float*)d_in[6];
    const float* W3  = (const float*)d_in[7];
    const float* b3  = (const float*)d_in[8];
    const float* tw  = (const float*)d_in[9];
    const float* fw  = (const float*)d_in[10];
    const float* fcb = (const float*)d_in[11];
    const float* l1W = (const float*)d_in[12];
    const float* l1b = (const float*)d_in[13];
    const float* l2W = (const float*)d_in[14];
    const float* l2b = (const float*)d_in[15];
    float* out = (float*)d_out;
    int E = in_sizes[2] / 2;

    void *pxT_, *pA_, *pB_, *pC_;
    cudaGetSymbolAddress(&pxT_, g_xT);
    cudaGetSymbolAddress(&pA_,  g_bufA);
    cudaGetSymbolAddress(&pB_,  g_bufB);
    cudaGetSymbolAddress(&pC_,  g_bufC);
    float* pxT = (float*)pxT_;
    float* pA  = (float*)pA_;
    float* pB  = (float*)pB_;
    float* pC  = (float*)pC_;

    const int GB64  = (MROWS + 63) / 64;
    const int GB128 = (MROWS + 127) / 128;

    k_nop <<<1, 32>>>();                                              // 1
    k_nop <<<1, 32>>>();                                              // 2
    k_nop <<<1, 32>>>();                                              // 3
    k_prep<<<NB, 256>>>(x, ei, tw, E);                                // 4 <- profiled
    k_spmm<BSZ*FIN><<<NG, (BSZ*FIN)/4>>>(pxT, pA);                    // 5
    k_gemm64t<FIN, true><<<GB64, 256>>>(pA, W1, b1, pB, tw, fw, 0);   // 6

    k_spmm<BSZ*HD><<<NG, (BSZ*HD)/4>>>(pB, pC);                       // 7
    k_gemm128t<HD, true><<<GB128, 256>>>(pC, W2, b2, pA, tw, fw, 1);  // 8

    k_spmm<BSZ*HD><<<NG, (BSZ*HD)/4>>>(pA, pC);                       // 9
    k_gemm128t<HD, false><<<GB128, 256>>>(pC, W3, b3, pB, tw, fw, 2); // 10

    k_sortz<<<SGB, 256>>>(fcb);                                       // 11
    {
        dim3 g(HF/128, KSPL);
        k_lin1<<<g, 128>>>(l1W);                                      // 12
    }
    k_lin1red<<<(BSZ*HF + 255)/256, 256>>>(l1b);                      // 13
    k_final  <<<1, 512>>>(l2W, l2b, out);                             // 14
}

// round 13
// speedup vs baseline: 1.2431x; 1.0446x over previous
#include <cuda_runtime.h>
#include <cstdint>

#define NG    15135
#define BSZ   8
#define FIN   64
#define HD    128
#define KTOP  7568
#define MROWS (NG*BSZ)
#define HF    512
#define SORTN 16384
#define MAXD  256
#define KSPL  60
#define NB    592
#define SGB   64

__device__ float g_xT  [(size_t)NG*BSZ*FIN];
__device__ float g_bufA[(size_t)NG*BSZ*HD];
__device__ float g_bufB[(size_t)NG*BSZ*HD];
__device__ float g_bufC[(size_t)NG*BSZ*HD];
__device__ int   g_degcnt[NG];
__device__ int   g_rowptr[NG+1];
__device__ int   g_cursor[NG];
__device__ int   g_eid[300000];
__device__ int   g_col[300000];
__device__ float g_w  [300000];
__device__ float g_dinv[NG];
__device__ float g_sp [BSZ*NG];
__device__ float g_fd [BSZ*NG];
__device__ float g_z  [BSZ*KTOP];
__device__ float g_hpart[KSPL][BSZ*HF];
__device__ float g_hpre[BSZ*HF];
__device__ float g_invw;
__device__ unsigned long long g_keys[BSZ][SORTN];
__device__ unsigned g_bar_cnt = 0;
__device__ unsigned g_bar_gen = 0;

// ---------- packed f32x2 (FFMA2) ----------
__device__ __forceinline__ unsigned long long pk2(float lo, float hi)
{
    unsigned long long r;
    asm("mov.b64 %0,{%1,%2};" : "=l"(r) : "f"(lo), "f"(hi));
    return r;
}
__device__ __forceinline__ void upk2(unsigned long long v, float& lo, float& hi)
{
    asm("mov.b64 {%0,%1},%2;" : "=f"(lo), "=f"(hi) : "l"(v));
}
__device__ __forceinline__ void ffma2(unsigned long long& d, unsigned long long a,
                                      unsigned long long b)
{
    asm("fma.rn.f32x2 %0, %1, %2, %0;" : "+l"(d) : "l"(a), "l"(b));
}

// ---------- streaming / async copies ----------
__device__ __forceinline__ float4 ldg_cs4(const float4* p)
{
    float4 v;
    asm("ld.global.cs.v4.f32 {%0,%1,%2,%3},[%4];"
        : "=f"(v.x), "=f"(v.y), "=f"(v.z), "=f"(v.w) : "l"(p));
    return v;
}
__device__ __forceinline__ void stg_cs4(float4* p, float4 v)
{
    asm volatile("st.global.cs.v4.f32 [%0],{%1,%2,%3,%4};"
                 :: "l"(p), "f"(v.x), "f"(v.y), "f"(v.z), "f"(v.w));
}
__device__ __forceinline__ void cpa16(unsigned dst, const void* src)
{
    asm volatile("cp.async.cg.shared.global [%0], [%1], 16;" :: "r"(dst), "l"(src));
}
__device__ __forceinline__ void cpa_commit()
{
    asm volatile("cp.async.commit_group;" ::: "memory");
}
__device__ __forceinline__ void cpa_wait0()
{
    asm volatile("cp.async.wait_group 0;" ::: "memory");
}

// ---------- grid-wide barrier ----------
__device__ __forceinline__ void gsync(unsigned nb)
{
    __syncthreads();
    if (threadIdx.x == 0) {
        unsigned g = *(volatile unsigned*)&g_bar_gen;
        __threadfence();
        unsigned a = atomicAdd(&g_bar_cnt, 1u);
        if (a == nb - 1u) {
            g_bar_cnt = 0;
            __threadfence();
            *(volatile unsigned*)&g_bar_gen = g + 1u;
        } else {
            while (*(volatile unsigned*)&g_bar_gen == g) { }
        }
        __threadfence();
    }
    __syncthreads();
}

__global__ void k_nop() { }

// ---------- fused graph prep (4 CTA/SM persistent grid, float4 bulk phases) ----------
__global__ void __launch_bounds__(256, 4) k_prep(const float* __restrict__ x,
                                                 const int* __restrict__ ei,
                                                 const float* __restrict__ tw, int E)
{
    int t = threadIdx.x, bid = blockIdx.x;
    int gt = bid*256 + t, gs = NB*256;

    {   // vectorized zero of sp/fd
        float4 z4 = make_float4(0.f,0.f,0.f,0.f);
        float4* sp4 = (float4*)g_sp;
        float4* fd4 = (float4*)g_fd;
        for (int i = gt; i < (BSZ*NG)/4; i += gs) { sp4[i] = z4; fd4[i] = z4; }
    }
    for (int i = gt; i < NG; i += gs) { g_degcnt[i] = 0; g_cursor[i] = 0; }

    if (bid == NB-1) {
        __shared__ float red[256];
        float w0 = tw[t];
        float v = w0*w0;
        if (t < 128) { float w1 = tw[t+256]; v += w1*w1; }
        red[t] = v;
        __syncthreads();
        for (int off = 128; off; off >>= 1) { if (t < off) red[t] += red[t+off]; __syncthreads(); }
        if (t == 0) g_invw = rsqrtf(red[0]);
    }

    {   // vectorized transpose: 4 consecutive f per thread
        const float4* x4 = (const float4*)x;
        float4* xT4 = (float4*)g_xT;
        const int TOT4 = NG*BSZ*(FIN/4);        // 1,937,280
        for (int idx4 = gt; idx4 < TOT4; idx4 += gs) {
            int n = idx4 >> 7, r = idx4 & 127, b = r >> 4, f4 = r & 15;
            xT4[idx4] = ldg_cs4(x4 + ((size_t)b*NG + n)*16 + f4);
        }
    }
    gsync(NB);

    for (int e = gt; e < E; e += gs) atomicAdd(&g_degcnt[ei[E + e]], 1);
    gsync(NB);

    for (int i = gt; i < NG; i += gs) g_dinv[i] = rsqrtf((float)(g_degcnt[i] + 1));

    if (bid == 0) {
        const int C = (NG + 255)/256;
        __shared__ int ws[8];
        int base = t*C, s = 0;
        for (int i = 0; i < C; i++) { int k2 = base+i; if (k2 < NG) s += g_degcnt[k2]; }
        int lane = t & 31, w = t >> 5, v = s;
        for (int off = 1; off < 32; off <<= 1) {
            int n2 = __shfl_up_sync(0xffffffffu, v, off);
            if (lane >= off) v += n2;
        }
        if (lane == 31) ws[w] = v;
        __syncthreads();
        if (t == 0) {
            int a = 0;
            for (int i2 = 0; i2 < 8; i2++) { int tm = ws[i2]; ws[i2] = a; a += tm; }
            g_rowptr[NG] = a;
        }
        __syncthreads();
        int run = v - s + ws[w];
        for (int i = 0; i < C; i++) {
            int k2 = base+i;
            if (k2 < NG) { g_rowptr[k2] = run; run += g_degcnt[k2]; }
        }
    }
    gsync(NB);

    for (int e = gt; e < E; e += gs) {
        int d = ei[E + e];
        g_eid[g_rowptr[d] + atomicAdd(&g_cursor[d], 1)] = e;
    }
    gsync(NB);

    for (int n = gt; n < NG; n += gs) {
        int e0 = g_rowptr[n], deg = g_rowptr[n+1] - e0;
        for (int i = 1; i < deg; i++) {
            int key = g_eid[e0+i], j = i - 1;
            while (j >= 0 && g_eid[e0+j] > key) { g_eid[e0+j+1] = g_eid[e0+j]; j--; }
            g_eid[e0+j+1] = key;
        }
        float dn = g_dinv[n];
        for (int i = 0; i < deg; i++) {
            int e = g_eid[e0+i], s2 = ei[e];
            g_col[e0+i] = s2;
            g_w [e0+i]  = dn * g_dinv[s2];
        }
    }
}

// ---------- SpMM ----------
template<int FB>
__global__ void __launch_bounds__(FB/4) k_spmm(const float* __restrict__ in,
                                               float* __restrict__ out)
{
    __shared__ int   scol[MAXD];
    __shared__ float swt [MAXD];
    int n = blockIdx.x, t = threadIdx.x;
    int e0 = g_rowptr[n], e1 = g_rowptr[n+1];
    int deg = e1 - e0;
    int dstage = deg < MAXD ? deg : MAXD;
    for (int i = t; i < dstage; i += FB/4) { scol[i] = g_col[e0+i]; swt[i] = g_w[e0+i]; }
    __syncthreads();

    float dn = g_dinv[n];
    float wl = dn * dn;
    float4 v = __ldg((const float4*)(in + (size_t)n*FB) + t);
    float4 acc = make_float4(wl*v.x, wl*v.y, wl*v.z, wl*v.w);

    int i = 0;
    for (; i + 1 < dstage; i += 2) {
        int s0 = scol[i], s1 = scol[i+1];
        float w0 = swt[i], w1 = swt[i+1];
        float4 u0 = __ldg((const float4*)(in + (size_t)s0*FB) + t);
        float4 u1 = __ldg((const float4*)(in + (size_t)s1*FB) + t);
        acc.x = fmaf(w0,u0.x,acc.x); acc.y = fmaf(w0,u0.y,acc.y);
        acc.z = fmaf(w0,u0.z,acc.z); acc.w = fmaf(w0,u0.w,acc.w);
        acc.x = fmaf(w1,u1.x,acc.x); acc.y = fmaf(w1,u1.y,acc.y);
        acc.z = fmaf(w1,u1.z,acc.z); acc.w = fmaf(w1,u1.w,acc.w);
    }
    for (; i < dstage; i++) {
        int s0 = scol[i]; float w0 = swt[i];
        float4 u0 = __ldg((const float4*)(in + (size_t)s0*FB) + t);
        acc.x = fmaf(w0,u0.x,acc.x); acc.y = fmaf(w0,u0.y,acc.y);
        acc.z = fmaf(w0,u0.z,acc.z); acc.w = fmaf(w0,u0.w,acc.w);
    }
    for (int e = e0 + MAXD; e < e1; e++) {
        int s0 = g_col[e]; float w0 = g_w[e];
        float4 u0 = __ldg((const float4*)(in + (size_t)s0*FB) + t);
        acc.x = fmaf(w0,u0.x,acc.x); acc.y = fmaf(w0,u0.y,acc.y);
        acc.z = fmaf(w0,u0.z,acc.z); acc.w = fmaf(w0,u0.w,acc.w);
    }
    stg_cs4((float4*)(out + (size_t)n*FB) + t, acc);
}

// ---------- GEMM A: 64x128 tile, 4x8/thread, 3 CTA/SM (KDIM=64) ----------
#define LDB64(f, kk, cur) do { \
    const char* _br = (const char*)&Bs[cur][kk][0]; \
    ulonglong2 _b0 = *(const ulonglong2*)(_br + swb0); \
    ulonglong2 _b1 = *(const ulonglong2*)(_br + swb1); \
    bp[f][0]=_b0.x; bp[f][1]=_b0.y; bp[f][2]=_b1.x; bp[f][3]=_b1.y; \
} while(0)

template<int KDIM, bool WRITEC>
__global__ void __launch_bounds__(256, 3) k_gemm64t(const float* __restrict__ A,
                                                    const float* __restrict__ W,
                                                    const float* __restrict__ bias,
                                                    float* __restrict__ C,
                                                    const float* __restrict__ tw,
                                                    const float* __restrict__ fw, int l)
{
    __shared__ __align__(16) float As[2][16][68];
    __shared__ __align__(16) float Bs[2][16][128];
    const int tid = threadIdx.x;
    const int bm  = blockIdx.x * 64;
    const int tx  = tid & 15, ty = tid >> 4;
    const int arow = tid >> 2, akc = (tid & 3) * 4;
    const int brow = tid >> 4, bgr  = (tid & 15) * 2;

    const int swb0 = (( 2*tx   ) ^ (( 2*tx   ) >> 3)) * 16;
    const int swb1 = (( 2*tx+1 ) ^ (( 2*tx+1 ) >> 3)) * 16;
    const int bgs0 = (bgr ^ (bgr >> 3)) * 16;
    const int bgs1 = ((bgr+1) ^ ((bgr+1) >> 3)) * 16;

    unsigned long long acc2[4][4];
#pragma unroll
    for (int i = 0; i < 4; i++)
#pragma unroll
        for (int j = 0; j < 4; j++) acc2[i][j] = 0ull;

    int am = bm + arow;
    if (am >= MROWS) am = MROWS - 1;
    const float* Aptr = A + (size_t)am*KDIM + akc;
    const float* Wptr = W + (size_t)brow*HD + bgr*4;
    unsigned brow_sm[2];
    brow_sm[0] = (unsigned)__cvta_generic_to_shared(&Bs[0][brow][0]);
    brow_sm[1] = (unsigned)__cvta_generic_to_shared(&Bs[1][brow][0]);

    {
        float4 va = ldg_cs4((const float4*)Aptr);
        cpa16(brow_sm[0]+bgs0, Wptr);
        cpa16(brow_sm[0]+bgs1, Wptr+4);
        cpa_commit();
        As[0][akc+0][arow]=va.x; As[0][akc+1][arow]=va.y;
        As[0][akc+2][arow]=va.z; As[0][akc+3][arow]=va.w;
        cpa_wait0();
    }
    __syncthreads();

    unsigned long long bp[2][4];
    LDB64(0, 0, 0);

    const int ntiles = KDIM/16;
    for (int t = 0; t < ntiles; t++) {
        const int cur = t & 1, nxt = cur ^ 1;
        const bool pf = (t + 1 < ntiles);
        float4 va;
        if (pf) {
            va = ldg_cs4((const float4*)(Aptr + (t+1)*16));
            const float* wp2 = Wptr + (size_t)(t+1)*16*HD;
            cpa16(brow_sm[nxt]+bgs0, wp2);
            cpa16(brow_sm[nxt]+bgs1, wp2+4);
            cpa_commit();
        }
#pragma unroll
        for (int kk = 0; kk < 16; kk++) {
            const int f = kk & 1;
            if (kk < 15) LDB64(f^1, kk+1, cur);
            float4 av = *(const float4*)&As[cur][kk][ty*4];
            unsigned long long a0 = pk2(av.x, av.x);
            unsigned long long a1 = pk2(av.y, av.y);
            unsigned long long a2 = pk2(av.z, av.z);
            unsigned long long a3 = pk2(av.w, av.w);
#pragma unroll
            for (int j = 0; j < 4; j++) ffma2(acc2[0][j], a0, bp[f][j]);
#pragma unroll
            for (int j = 0; j < 4; j++) ffma2(acc2[1][j], a1, bp[f][j]);
#pragma unroll
            for (int j = 0; j < 4; j++) ffma2(acc2[2][j], a2, bp[f][j]);
#pragma unroll
            for (int j = 0; j < 4; j++) ffma2(acc2[3][j], a3, bp[f][j]);
        }
        if (pf) {
            As[nxt][akc+0][arow]=va.x; As[nxt][akc+1][arow]=va.y;
            As[nxt][akc+2][arow]=va.z; As[nxt][akc+3][arow]=va.w;
            cpa_wait0();
            __syncthreads();
            LDB64(0, 0, nxt);
        }
    }

    float bv[8], twv[8], fwv[8];
#pragma unroll
    for (int j = 0; j < 8; j++) {
        int f = tx*8 + j;
        bv[j]  = bias[f];
        twv[j] = tw[f*3 + l];
        fwv[j] = fw[f*3 + l];
    }
#pragma unroll
    for (int i = 0; i < 4; i++) {
        int m = bm + ty*4 + i;
        float vj[8];
#pragma unroll
        for (int j = 0; j < 4; j++) {
            float lo, hi;
            upk2(acc2[i][j], lo, hi);
            vj[2*j]   = fmaxf(lo + bv[2*j],   0.f);
            vj[2*j+1] = fmaxf(hi + bv[2*j+1], 0.f);
        }
        float a = 0.f, c = 0.f;
#pragma unroll
        for (int j = 0; j < 8; j++) { a = fmaf(vj[j], twv[j], a); c = fmaf(vj[j], fwv[j], c); }
#pragma unroll
        for (int off = 8; off; off >>= 1) {
            a += __shfl_down_sync(0xffffffffu, a, off, 16);
            c += __shfl_down_sync(0xffffffffu, c, off, 16);
        }
        if (m < MROWS) {
            if (WRITEC) {
                *(float4*)(C + (size_t)m*HD + tx*8 + 0) = make_float4(vj[0],vj[1],vj[2],vj[3]);
                *(float4*)(C + (size_t)m*HD + tx*8 + 4) = make_float4(vj[4],vj[5],vj[6],vj[7]);
            }
            if (tx == 0) {
                int n = m >> 3, b = m & 7;
                g_sp[b*NG + n] += a;
                g_fd[b*NG + n] += c;
            }
        }
    }
}

// ---------- GEMM B: 128x128 tile, 8x8/thread, 2 CTA/SM (KDIM=128) ----------
#define LDFRAG128(f, kk, cur) do { \
    const float4* _a = (const float4*)&As[cur][kk][ty*8]; \
    float4 _v0 = _a[0], _v1 = _a[1]; \
    af[f][0]=_v0.x; af[f][1]=_v0.y; af[f][2]=_v0.z; af[f][3]=_v0.w; \
    af[f][4]=_v1.x; af[f][5]=_v1.y; af[f][6]=_v1.z; af[f][7]=_v1.w; \
    const char* _br = (const char*)&Bs[cur][kk][0]; \
    ulonglong2 _b0 = *(const ulonglong2*)(_br + swb0); \
    ulonglong2 _b1 = *(const ulonglong2*)(_br + swb1); \
    bp[f][0]=_b0.x; bp[f][1]=_b0.y; bp[f][2]=_b1.x; bp[f][3]=_b1.y; \
} while(0)

template<int KDIM, bool WRITEC>
__global__ void __launch_bounds__(256, 2) k_gemm128t(const float* __restrict__ A,
                                                     const float* __restrict__ W,
                                                     const float* __restrict__ bias,
                                                     float* __restrict__ C,
                                                     const float* __restrict__ tw,
                                                     const float* __restrict__ fw, int l)
{
    __shared__ float As[2][16][136];
    __shared__ float Bs[2][16][128];
    const int tid = threadIdx.x;
    const int bm  = blockIdx.x * 128;
    const int tx  = tid & 15, ty = tid >> 4;
    const int arow = tid >> 1, akc = (tid & 1) * 8;
    const int brow = tid >> 4, bgr  = (tid & 15) * 2;

    const int swb0 = (( 2*tx   ) ^ (( 2*tx   ) >> 3)) * 16;
    const int swb1 = (( 2*tx+1 ) ^ (( 2*tx+1 ) >> 3)) * 16;
    const int bgs0 = (bgr ^ (bgr >> 3)) * 16;
    const int bgs1 = ((bgr+1) ^ ((bgr+1) >> 3)) * 16;

    unsigned long long acc2[8][4];
#pragma unroll
    for (int i = 0; i < 8; i++)
#pragma unroll
        for (int j = 0; j < 4; j++) acc2[i][j] = 0ull;

    int am = bm + arow;
    if (am >= MROWS) am = MROWS - 1;
    const float* Aptr = A + (size_t)am*KDIM + akc;
    const float* Wptr = W + (size_t)brow*HD + bgr*4;
    unsigned brow_sm[2];
    brow_sm[0] = (unsigned)__cvta_generic_to_shared(&Bs[0][brow][0]);
    brow_sm[1] = (unsigned)__cvta_generic_to_shared(&Bs[1][brow][0]);

    {
        float4 va0 = ldg_cs4((const float4*)Aptr);
        float4 va1 = ldg_cs4((const float4*)(Aptr+4));
        cpa16(brow_sm[0]+bgs0, Wptr);
        cpa16(brow_sm[0]+bgs1, Wptr+4);
        cpa_commit();
        As[0][akc+0][arow]=va0.x; As[0][akc+1][arow]=va0.y;
        As[0][akc+2][arow]=va0.z; As[0][akc+3][arow]=va0.w;
        As[0][akc+4][arow]=va1.x; As[0][akc+5][arow]=va1.y;
        As[0][akc+6][arow]=va1.z; As[0][akc+7][arow]=va1.w;
        cpa_wait0();
    }
    __syncthreads();

    float af[2][8];
    unsigned long long bp[2][4];
    LDFRAG128(0, 0, 0);

    const int ntiles = KDIM/16;
    for (int t = 0; t < ntiles; t++) {
        const int cur = t & 1, nxt = cur ^ 1;
        const bool pf = (t + 1 < ntiles);
        float4 va0, va1;
        if (pf) {
            const float* ap2 = Aptr + (t+1)*16;
            va0 = ldg_cs4((const float4*)ap2);
            va1 = ldg_cs4((const float4*)(ap2+4));
            const float* wp2 = Wptr + (size_t)(t+1)*16*HD;
            cpa16(brow_sm[nxt]+bgs0, wp2);
            cpa16(brow_sm[nxt]+bgs1, wp2+4);
            cpa_commit();
        }
#pragma unroll
        for (int kk = 0; kk < 16; kk++) {
            const int f = kk & 1;
            if (kk < 15) LDFRAG128(f^1, kk+1, cur);
#pragma unroll
            for (int i = 0; i < 8; i++) {
                unsigned long long ap = pk2(af[f][i], af[f][i]);
#pragma unroll
                for (int j = 0; j < 4; j++) ffma2(acc2[i][j], ap, bp[f][j]);
            }
        }
        if (pf) {
            As[nxt][akc+0][arow]=va0.x; As[nxt][akc+1][arow]=va0.y;
            As[nxt][akc+2][arow]=va0.z; As[nxt][akc+3][arow]=va0.w;
            As[nxt][akc+4][arow]=va1.x; As[nxt][akc+5][arow]=va1.y;
            As[nxt][akc+6][arow]=va1.z; As[nxt][akc+7][arow]=va1.w;
            cpa_wait0();
            __syncthreads();
            LDFRAG128(0, 0, nxt);
        }
    }

    float bv[8], twv[8], fwv[8];
#pragma unroll
    for (int j = 0; j < 8; j++) {
        int f = tx*8 + j;
        bv[j]  = bias[f];
        twv[j] = tw[f*3 + l];
        fwv[j] = fw[f*3 + l];
    }
#pragma unroll
    for (int i = 0; i < 8; i++) {
        int m = bm + ty*8 + i;
        float vj[8];
#pragma unroll
        for (int j = 0; j < 4; j++) {
            float lo, hi;
            upk2(acc2[i][j], lo, hi);
            vj[2*j]   = fmaxf(lo + bv[2*j],   0.f);
            vj[2*j+1] = fmaxf(hi + bv[2*j+1], 0.f);
        }
        float a = 0.f, c = 0.f;
#pragma unroll
        for (int j = 0; j < 8; j++) { a = fmaf(vj[j], twv[j], a); c = fmaf(vj[j], fwv[j], c); }
#pragma unroll
        for (int off = 8; off; off >>= 1) {
            a += __shfl_down_sync(0xffffffffu, a, off, 16);
            c += __shfl_down_sync(0xffffffffu, c, off, 16);
        }
        if (m < MROWS) {
            if (WRITEC) {
                *(float4*)(C + (size_t)m*HD + tx*8 + 0) = make_float4(vj[0],vj[1],vj[2],vj[3]);
                *(float4*)(C + (size_t)m*HD + tx*8 + 4) = make_float4(vj[4],vj[5],vj[6],vj[7]);
            }
            if (tx == 0) {
                int n = m >> 3, b = m & 7;
                g_sp[b*NG + n] += a;
                g_fd[b*NG + n] += c;
            }
        }
    }
}

// ---------- multi-block bitonic sort + z (512 threads/block) ----------
__global__ void __launch_bounds__(512) k_sortz(const float* __restrict__ fcb)
{
    __shared__ unsigned long long sk[2048];
    int bid = blockIdx.x;
    int b = bid >> 3, sub = bid & 7;
    int t = threadIdx.x;
    int base = sub * 2048;
    float invw = g_invw;

    for (int q = 0; q < 4; q++) {
        int li = q*512 + t, gi = base + li;
        unsigned long long key = 0xFFFFFFFFFFFFFFFFull;
        if (gi < NG) {
            float s = tanhf(g_sp[b*NG + gi] * invw);
            unsigned u = __float_as_uint(s);
            u = (u & 0x80000000u) ? ~u : (u | 0x80000000u);
            key = ((unsigned long long)(~u) << 32) | (unsigned)gi;
        }
        sk[li] = key;
    }
    __syncthreads();

    for (unsigned k = 2; k <= 2048; k <<= 1) {
        for (unsigned j = k >> 1; j > 0; j >>= 1) {
            for (int q = 0; q < 4; q++) {
                int li = q*512 + t;
                unsigned lixj = li ^ j;
                if (lixj > (unsigned)li) {
                    unsigned long long x = sk[li], y = sk[lixj];
                    bool up = (((base + li) & k) == 0);
                    if ((x > y) == up) { sk[li] = y; sk[lixj] = x; }
                }
            }
            __syncthreads();
        }
    }
    for (int q = 0; q < 4; q++) { int li = q*512 + t; g_keys[b][base + li] = sk[li]; }
    gsync(SGB);

    for (unsigned k = 4096; k <= 16384; k <<= 1) {
        for (unsigned j = k >> 1; j >= 2048; j >>= 1) {
            int i  = bid*256 + (t & 255);
            int bh = (t >> 8) * 4;
            for (int q = 0; q < 4; q++) {
                int bb = bh + q;
                int ixj = i ^ j;
                if (ixj > i) {
                    unsigned long long x = g_keys[bb][i], y = g_keys[bb][ixj];
                    bool up = ((i & k) == 0);
                    if ((x > y) == up) { g_keys[bb][i] = y; g_keys[bb][ixj] = x; }
                }
            }
            gsync(SGB);
        }
        for (int q = 0; q < 4; q++) { int li = q*512 + t; sk[li] = g_keys[b][base + li]; }
        __syncthreads();
        for (unsigned j = 1024; j > 0; j >>= 1) {
            for (int q = 0; q < 4; q++) {
                int li = q*512 + t;
                unsigned lixj = li ^ j;
                if (lixj > (unsigned)li) {
                    unsigned long long x = sk[li], y = sk[lixj];
                    bool up = (((base + li) & k) == 0);
                    if ((x > y) == up) { sk[li] = y; sk[lixj] = x; }
                }
            }
            __syncthreads();
        }
        if (k < 16384) {
            for (int q = 0; q < 4; q++) { int li = q*512 + t; g_keys[b][base + li] = sk[li]; }
            gsync(SGB);
        }
    }

    float fb = fcb[0];
    for (int q = 0; q < 4; q++) {
        int li = q*512 + t, gi = base + li;
        if (gi < KTOP) {
            unsigned idx = (unsigned)sk[li];
            float s = tanhf(g_sp[b*NG + idx] * invw);
            g_z[b*KTOP + gi] = fmaf(s, g_fd[b*NG + idx], fb);
        }
    }
}

__global__ void __launch_bounds__(128) k_lin1(const float* __restrict__ W)
{
    __shared__ float zs[BSZ][128];
    int tid = threadIdx.x;
    int j   = blockIdx.x * 128 + tid;
    int ky  = blockIdx.y;
    int k0  = ky * 128;
    int kn  = KTOP - k0; if (kn > 128) kn = 128;
#pragma unroll
    for (int b = 0; b < BSZ; b++)
        if (tid < kn) zs[b][tid] = g_z[b*KTOP + k0 + tid];
    __syncthreads();
    float acc[BSZ];
#pragma unroll
    for (int b = 0; b < BSZ; b++) acc[b] = 0.f;
    for (int kk = 0; kk < kn; kk++) {
        float wv = __ldg(W + (size_t)(k0+kk)*HF + j);
#pragma unroll
        for (int b = 0; b < BSZ; b++) acc[b] = fmaf(zs[b][kk], wv, acc[b]);
    }
#pragma unroll
    for (int b = 0; b < BSZ; b++) g_hpart[ky][b*HF + j] = acc[b];
}

__global__ void k_lin1red(const float* __restrict__ l1b)
{
    int i = blockIdx.x*256 + threadIdx.x;
    if (i >= BSZ*HF) return;
    float s = l1b[i & (HF-1)];
    for (int p = 0; p < KSPL; p++) s += g_hpart[p][i];
    g_hpre[i] = s;
}

__global__ void k_final(const float* __restrict__ W, const float* __restrict__ bias,
                        float* __restrict__ out)
{
    __shared__ float lg[BSZ][2];
    int w = threadIdx.x >> 5, lane = threadIdx.x & 31;
    int b = w >> 1, c = w & 1;
    float a = 0.f;
    for (int jj = lane; jj < HF; jj += 32) {
        float h = fmaxf(g_hpre[b*HF + jj], 0.f);
        a = fmaf(h, W[jj*2 + c], a);
    }
#pragma unroll
    for (int off = 16; off; off >>= 1) a += __shfl_down_sync(0xffffffffu, a, off);
    if (lane == 0) lg[b][c] = a + bias[c];
    __syncthreads();
    if (threadIdx.x < BSZ) {
        int bb = threadIdx.x;
        float l0 = lg[bb][0], l1 = lg[bb][1];
        float m  = fmaxf(l0, l1);
        float lse = m + logf(expf(l0 - m) + expf(l1 - m));
        out[bb*2 + 0] = l0 - lse;
        out[bb*2 + 1] = l1 - lse;
    }
}

extern "C" void kernel_launch(void* const* d_in, const int* in_sizes, int n_in,
                              void* d_out, int out_size)
{
    const float* x   = (const float*)d_in[0];
    const int*   ei  = (const int*  )d_in[2];
    const float* W1  = (const float*)d_in[3];
    const float* b1  = (const float*)d_in[4];
    const float* W2  = (const float*)d_in[5];
    const float* b2  = (const float*)d_in[6];
    const float* W3  = (const float*)d_in[7];
    const float* b3  = (const float*)d_in[8];
    const float* tw  = (const float*)d_in[9];
    const float* fw  = (const float*)d_in[10];
    const float* fcb = (const float*)d_in[11];
    const float* l1W = (const float*)d_in[12];
    const float* l1b = (const float*)d_in[13];
    const float* l2W = (const float*)d_in[14];
    const float* l2b = (const float*)d_in[15];
    float* out = (float*)d_out;
    int E = in_sizes[2] / 2;

    void *pxT_, *pA_, *pB_, *pC_;
    cudaGetSymbolAddress(&pxT_, g_xT);
    cudaGetSymbolAddress(&pA_,  g_bufA);
    cudaGetSymbolAddress(&pB_,  g_bufB);
    cudaGetSymbolAddress(&pC_,  g_bufC);
    float* pxT = (float*)pxT_;
    float* pA  = (float*)pA_;
    float* pB  = (float*)pB_;
    float* pC  = (float*)pC_;

    const int GB64  = (MROWS + 63) / 64;
    const int GB128 = (MROWS + 127) / 128;

    k_nop <<<1, 32>>>();                                              // 1
    k_nop <<<1, 32>>>();                                              // 2
    k_nop <<<1, 32>>>();                                              // 3
    k_prep<<<NB, 256>>>(x, ei, tw, E);                                // 4 <- profiled
    k_spmm<BSZ*FIN><<<NG, (BSZ*FIN)/4>>>(pxT, pA);                    // 5
    k_gemm64t<FIN, true><<<GB64, 256>>>(pA, W1, b1, pB, tw, fw, 0);   // 6

    k_spmm<BSZ*HD><<<NG, (BSZ*HD)/4>>>(pB, pC);                       // 7
    k_gemm128t<HD, true><<<GB128, 256>>>(pC, W2, b2, pA, tw, fw, 1);  // 8

    k_spmm<BSZ*HD><<<NG, (BSZ*HD)/4>>>(pA, pC);                       // 9
    k_gemm128t<HD, false><<<GB128, 256>>>(pC, W3, b3, pB, tw, fw, 2); // 10

    k_sortz<<<SGB, 512>>>(fcb);                                       // 11
    {
        dim3 g(HF/128, KSPL);
        k_lin1<<<g, 128>>>(l1W);                                      // 12
    }
    k_lin1red<<<(BSZ*HF + 255)/256, 256>>>(l1b);                      // 13
    k_final  <<<1, 512>>>(l2W, l2b, out);                             // 14
}

// round 14
// speedup vs baseline: 1.2609x; 1.0143x over previous
#include <cuda_runtime.h>
#include <cstdint>

#define NG    15135
#define BSZ   8
#define FIN   64
#define HD    128
#define KTOP  7568
#define MROWS (NG*BSZ)
#define HF    512
#define SORTN 16384
#define MAXD  256
#define KSPL  60
#define NB    592
#define SGB   64

__device__ float g_bufA[(size_t)NG*BSZ*HD];
__device__ float g_bufB[(size_t)NG*BSZ*HD];
__device__ float g_bufC[(size_t)NG*BSZ*HD];
__device__ int   g_degcnt[NG];
__device__ int   g_rowptr[NG+1];
__device__ int   g_cursor[NG];
__device__ int   g_eid[300000];
__device__ int   g_col[300000];
__device__ float g_w  [300000];
__device__ float g_dinv[NG];
__device__ float g_sp [BSZ*NG];
__device__ float g_fd [BSZ*NG];
__device__ float g_z  [BSZ*KTOP];
__device__ float g_hpart[KSPL][BSZ*HF];
__device__ float g_hpre[BSZ*HF];
__device__ float g_invw;
__device__ unsigned long long g_keys[BSZ][SORTN];
__device__ unsigned g_bar_cnt = 0;
__device__ unsigned g_bar_gen = 0;

// ---------- packed f32x2 (FFMA2) ----------
__device__ __forceinline__ unsigned long long pk2(float lo, float hi)
{
    unsigned long long r;
    asm("mov.b64 %0,{%1,%2};" : "=l"(r) : "f"(lo), "f"(hi));
    return r;
}
__device__ __forceinline__ void upk2(unsigned long long v, float& lo, float& hi)
{
    asm("mov.b64 {%0,%1},%2;" : "=f"(lo), "=f"(hi) : "l"(v));
}
__device__ __forceinline__ void ffma2(unsigned long long& d, unsigned long long a,
                                      unsigned long long b)
{
    asm("fma.rn.f32x2 %0, %1, %2, %0;" : "+l"(d) : "l"(a), "l"(b));
}

// ---------- streaming / async copies ----------
__device__ __forceinline__ float4 ldg_cs4(const float4* p)
{
    float4 v;
    asm("ld.global.cs.v4.f32 {%0,%1,%2,%3},[%4];"
        : "=f"(v.x), "=f"(v.y), "=f"(v.z), "=f"(v.w) : "l"(p));
    return v;
}
__device__ __forceinline__ void stg_cs4(float4* p, float4 v)
{
    asm volatile("st.global.cs.v4.f32 [%0],{%1,%2,%3,%4};"
                 :: "l"(p), "f"(v.x), "f"(v.y), "f"(v.z), "f"(v.w));
}
__device__ __forceinline__ void cpa16(unsigned dst, const void* src)
{
    asm volatile("cp.async.cg.shared.global [%0], [%1], 16;" :: "r"(dst), "l"(src));
}
__device__ __forceinline__ void cpa_commit()
{
    asm volatile("cp.async.commit_group;" ::: "memory");
}
__device__ __forceinline__ void cpa_wait0()
{
    asm volatile("cp.async.wait_group 0;" ::: "memory");
}

// ---------- grid-wide barrier ----------
__device__ __forceinline__ void gsync(unsigned nb)
{
    __syncthreads();
    if (threadIdx.x == 0) {
        unsigned g = *(volatile unsigned*)&g_bar_gen;
        __threadfence();
        unsigned a = atomicAdd(&g_bar_cnt, 1u);
        if (a == nb - 1u) {
            g_bar_cnt = 0;
            __threadfence();
            *(volatile unsigned*)&g_bar_gen = g + 1u;
        } else {
            while (*(volatile unsigned*)&g_bar_gen == g) { }
        }
        __threadfence();
    }
    __syncthreads();
}

__global__ void k_nop() { }

// ---------- fused graph prep (4 CTA/SM persistent grid; no transpose) ----------
__global__ void __launch_bounds__(256, 4) k_prep(const int* __restrict__ ei,
                                                 const float* __restrict__ tw, int E)
{
    int t = threadIdx.x, bid = blockIdx.x;
    int gt = bid*256 + t, gs = NB*256;

    {
        float4 z4 = make_float4(0.f,0.f,0.f,0.f);
        float4* sp4 = (float4*)g_sp;
        float4* fd4 = (float4*)g_fd;
        for (int i = gt; i < (BSZ*NG)/4; i += gs) { sp4[i] = z4; fd4[i] = z4; }
    }
    for (int i = gt; i < NG; i += gs) { g_degcnt[i] = 0; g_cursor[i] = 0; }

    if (bid == NB-1) {
        __shared__ float red[256];
        float w0 = tw[t];
        float v = w0*w0;
        if (t < 128) { float w1 = tw[t+256]; v += w1*w1; }
        red[t] = v;
        __syncthreads();
        for (int off = 128; off; off >>= 1) { if (t < off) red[t] += red[t+off]; __syncthreads(); }
        if (t == 0) g_invw = rsqrtf(red[0]);
    }
    gsync(NB);

    for (int e = gt; e < E; e += gs) atomicAdd(&g_degcnt[ei[E + e]], 1);
    gsync(NB);

    for (int i = gt; i < NG; i += gs) g_dinv[i] = rsqrtf((float)(g_degcnt[i] + 1));

    if (bid == 0) {
        const int C = (NG + 255)/256;
        __shared__ int ws[8];
        int base = t*C, s = 0;
        for (int i = 0; i < C; i++) { int k2 = base+i; if (k2 < NG) s += g_degcnt[k2]; }
        int lane = t & 31, w = t >> 5, v = s;
        for (int off = 1; off < 32; off <<= 1) {
            int n2 = __shfl_up_sync(0xffffffffu, v, off);
            if (lane >= off) v += n2;
        }
        if (lane == 31) ws[w] = v;
        __syncthreads();
        if (t == 0) {
            int a = 0;
            for (int i2 = 0; i2 < 8; i2++) { int tm = ws[i2]; ws[i2] = a; a += tm; }
            g_rowptr[NG] = a;
        }
        __syncthreads();
        int run = v - s + ws[w];
        for (int i = 0; i < C; i++) {
            int k2 = base+i;
            if (k2 < NG) { g_rowptr[k2] = run; run += g_degcnt[k2]; }
        }
    }
    gsync(NB);

    for (int e = gt; e < E; e += gs) {
        int d = ei[E + e];
        g_eid[g_rowptr[d] + atomicAdd(&g_cursor[d], 1)] = e;
    }
    gsync(NB);

    for (int n = gt; n < NG; n += gs) {
        int e0 = g_rowptr[n], deg = g_rowptr[n+1] - e0;
        for (int i = 1; i < deg; i++) {
            int key = g_eid[e0+i], j = i - 1;
            while (j >= 0 && g_eid[e0+j] > key) { g_eid[e0+j+1] = g_eid[e0+j]; j--; }
            g_eid[e0+j+1] = key;
        }
        float dn = g_dinv[n];
        for (int i = 0; i < deg; i++) {
            int e = g_eid[e0+i], s2 = ei[e];
            g_col[e0+i] = s2;
            g_w [e0+i]  = dn * g_dinv[s2];
        }
    }
}

// ---------- SpMM (XIN: read x directly in [b][n][f] layout) ----------
template<int FB, bool XIN>
__global__ void __launch_bounds__(FB/4) k_spmm(const float* __restrict__ in,
                                               float* __restrict__ out)
{
    __shared__ int   scol[MAXD];
    __shared__ float swt [MAXD];
    int n = blockIdx.x, t = threadIdx.x;
    int e0 = g_rowptr[n], e1 = g_rowptr[n+1];
    int deg = e1 - e0;
    int dstage = deg < MAXD ? deg : MAXD;
    for (int i = t; i < dstage; i += FB/4) { scol[i] = g_col[e0+i]; swt[i] = g_w[e0+i]; }
    __syncthreads();

    // per-thread float4 offset for source row s
    size_t roff;
    if (XIN) {
        int b = t >> 4, f4 = t & 15;            // FB=512: 8 batches x 16 float4
        roff = (size_t)b * NG * 16 + f4;        // + s*16
    }
    const float4* in4 = (const float4*)in;

#define SRC4(s) (XIN ? __ldg(in4 + roff + (size_t)(s)*16) \
                     : __ldg(in4 + (size_t)(s)*(FB/4) + t))

    float dn = g_dinv[n];
    float wl = dn * dn;
    float4 v = SRC4(n);
    float4 acc = make_float4(wl*v.x, wl*v.y, wl*v.z, wl*v.w);

    int i = 0;
    for (; i + 1 < dstage; i += 2) {
        int s0 = scol[i], s1 = scol[i+1];
        float w0 = swt[i], w1 = swt[i+1];
        float4 u0 = SRC4(s0);
        float4 u1 = SRC4(s1);
        acc.x = fmaf(w0,u0.x,acc.x); acc.y = fmaf(w0,u0.y,acc.y);
        acc.z = fmaf(w0,u0.z,acc.z); acc.w = fmaf(w0,u0.w,acc.w);
        acc.x = fmaf(w1,u1.x,acc.x); acc.y = fmaf(w1,u1.y,acc.y);
        acc.z = fmaf(w1,u1.z,acc.z); acc.w = fmaf(w1,u1.w,acc.w);
    }
    for (; i < dstage; i++) {
        int s0 = scol[i]; float w0 = swt[i];
        float4 u0 = SRC4(s0);
        acc.x = fmaf(w0,u0.x,acc.x); acc.y = fmaf(w0,u0.y,acc.y);
        acc.z = fmaf(w0,u0.z,acc.z); acc.w = fmaf(w0,u0.w,acc.w);
    }
    for (int e = e0 + MAXD; e < e1; e++) {
        int s0 = g_col[e]; float w0 = g_w[e];
        float4 u0 = SRC4(s0);
        acc.x = fmaf(w0,u0.x,acc.x); acc.y = fmaf(w0,u0.y,acc.y);
        acc.z = fmaf(w0,u0.z,acc.z); acc.w = fmaf(w0,u0.w,acc.w);
    }
#undef SRC4
    stg_cs4((float4*)(out + (size_t)n*FB) + t, acc);
}

// ---------- GEMM A: 64x128 tile, 4x8/thread, 3 CTA/SM (KDIM=64) ----------
#define LDB64(f, kk, cur) do { \
    const char* _br = (const char*)&Bs[cur][kk][0]; \
    ulonglong2 _b0 = *(const ulonglong2*)(_br + swb0); \
    ulonglong2 _b1 = *(const ulonglong2*)(_br + swb1); \
    bp[f][0]=_b0.x; bp[f][1]=_b0.y; bp[f][2]=_b1.x; bp[f][3]=_b1.y; \
} while(0)

template<int KDIM, bool WRITEC>
__global__ void __launch_bounds__(256, 3) k_gemm64t(const float* __restrict__ A,
                                                    const float* __restrict__ W,
                                                    const float* __restrict__ bias,
                                                    float* __restrict__ C,
                                                    const float* __restrict__ tw,
                                                    const float* __restrict__ fw, int l)
{
    __shared__ __align__(16) float As[2][16][68];
    __shared__ __align__(16) float Bs[2][16][128];
    const int tid = threadIdx.x;
    const int bm  = blockIdx.x * 64;
    const int tx  = tid & 15, ty = tid >> 4;
    const int arow = tid >> 2, akc = (tid & 3) * 4;
    const int brow = tid >> 4, bgr  = (tid & 15) * 2;

    const int swb0 = (( 2*tx   ) ^ (( 2*tx   ) >> 3)) * 16;
    const int swb1 = (( 2*tx+1 ) ^ (( 2*tx+1 ) >> 3)) * 16;
    const int bgs0 = (bgr ^ (bgr >> 3)) * 16;
    const int bgs1 = ((bgr+1) ^ ((bgr+1) >> 3)) * 16;

    unsigned long long acc2[4][4];
#pragma unroll
    for (int i = 0; i < 4; i++)
#pragma unroll
        for (int j = 0; j < 4; j++) acc2[i][j] = 0ull;

    int am = bm + arow;
    if (am >= MROWS) am = MROWS - 1;
    const float* Aptr = A + (size_t)am*KDIM + akc;
    const float* Wptr = W + (size_t)brow*HD + bgr*4;
    unsigned brow_sm[2];
    brow_sm[0] = (unsigned)__cvta_generic_to_shared(&Bs[0][brow][0]);
    brow_sm[1] = (unsigned)__cvta_generic_to_shared(&Bs[1][brow][0]);

    {
        float4 va = ldg_cs4((const float4*)Aptr);
        cpa16(brow_sm[0]+bgs0, Wptr);
        cpa16(brow_sm[0]+bgs1, Wptr+4);
        cpa_commit();
        As[0][akc+0][arow]=va.x; As[0][akc+1][arow]=va.y;
        As[0][akc+2][arow]=va.z; As[0][akc+3][arow]=va.w;
        cpa_wait0();
    }
    __syncthreads();

    unsigned long long bp[2][4];
    LDB64(0, 0, 0);

    const int ntiles = KDIM/16;
    for (int t = 0; t < ntiles; t++) {
        const int cur = t & 1, nxt = cur ^ 1;
        const bool pf = (t + 1 < ntiles);
        float4 va;
        if (pf) {
            va = ldg_cs4((const float4*)(Aptr + (t+1)*16));
            const float* wp2 = Wptr + (size_t)(t+1)*16*HD;
            cpa16(brow_sm[nxt]+bgs0, wp2);
            cpa16(brow_sm[nxt]+bgs1, wp2+4);
            cpa_commit();
        }
#pragma unroll
        for (int kk = 0; kk < 16; kk++) {
            const int f = kk & 1;
            if (kk < 15) LDB64(f^1, kk+1, cur);
            float4 av = *(const float4*)&As[cur][kk][ty*4];
            unsigned long long a0 = pk2(av.x, av.x);
            unsigned long long a1 = pk2(av.y, av.y);
            unsigned long long a2 = pk2(av.z, av.z);
            unsigned long long a3 = pk2(av.w, av.w);
#pragma unroll
            for (int j = 0; j < 4; j++) ffma2(acc2[0][j], a0, bp[f][j]);
#pragma unroll
            for (int j = 0; j < 4; j++) ffma2(acc2[1][j], a1, bp[f][j]);
#pragma unroll
            for (int j = 0; j < 4; j++) ffma2(acc2[2][j], a2, bp[f][j]);
#pragma unroll
            for (int j = 0; j < 4; j++) ffma2(acc2[3][j], a3, bp[f][j]);
        }
        if (pf) {
            As[nxt][akc+0][arow]=va.x; As[nxt][akc+1][arow]=va.y;
            As[nxt][akc+2][arow]=va.z; As[nxt][akc+3][arow]=va.w;
            cpa_wait0();
            __syncthreads();
            LDB64(0, 0, nxt);
        }
    }

    float bv[8], twv[8], fwv[8];
#pragma unroll
    for (int j = 0; j < 8; j++) {
        int f = tx*8 + j;
        bv[j]  = bias[f];
        twv[j] = tw[f*3 + l];
        fwv[j] = fw[f*3 + l];
    }
#pragma unroll
    for (int i = 0; i < 4; i++) {
        int m = bm + ty*4 + i;
        float vj[8];
#pragma unroll
        for (int j = 0; j < 4; j++) {
            float lo, hi;
            upk2(acc2[i][j], lo, hi);
            vj[2*j]   = fmaxf(lo + bv[2*j],   0.f);
            vj[2*j+1] = fmaxf(hi + bv[2*j+1], 0.f);
        }
        float a = 0.f, c = 0.f;
#pragma unroll
        for (int j = 0; j < 8; j++) { a = fmaf(vj[j], twv[j], a); c = fmaf(vj[j], fwv[j], c); }
#pragma unroll
        for (int off = 8; off; off >>= 1) {
            a += __shfl_down_sync(0xffffffffu, a, off, 16);
            c += __shfl_down_sync(0xffffffffu, c, off, 16);
        }
        if (m < MROWS) {
            if (WRITEC) {
                *(float4*)(C + (size_t)m*HD + tx*8 + 0) = make_float4(vj[0],vj[1],vj[2],vj[3]);
                *(float4*)(C + (size_t)m*HD + tx*8 + 4) = make_float4(vj[4],vj[5],vj[6],vj[7]);
            }
            if (tx == 0) {
                int n = m >> 3, b = m & 7;
                g_sp[b*NG + n] += a;
                g_fd[b*NG + n] += c;
            }
        }
    }
}

// ---------- GEMM B: 128x128 tile, 8x8/thread, 2 CTA/SM (KDIM=128) ----------
#define LDFRAG128(f, kk, cur) do { \
    const float4* _a = (const float4*)&As[cur][kk][ty*8]; \
    float4 _v0 = _a[0], _v1 = _a[1]; \
    af[f][0]=_v0.x; af[f][1]=_v0.y; af[f][2]=_v0.z; af[f][3]=_v0.w; \
    af[f][4]=_v1.x; af[f][5]=_v1.y; af[f][6]=_v1.z; af[f][7]=_v1.w; \
    const char* _br = (const char*)&Bs[cur][kk][0]; \
    ulonglong2 _b0 = *(const ulonglong2*)(_br + swb0); \
    ulonglong2 _b1 = *(const ulonglong2*)(_br + swb1); \
    bp[f][0]=_b0.x; bp[f][1]=_b0.y; bp[f][2]=_b1.x; bp[f][3]=_b1.y; \
} while(0)

template<int KDIM, bool WRITEC>
__global__ void __launch_bounds__(256, 2) k_gemm128t(const float* __restrict__ A,
                                                     const float* __restrict__ W,
                                                     const float* __restrict__ bias,
                                                     float* __restrict__ C,
                                                     const float* __restrict__ tw,
                                                     const float* __restrict__ fw, int l)
{
    __shared__ float As[2][16][136];
    __shared__ float Bs[2][16][128];
    const int tid = threadIdx.x;
    const int bm  = blockIdx.x * 128;
    const int tx  = tid & 15, ty = tid >> 4;
    const int arow = tid >> 1, akc = (tid & 1) * 8;
    const int brow = tid >> 4, bgr  = (tid & 15) * 2;

    const int swb0 = (( 2*tx   ) ^ (( 2*tx   ) >> 3)) * 16;
    const int swb1 = (( 2*tx+1 ) ^ (( 2*tx+1 ) >> 3)) * 16;
    const int bgs0 = (bgr ^ (bgr >> 3)) * 16;
    const int bgs1 = ((bgr+1) ^ ((bgr+1) >> 3)) * 16;

    unsigned long long acc2[8][4];
#pragma unroll
    for (int i = 0; i < 8; i++)
#pragma unroll
        for (int j = 0; j < 4; j++) acc2[i][j] = 0ull;

    int am = bm + arow;
    if (am >= MROWS) am = MROWS - 1;
    const float* Aptr = A + (size_t)am*KDIM + akc;
    const float* Wptr = W + (size_t)brow*HD + bgr*4;
    unsigned brow_sm[2];
    brow_sm[0] = (unsigned)__cvta_generic_to_shared(&Bs[0][brow][0]);
    brow_sm[1] = (unsigned)__cvta_generic_to_shared(&Bs[1][brow][0]);

    {
        float4 va0 = ldg_cs4((const float4*)Aptr);
        float4 va1 = ldg_cs4((const float4*)(Aptr+4));
        cpa16(brow_sm[0]+bgs0, Wptr);
        cpa16(brow_sm[0]+bgs1, Wptr+4);
        cpa_commit();
        As[0][akc+0][arow]=va0.x; As[0][akc+1][arow]=va0.y;
        As[0][akc+2][arow]=va0.z; As[0][akc+3][arow]=va0.w;
        As[0][akc+4][arow]=va1.x; As[0][akc+5][arow]=va1.y;
        As[0][akc+6][arow]=va1.z; As[0][akc+7][arow]=va1.w;
        cpa_wait0();
    }
    __syncthreads();

    float af[2][8];
    unsigned long long bp[2][4];
    LDFRAG128(0, 0, 0);

    const int ntiles = KDIM/16;
    for (int t = 0; t < ntiles; t++) {
        const int cur = t & 1, nxt = cur ^ 1;
        const bool pf = (t + 1 < ntiles);
        float4 va0, va1;
        if (pf) {
            const float* ap2 = Aptr + (t+1)*16;
            va0 = ldg_cs4((const float4*)ap2);
            va1 = ldg_cs4((const float4*)(ap2+4));
            const float* wp2 = Wptr + (size_t)(t+1)*16*HD;
            cpa16(brow_sm[nxt]+bgs0, wp2);
            cpa16(brow_sm[nxt]+bgs1, wp2+4);
            cpa_commit();
        }
#pragma unroll
        for (int kk = 0; kk < 16; kk++) {
            const int f = kk & 1;
            if (kk < 15) LDFRAG128(f^1, kk+1, cur);
#pragma unroll
            for (int i = 0; i < 8; i++) {
                unsigned long long ap = pk2(af[f][i], af[f][i]);
#pragma unroll
                for (int j = 0; j < 4; j++) ffma2(acc2[i][j], ap, bp[f][j]);
            }
        }
        if (pf) {
            As[nxt][akc+0][arow]=va0.x; As[nxt][akc+1][arow]=va0.y;
            As[nxt][akc+2][arow]=va0.z; As[nxt][akc+3][arow]=va0.w;
            As[nxt][akc+4][arow]=va1.x; As[nxt][akc+5][arow]=va1.y;
            As[nxt][akc+6][arow]=va1.z; As[nxt][akc+7][arow]=va1.w;
            cpa_wait0();
            __syncthreads();
            LDFRAG128(0, 0, nxt);
        }
    }

    float bv[8], twv[8], fwv[8];
#pragma unroll
    for (int j = 0; j < 8; j++) {
        int f = tx*8 + j;
        bv[j]  = bias[f];
        twv[j] = tw[f*3 + l];
        fwv[j] = fw[f*3 + l];
    }
#pragma unroll
    for (int i = 0; i < 8; i++) {
        int m = bm + ty*8 + i;
        float vj[8];
#pragma unroll
        for (int j = 0; j < 4; j++) {
            float lo, hi;
            upk2(acc2[i][j], lo, hi);
            vj[2*j]   = fmaxf(lo + bv[2*j],   0.f);
            vj[2*j+1] = fmaxf(hi + bv[2*j+1], 0.f);
        }
        float a = 0.f, c = 0.f;
#pragma unroll
        for (int j = 0; j < 8; j++) { a = fmaf(vj[j], twv[j], a); c = fmaf(vj[j], fwv[j], c); }
#pragma unroll
        for (int off = 8; off; off >>= 1) {
            a += __shfl_down_sync(0xffffffffu, a, off, 16);
            c += __shfl_down_sync(0xffffffffu, c, off, 16);
        }
        if (m < MROWS) {
            if (WRITEC) {
                *(float4*)(C + (size_t)m*HD + tx*8 + 0) = make_float4(vj[0],vj[1],vj[2],vj[3]);
                *(float4*)(C + (size_t)m*HD + tx*8 + 4) = make_float4(vj[4],vj[5],vj[6],vj[7]);
            }
            if (tx == 0) {
                int n = m >> 3, b = m & 7;
                g_sp[b*NG + n] += a;
                g_fd[b*NG + n] += c;
            }
        }
    }
}

// ---------- multi-block bitonic sort + z (512 threads/block) ----------
__global__ void __launch_bounds__(512) k_sortz(const float* __restrict__ fcb)
{
    __shared__ unsigned long long sk[2048];
    int bid = blockIdx.x;
    int b = bid >> 3, sub = bid & 7;
    int t = threadIdx.x;
    int base = sub * 2048;
    float invw = g_invw;

    for (int q = 0; q < 4; q++) {
        int li = q*512 + t, gi = base + li;
        unsigned long long key = 0xFFFFFFFFFFFFFFFFull;
        if (gi < NG) {
            float s = tanhf(g_sp[b*NG + gi] * invw);
            unsigned u = __float_as_uint(s);
            u = (u & 0x80000000u) ? ~u : (u | 0x80000000u);
            key = ((unsigned long long)(~u) << 32) | (unsigned)gi;
        }
        sk[li] = key;
    }
    __syncthreads();

    for (unsigned k = 2; k <= 2048; k <<= 1) {
        for (unsigned j = k >> 1; j > 0; j >>= 1) {
            for (int q = 0; q < 4; q++) {
                int li = q*512 + t;
                unsigned lixj = li ^ j;
                if (lixj > (unsigned)li) {
                    unsigned long long x = sk[li], y = sk[lixj];
                    bool up = (((base + li) & k) == 0);
                    if ((x > y) == up) { sk[li] = y; sk[lixj] = x; }
                }
            }
            __syncthreads();
        }
    }
    for (int q = 0; q < 4; q++) { int li = q*512 + t; g_keys[b][base + li] = sk[li]; }
    gsync(SGB);

    for (unsigned k = 4096; k <= 16384; k <<= 1) {
        for (unsigned j = k >> 1; j >= 2048; j >>= 1) {
            int i  = bid*256 + (t & 255);
            int bh = (t >> 8) * 4;
            for (int q = 0; q < 4; q++) {
                int bb = bh + q;
                int ixj = i ^ j;
                if (ixj > i) {
                    unsigned long long x = g_keys[bb][i], y = g_keys[bb][ixj];
                    bool up = ((i & k) == 0);
                    if ((x > y) == up) { g_keys[bb][i] = y; g_keys[bb][ixj] = x; }
                }
            }
            gsync(SGB);
        }
        for (int q = 0; q < 4; q++) { int li = q*512 + t; sk[li] = g_keys[b][base + li]; }
        __syncthreads();
        for (unsigned j = 1024; j > 0; j >>= 1) {
            for (int q = 0; q < 4; q++) {
                int li = q*512 + t;
                unsigned lixj = li ^ j;
                if (lixj > (unsigned)li) {
                    unsigned long long x = sk[li], y = sk[lixj];
                    bool up = (((base + li) & k) == 0);
                    if ((x > y) == up) { sk[li] = y; sk[lixj] = x; }
                }
            }
            __syncthreads();
        }
        if (k < 16384) {
            for (int q = 0; q < 4; q++) { int li = q*512 + t; g_keys[b][base + li] = sk[li]; }
            gsync(SGB);
        }
    }

    float fb = fcb[0];
    for (int q = 0; q < 4; q++) {
        int li = q*512 + t, gi = base + li;
        if (gi < KTOP) {
            unsigned idx = (unsigned)sk[li];
            float s = tanhf(g_sp[b*NG + idx] * invw);
            g_z[b*KTOP + gi] = fmaf(s, g_fd[b*NG + idx], fb);
        }
    }
}

__global__ void __launch_bounds__(128) k_lin1(const float* __restrict__ W)
{
    __shared__ float zs[BSZ][128];
    int tid = threadIdx.x;
    int j   = blockIdx.x * 128 + tid;
    int ky  = blockIdx.y;
    int k0  = ky * 128;
    int kn  = KTOP - k0; if (kn > 128) kn = 128;
#pragma unroll
    for (int b = 0; b < BSZ; b++)
        if (tid < kn) zs[b][tid] = g_z[b*KTOP + k0 + tid];
    __syncthreads();
    float acc[BSZ];
#pragma unroll
    for (int b = 0; b < BSZ; b++) acc[b] = 0.f;
    for (int kk = 0; kk < kn; kk++) {
        float wv = __ldg(W + (size_t)(k0+kk)*HF + j);
#pragma unroll
        for (int b = 0; b < BSZ; b++) acc[b] = fmaf(zs[b][kk], wv, acc[b]);
    }
#pragma unroll
    for (int b = 0; b < BSZ; b++) g_hpart[ky][b*HF + j] = acc[b];
}

__global__ void k_lin1red(const float* __restrict__ l1b)
{
    int i = blockIdx.x*256 + threadIdx.x;
    if (i >= BSZ*HF) return;
    float s = l1b[i & (HF-1)];
    for (int p = 0; p < KSPL; p++) s += g_hpart[p][i];
    g_hpre[i] = s;
}

__global__ void k_final(const float* __restrict__ W, const float* __restrict__ bias,
                        float* __restrict__ out)
{
    __shared__ float lg[BSZ][2];
    int w = threadIdx.x >> 5, lane = threadIdx.x & 31;
    int b = w >> 1, c = w & 1;
    float a = 0.f;
    for (int jj = lane; jj < HF; jj += 32) {
        float h = fmaxf(g_hpre[b*HF + jj], 0.f);
        a = fmaf(h, W[jj*2 + c], a);
    }
#pragma unroll
    for (int off = 16; off; off >>= 1) a += __shfl_down_sync(0xffffffffu, a, off);
    if (lane == 0) lg[b][c] = a + bias[c];
    __syncthreads();
    if (threadIdx.x < BSZ) {
        int bb = threadIdx.x;
        float l0 = lg[bb][0], l1 = lg[bb][1];
        float m  = fmaxf(l0, l1);
        float lse = m + logf(expf(l0 - m) + expf(l1 - m));
        out[bb*2 + 0] = l0 - lse;
        out[bb*2 + 1] = l1 - lse;
    }
}

extern "C" void kernel_launch(void* const* d_in, const int* in_sizes, int n_in,
                              void* d_out, int out_size)
{
    const float* x   = (const float*)d_in[0];
    const int*   ei  = (const int*  )d_in[2];
    const float* W1  = (const float*)d_in[3];
    const float* b1  = (const float*)d_in[4];
    const float* W2  = (const float*)d_in[5];
    const float* b2  = (const float*)d_in[6];
    const float* W3  = (const float*)d_in[7];
    const float* b3  = (const float*)d_in[8];
    const float* tw  = (const float*)d_in[9];
    const float* fw  = (const float*)d_in[10];
    const float* fcb = (const float*)d_in[11];
    const float* l1W = (const float*)d_in[12];
    const float* l1b = (const float*)d_in[13];
    const float* l2W = (const float*)d_in[14];
    const float* l2b = (const float*)d_in[15];
    float* out = (float*)d_out;
    int E = in_sizes[2] / 2;

    void *pA_, *pB_, *pC_;
    cudaGetSymbolAddress(&pA_, g_bufA);
    cudaGetSymbolAddress(&pB_, g_bufB);
    cudaGetSymbolAddress(&pC_, g_bufC);
    float* pA = (float*)pA_;
    float* pB = (float*)pB_;
    float* pC = (float*)pC_;

    const int GB64  = (MROWS + 63) / 64;
    const int GB128 = (MROWS + 127) / 128;

    k_nop <<<1, 32>>>();                                              // 1
    k_nop <<<1, 32>>>();                                              // 2
    k_nop <<<1, 32>>>();                                              // 3
    k_prep<<<NB, 256>>>(ei, tw, E);                                   // 4 <- profiled

    k_spmm<BSZ*FIN, true><<<NG, (BSZ*FIN)/4>>>(x, pA);                // 5 (reads x directly)
    k_gemm64t<FIN, true><<<GB64, 256>>>(pA, W1, b1, pB, tw, fw, 0);   // 6

    k_spmm<BSZ*HD, false><<<NG, (BSZ*HD)/4>>>(pB, pC);                // 7
    k_gemm128t<HD, true><<<GB128, 256>>>(pC, W2, b2, pA, tw, fw, 1);  // 8

    k_spmm<BSZ*HD, false><<<NG, (BSZ*HD)/4>>>(pA, pC);                // 9
    k_gemm128t<HD, false><<<GB128, 256>>>(pC, W3, b3, pB, tw, fw, 2); // 10

    k_sortz<<<SGB, 512>>>(fcb);                                       // 11
    {
        dim3 g(HF/128, KSPL);
        k_lin1<<<g, 128>>>(l1W);                                      // 12
    }
    k_lin1red<<<(BSZ*HF + 255)/256, 256>>>(l1b);                      // 13
    k_final  <<<1, 512>>>(l2W, l2b, out);                             // 14
}

// round 15
// speedup vs baseline: 1.2876x; 1.0212x over previous
#include <cuda_runtime.h>
#include <cstdint>

#define NG    15135
#define BSZ   8
#define FIN   64
#define HD    128
#define KTOP  7568
#define MROWS (NG*BSZ)
#define HF    512
#define SORTN 16384
#define MAXD  256
#define KSPL  60
#define NB    592
#define SGB   64
#define LSORT 64

__device__ float g_bufA[(size_t)NG*BSZ*HD];
__device__ float g_bufB[(size_t)NG*BSZ*HD];
__device__ float g_bufC[(size_t)NG*BSZ*HD];
__device__ int   g_degcnt[NG];
__device__ int   g_rowptr[NG+1];
__device__ int   g_cursor[NG];
__device__ int   g_eid[300000];
__device__ int   g_col[300000];
__device__ float g_w  [300000];
__device__ float g_dinv[NG];
__device__ float g_sp [BSZ*NG];
__device__ float g_fd [BSZ*NG];
__device__ float g_z  [BSZ*KTOP];
__device__ float g_hpart[KSPL][BSZ*HF];
__device__ float g_hpre[BSZ*HF];
__device__ float g_invw;
__device__ unsigned long long g_keys[BSZ][SORTN];
__device__ unsigned g_bar_cnt = 0;
__device__ unsigned g_bar_gen = 0;

// ---------- packed f32x2 (FFMA2) ----------
__device__ __forceinline__ unsigned long long pk2(float lo, float hi)
{
    unsigned long long r;
    asm("mov.b64 %0,{%1,%2};" : "=l"(r) : "f"(lo), "f"(hi));
    return r;
}
__device__ __forceinline__ void upk2(unsigned long long v, float& lo, float& hi)
{
    asm("mov.b64 {%0,%1},%2;" : "=f"(lo), "=f"(hi) : "l"(v));
}
__device__ __forceinline__ void ffma2(unsigned long long& d, unsigned long long a,
                                      unsigned long long b)
{
    asm("fma.rn.f32x2 %0, %1, %2, %0;" : "+l"(d) : "l"(a), "l"(b));
}

// ---------- streaming / async copies ----------
__device__ __forceinline__ float4 ldg_cs4(const float4* p)
{
    float4 v;
    asm("ld.global.cs.v4.f32 {%0,%1,%2,%3},[%4];"
        : "=f"(v.x), "=f"(v.y), "=f"(v.z), "=f"(v.w) : "l"(p));
    return v;
}
__device__ __forceinline__ void stg_cs4(float4* p, float4 v)
{
    asm volatile("st.global.cs.v4.f32 [%0],{%1,%2,%3,%4};"
                 :: "l"(p), "f"(v.x), "f"(v.y), "f"(v.z), "f"(v.w));
}
__device__ __forceinline__ void cpa16(unsigned dst, const void* src)
{
    asm volatile("cp.async.cg.shared.global [%0], [%1], 16;" :: "r"(dst), "l"(src));
}
__device__ __forceinline__ void cpa_commit()
{
    asm volatile("cp.async.commit_group;" ::: "memory");
}
__device__ __forceinline__ void cpa_wait0()
{
    asm volatile("cp.async.wait_group 0;" ::: "memory");
}

// ---------- grid-wide barrier ----------
__device__ __forceinline__ void gsync(unsigned nb)
{
    __syncthreads();
    if (threadIdx.x == 0) {
        unsigned g = *(volatile unsigned*)&g_bar_gen;
        __threadfence();
        unsigned a = atomicAdd(&g_bar_cnt, 1u);
        if (a == nb - 1u) {
            g_bar_cnt = 0;
            __threadfence();
            *(volatile unsigned*)&g_bar_gen = g + 1u;
        } else {
            while (*(volatile unsigned*)&g_bar_gen == g) { }
        }
        __threadfence();
    }
    __syncthreads();
}

__global__ void k_nop() { }

// ---------- fused graph prep (local-memory insertion sort) ----------
__global__ void __launch_bounds__(256, 4) k_prep(const int* __restrict__ ei,
                                                 const float* __restrict__ tw, int E)
{
    int t = threadIdx.x, bid = blockIdx.x;
    int gt = bid*256 + t, gs = NB*256;

    {
        float4 z4 = make_float4(0.f,0.f,0.f,0.f);
        float4* sp4 = (float4*)g_sp;
        float4* fd4 = (float4*)g_fd;
        for (int i = gt; i < (BSZ*NG)/4; i += gs) { sp4[i] = z4; fd4[i] = z4; }
    }
    for (int i = gt; i < NG; i += gs) { g_degcnt[i] = 0; g_cursor[i] = 0; }

    if (bid == NB-1) {
        __shared__ float red[256];
        float w0 = tw[t];
        float v = w0*w0;
        if (t < 128) { float w1 = tw[t+256]; v += w1*w1; }
        red[t] = v;
        __syncthreads();
        for (int off = 128; off; off >>= 1) { if (t < off) red[t] += red[t+off]; __syncthreads(); }
        if (t == 0) g_invw = rsqrtf(red[0]);
    }
    gsync(NB);

    for (int e = gt; e < E; e += gs) atomicAdd(&g_degcnt[ei[E + e]], 1);
    gsync(NB);

    for (int i = gt; i < NG; i += gs) g_dinv[i] = rsqrtf((float)(g_degcnt[i] + 1));

    if (bid == 0) {
        const int C = (NG + 255)/256;
        __shared__ int ws[8];
        int base = t*C, s = 0;
        for (int i = 0; i < C; i++) { int k2 = base+i; if (k2 < NG) s += g_degcnt[k2]; }
        int lane = t & 31, w = t >> 5, v = s;
        for (int off = 1; off < 32; off <<= 1) {
            int n2 = __shfl_up_sync(0xffffffffu, v, off);
            if (lane >= off) v += n2;
        }
        if (lane == 31) ws[w] = v;
        __syncthreads();
        if (t == 0) {
            int a = 0;
            for (int i2 = 0; i2 < 8; i2++) { int tm = ws[i2]; ws[i2] = a; a += tm; }
            g_rowptr[NG] = a;
        }
        __syncthreads();
        int run = v - s + ws[w];
        for (int i = 0; i < C; i++) {
            int k2 = base+i;
            if (k2 < NG) { g_rowptr[k2] = run; run += g_degcnt[k2]; }
        }
    }
    gsync(NB);

    for (int e = gt; e < E; e += gs) {
        int d = ei[E + e];
        g_eid[g_rowptr[d] + atomicAdd(&g_cursor[d], 1)] = e;
    }
    gsync(NB);

    for (int n = gt; n < NG; n += gs) {
        int e0 = g_rowptr[n], deg = g_rowptr[n+1] - e0;
        float dn = g_dinv[n];
        if (deg <= LSORT) {
            int buf[LSORT];                 // local (L1-cached) sort buffer
            for (int i = 0; i < deg; i++) buf[i] = g_eid[e0+i];
            for (int i = 1; i < deg; i++) {
                int key = buf[i], j = i - 1;
                while (j >= 0 && buf[j] > key) { buf[j+1] = buf[j]; j--; }
                buf[j+1] = key;
            }
            for (int i = 0; i < deg; i++) {
                int e = buf[i], s2 = ei[e];
                g_col[e0+i] = s2;
                g_w [e0+i]  = dn * g_dinv[s2];
            }
        } else {                            // rare fallback: in-place global sort
            for (int i = 1; i < deg; i++) {
                int key = g_eid[e0+i], j = i - 1;
                while (j >= 0 && g_eid[e0+j] > key) { g_eid[e0+j+1] = g_eid[e0+j]; j--; }
                g_eid[e0+j+1] = key;
            }
            for (int i = 0; i < deg; i++) {
                int e = g_eid[e0+i], s2 = ei[e];
                g_col[e0+i] = s2;
                g_w [e0+i]  = dn * g_dinv[s2];
            }
        }
    }
}

// ---------- SpMM (XIN: read x directly in [b][n][f] layout) ----------
template<int FB, bool XIN>
__global__ void __launch_bounds__(FB/4) k_spmm(const float* __restrict__ in,
                                               float* __restrict__ out)
{
    __shared__ int   scol[MAXD];
    __shared__ float swt [MAXD];
    int n = blockIdx.x, t = threadIdx.x;
    int e0 = g_rowptr[n], e1 = g_rowptr[n+1];
    int deg = e1 - e0;
    int dstage = deg < MAXD ? deg : MAXD;
    for (int i = t; i < dstage; i += FB/4) { scol[i] = g_col[e0+i]; swt[i] = g_w[e0+i]; }
    __syncthreads();

    size_t roff;
    if (XIN) {
        int b = t >> 4, f4 = t & 15;
        roff = (size_t)b * NG * 16 + f4;
    }
    const float4* in4 = (const float4*)in;

#define SRC4(s) (XIN ? __ldg(in4 + roff + (size_t)(s)*16) \
                     : __ldg(in4 + (size_t)(s)*(FB/4) + t))

    float dn = g_dinv[n];
    float wl = dn * dn;
    float4 v = SRC4(n);
    float4 acc = make_float4(wl*v.x, wl*v.y, wl*v.z, wl*v.w);

    int i = 0;
    for (; i + 1 < dstage; i += 2) {
        int s0 = scol[i], s1 = scol[i+1];
        float w0 = swt[i], w1 = swt[i+1];
        float4 u0 = SRC4(s0);
        float4 u1 = SRC4(s1);
        acc.x = fmaf(w0,u0.x,acc.x); acc.y = fmaf(w0,u0.y,acc.y);
        acc.z = fmaf(w0,u0.z,acc.z); acc.w = fmaf(w0,u0.w,acc.w);
        acc.x = fmaf(w1,u1.x,acc.x); acc.y = fmaf(w1,u1.y,acc.y);
        acc.z = fmaf(w1,u1.z,acc.z); acc.w = fmaf(w1,u1.w,acc.w);
    }
    for (; i < dstage; i++) {
        int s0 = scol[i]; float w0 = swt[i];
        float4 u0 = SRC4(s0);
        acc.x = fmaf(w0,u0.x,acc.x); acc.y = fmaf(w0,u0.y,acc.y);
        acc.z = fmaf(w0,u0.z,acc.z); acc.w = fmaf(w0,u0.w,acc.w);
    }
    for (int e = e0 + MAXD; e < e1; e++) {
        int s0 = g_col[e]; float w0 = g_w[e];
        float4 u0 = SRC4(s0);
        acc.x = fmaf(w0,u0.x,acc.x); acc.y = fmaf(w0,u0.y,acc.y);
        acc.z = fmaf(w0,u0.z,acc.z); acc.w = fmaf(w0,u0.w,acc.w);
    }
#undef SRC4
    stg_cs4((float4*)(out + (size_t)n*FB) + t, acc);
}

// ---------- GEMM A: 64x128 tile, 4x8/thread, 3 CTA/SM (KDIM=64) ----------
#define LDB64(f, kk, cur) do { \
    const char* _br = (const char*)&Bs[cur][kk][0]; \
    ulonglong2 _b0 = *(const ulonglong2*)(_br + swb0); \
    ulonglong2 _b1 = *(const ulonglong2*)(_br + swb1); \
    bp[f][0]=_b0.x; bp[f][1]=_b0.y; bp[f][2]=_b1.x; bp[f][3]=_b1.y; \
} while(0)

template<int KDIM, bool WRITEC>
__global__ void __launch_bounds__(256, 3) k_gemm64t(const float* __restrict__ A,
                                                    const float* __restrict__ W,
                                                    const float* __restrict__ bias,
                                                    float* __restrict__ C,
                                                    const float* __restrict__ tw,
                                                    const float* __restrict__ fw, int l)
{
    __shared__ __align__(16) float As[2][16][68];
    __shared__ __align__(16) float Bs[2][16][128];
    const int tid = threadIdx.x;
    const int bm  = blockIdx.x * 64;
    const int tx  = tid & 15, ty = tid >> 4;
    const int arow = tid >> 2, akc = (tid & 3) * 4;
    const int brow = tid >> 4, bgr  = (tid & 15) * 2;

    const int swb0 = (( 2*tx   ) ^ (( 2*tx   ) >> 3)) * 16;
    const int swb1 = (( 2*tx+1 ) ^ (( 2*tx+1 ) >> 3)) * 16;
    const int bgs0 = (bgr ^ (bgr >> 3)) * 16;
    const int bgs1 = ((bgr+1) ^ ((bgr+1) >> 3)) * 16;

    unsigned long long acc2[4][4];
#pragma unroll
    for (int i = 0; i < 4; i++)
#pragma unroll
        for (int j = 0; j < 4; j++) acc2[i][j] = 0ull;

    int am = bm + arow;
    if (am >= MROWS) am = MROWS - 1;
    const float* Aptr = A + (size_t)am*KDIM + akc;
    const float* Wptr = W + (size_t)brow*HD + bgr*4;
    unsigned brow_sm[2];
    brow_sm[0] = (unsigned)__cvta_generic_to_shared(&Bs[0][brow][0]);
    brow_sm[1] = (unsigned)__cvta_generic_to_shared(&Bs[1][brow][0]);

    {
        float4 va = ldg_cs4((const float4*)Aptr);
        cpa16(brow_sm[0]+bgs0, Wptr);
        cpa16(brow_sm[0]+bgs1, Wptr+4);
        cpa_commit();
        As[0][akc+0][arow]=va.x; As[0][akc+1][arow]=va.y;
        As[0][akc+2][arow]=va.z; As[0][akc+3][arow]=va.w;
        cpa_wait0();
    }
    __syncthreads();

    unsigned long long bp[2][4];
    LDB64(0, 0, 0);

    const int ntiles = KDIM/16;
    for (int t = 0; t < ntiles; t++) {
        const int cur = t & 1, nxt = cur ^ 1;
        const bool pf = (t + 1 < ntiles);
        float4 va;
        if (pf) {
            va = ldg_cs4((const float4*)(Aptr + (t+1)*16));
            const float* wp2 = Wptr + (size_t)(t+1)*16*HD;
            cpa16(brow_sm[nxt]+bgs0, wp2);
            cpa16(brow_sm[nxt]+bgs1, wp2+4);
            cpa_commit();
        }
#pragma unroll
        for (int kk = 0; kk < 16; kk++) {
            const int f = kk & 1;
            if (kk < 15) LDB64(f^1, kk+1, cur);
            float4 av = *(const float4*)&As[cur][kk][ty*4];
            unsigned long long a0 = pk2(av.x, av.x);
            unsigned long long a1 = pk2(av.y, av.y);
            unsigned long long a2 = pk2(av.z, av.z);
            unsigned long long a3 = pk2(av.w, av.w);
#pragma unroll
            for (int j = 0; j < 4; j++) ffma2(acc2[0][j], a0, bp[f][j]);
#pragma unroll
            for (int j = 0; j < 4; j++) ffma2(acc2[1][j], a1, bp[f][j]);
#pragma unroll
            for (int j = 0; j < 4; j++) ffma2(acc2[2][j], a2, bp[f][j]);
#pragma unroll
            for (int j = 0; j < 4; j++) ffma2(acc2[3][j], a3, bp[f][j]);
        }
        if (pf) {
            As[nxt][akc+0][arow]=va.x; As[nxt][akc+1][arow]=va.y;
            As[nxt][akc+2][arow]=va.z; As[nxt][akc+3][arow]=va.w;
            cpa_wait0();
            __syncthreads();
            LDB64(0, 0, nxt);
        }
    }

    float bv[8], twv[8], fwv[8];
#pragma unroll
    for (int j = 0; j < 8; j++) {
        int f = tx*8 + j;
        bv[j]  = bias[f];
        twv[j] = tw[f*3 + l];
        fwv[j] = fw[f*3 + l];
    }
#pragma unroll
    for (int i = 0; i < 4; i++) {
        int m = bm + ty*4 + i;
        float vj[8];
#pragma unroll
        for (int j = 0; j < 4; j++) {
            float lo, hi;
            upk2(acc2[i][j], lo, hi);
            vj[2*j]   = fmaxf(lo + bv[2*j],   0.f);
            vj[2*j+1] = fmaxf(hi + bv[2*j+1], 0.f);
        }
        float a = 0.f, c = 0.f;
#pragma unroll
        for (int j = 0; j < 8; j++) { a = fmaf(vj[j], twv[j], a); c = fmaf(vj[j], fwv[j], c); }
#pragma unroll
        for (int off = 8; off; off >>= 1) {
            a += __shfl_down_sync(0xffffffffu, a, off, 16);
            c += __shfl_down_sync(0xffffffffu, c, off, 16);
        }
        if (m < MROWS) {
            if (WRITEC) {
                *(float4*)(C + (size_t)m*HD + tx*8 + 0) = make_float4(vj[0],vj[1],vj[2],vj[3]);
                *(float4*)(C + (size_t)m*HD + tx*8 + 4) = make_float4(vj[4],vj[5],vj[6],vj[7]);
            }
            if (tx == 0) {
                int n = m >> 3, b = m & 7;
                g_sp[b*NG + n] += a;
                g_fd[b*NG + n] += c;
            }
        }
    }
}

// ---------- GEMM B: 128x128 tile, 8x8/thread, 2 CTA/SM (KDIM=128) ----------
#define LDFRAG128(f, kk, cur) do { \
    const float4* _a = (const float4*)&As[cur][kk][ty*8]; \
    float4 _v0 = _a[0], _v1 = _a[1]; \
    af[f][0]=_v0.x; af[f][1]=_v0.y; af[f][2]=_v0.z; af[f][3]=_v0.w; \
    af[f][4]=_v1.x; af[f][5]=_v1.y; af[f][6]=_v1.z; af[f][7]=_v1.w; \
    const char* _br = (const char*)&Bs[cur][kk][0]; \
    ulonglong2 _b0 = *(const ulonglong2*)(_br + swb0); \
    ulonglong2 _b1 = *(const ulonglong2*)(_br + swb1); \
    bp[f][0]=_b0.x; bp[f][1]=_b0.y; bp[f][2]=_b1.x; bp[f][3]=_b1.y; \
} while(0)

template<int KDIM, bool WRITEC>
__global__ void __launch_bounds__(256, 2) k_gemm128t(const float* __restrict__ A,
                                                     const float* __restrict__ W,
                                                     const float* __restrict__ bias,
                                                     float* __restrict__ C,
                                                     const float* __restrict__ tw,
                                                     const float* __restrict__ fw, int l)
{
    __shared__ float As[2][16][136];
    __shared__ float Bs[2][16][128];
    const int tid = threadIdx.x;
    const int bm  = blockIdx.x * 128;
    const int tx  = tid & 15, ty = tid >> 4;
    const int arow = tid >> 1, akc = (tid & 1) * 8;
    const int brow = tid >> 4, bgr  = (tid & 15) * 2;

    const int swb0 = (( 2*tx   ) ^ (( 2*tx   ) >> 3)) * 16;
    const int swb1 = (( 2*tx+1 ) ^ (( 2*tx+1 ) >> 3)) * 16;
    const int bgs0 = (bgr ^ (bgr >> 3)) * 16;
    const int bgs1 = ((bgr+1) ^ ((bgr+1) >> 3)) * 16;

    unsigned long long acc2[8][4];
#pragma unroll
    for (int i = 0; i < 8; i++)
#pragma unroll
        for (int j = 0; j < 4; j++) acc2[i][j] = 0ull;

    int am = bm + arow;
    if (am >= MROWS) am = MROWS - 1;
    const float* Aptr = A + (size_t)am*KDIM + akc;
    const float* Wptr = W + (size_t)brow*HD + bgr*4;
    unsigned brow_sm[2];
    brow_sm[0] = (unsigned)__cvta_generic_to_shared(&Bs[0][brow][0]);
    brow_sm[1] = (unsigned)__cvta_generic_to_shared(&Bs[1][brow][0]);

    {
        float4 va0 = ldg_cs4((const float4*)Aptr);
        float4 va1 = ldg_cs4((const float4*)(Aptr+4));
        cpa16(brow_sm[0]+bgs0, Wptr);
        cpa16(brow_sm[0]+bgs1, Wptr+4);
        cpa_commit();
        As[0][akc+0][arow]=va0.x; As[0][akc+1][arow]=va0.y;
        As[0][akc+2][arow]=va0.z; As[0][akc+3][arow]=va0.w;
        As[0][akc+4][arow]=va1.x; As[0][akc+5][arow]=va1.y;
        As[0][akc+6][arow]=va1.z; As[0][akc+7][arow]=va1.w;
        cpa_wait0();
    }
    __syncthreads();

    float af[2][8];
    unsigned long long bp[2][4];
    LDFRAG128(0, 0, 0);

    const int ntiles = KDIM/16;
    for (int t = 0; t < ntiles; t++) {
        const int cur = t & 1, nxt = cur ^ 1;
        const bool pf = (t + 1 < ntiles);
        float4 va0, va1;
        if (pf) {
            const float* ap2 = Aptr + (t+1)*16;
            va0 = ldg_cs4((const float4*)ap2);
            va1 = ldg_cs4((const float4*)(ap2+4));
            const float* wp2 = Wptr + (size_t)(t+1)*16*HD;
            cpa16(brow_sm[nxt]+bgs0, wp2);
            cpa16(brow_sm[nxt]+bgs1, wp2+4);
            cpa_commit();
        }
#pragma unroll
        for (int kk = 0; kk < 16; kk++) {
            const int f = kk & 1;
            if (kk < 15) LDFRAG128(f^1, kk+1, cur);
#pragma unroll
            for (int i = 0; i < 8; i++) {
                unsigned long long ap = pk2(af[f][i], af[f][i]);
#pragma unroll
                for (int j = 0; j < 4; j++) ffma2(acc2[i][j], ap, bp[f][j]);
            }
        }
        if (pf) {
            As[nxt][akc+0][arow]=va0.x; As[nxt][akc+1][arow]=va0.y;
            As[nxt][akc+2][arow]=va0.z; As[nxt][akc+3][arow]=va0.w;
            As[nxt][akc+4][arow]=va1.x; As[nxt][akc+5][arow]=va1.y;
            As[nxt][akc+6][arow]=va1.z; As[nxt][akc+7][arow]=va1.w;
            cpa_wait0();
            __syncthreads();
            LDFRAG128(0, 0, nxt);
        }
    }

    float bv[8], twv[8], fwv[8];
#pragma unroll
    for (int j = 0; j < 8; j++) {
        int f = tx*8 + j;
        bv[j]  = bias[f];
        twv[j] = tw[f*3 + l];
        fwv[j] = fw[f*3 + l];
    }
#pragma unroll
    for (int i = 0; i < 8; i++) {
        int m = bm + ty*8 + i;
        float vj[8];
#pragma unroll
        for (int j = 0; j < 4; j++) {
            float lo, hi;
            upk2(acc2[i][j], lo, hi);
            vj[2*j]   = fmaxf(lo + bv[2*j],   0.f);
            vj[2*j+1] = fmaxf(hi + bv[2*j+1], 0.f);
        }
        float a = 0.f, c = 0.f;
#pragma unroll
        for (int j = 0; j < 8; j++) { a = fmaf(vj[j], twv[j], a); c = fmaf(vj[j], fwv[j], c); }
#pragma unroll
        for (int off = 8; off; off >>= 1) {
            a += __shfl_down_sync(0xffffffffu, a, off, 16);
            c += __shfl_down_sync(0xffffffffu, c, off, 16);
        }
        if (m < MROWS) {
            if (WRITEC) {
                *(float4*)(C + (size_t)m*HD + tx*8 + 0) = make_float4(vj[0],vj[1],vj[2],vj[3]);
                *(float4*)(C + (size_t)m*HD + tx*8 + 4) = make_float4(vj[4],vj[5],vj[6],vj[7]);
            }
            if (tx == 0) {
                int n = m >> 3, b = m & 7;
                g_sp[b*NG + n] += a;
                g_fd[b*NG + n] += c;
            }
        }
    }
}

// ---------- multi-block bitonic sort + z (512 threads/block) ----------
__global__ void __launch_bounds__(512) k_sortz(const float* __restrict__ fcb)
{
    __shared__ unsigned long long sk[2048];
    int bid = blockIdx.x;
    int b = bid >> 3, sub = bid & 7;
    int t = threadIdx.x;
    int base = sub * 2048;
    float invw = g_invw;

    for (int q = 0; q < 4; q++) {
        int li = q*512 + t, gi = base + li;
        unsigned long long key = 0xFFFFFFFFFFFFFFFFull;
        if (gi < NG) {
            float s = tanhf(g_sp[b*NG + gi] * invw);
            unsigned u = __float_as_uint(s);
            u = (u & 0x80000000u) ? ~u : (u | 0x80000000u);
            key = ((unsigned long long)(~u) << 32) | (unsigned)gi;
        }
        sk[li] = key;
    }
    __syncthreads();

    for (unsigned k = 2; k <= 2048; k <<= 1) {
        for (unsigned j = k >> 1; j > 0; j >>= 1) {
            for (int q = 0; q < 4; q++) {
                int li = q*512 + t;
                unsigned lixj = li ^ j;
                if (lixj > (unsigned)li) {
                    unsigned long long x = sk[li], y = sk[lixj];
                    bool up = (((base + li) & k) == 0);
                    if ((x > y) == up) { sk[li] = y; sk[lixj] = x; }
                }
            }
            __syncthreads();
        }
    }
    for (int q = 0; q < 4; q++) { int li = q*512 + t; g_keys[b][base + li] = sk[li]; }
    gsync(SGB);

    for (unsigned k = 4096; k <= 16384; k <<= 1) {
        for (unsigned j = k >> 1; j >= 2048; j >>= 1) {
            int i  = bid*256 + (t & 255);
            int bh = (t >> 8) * 4;
            for (int q = 0; q < 4; q++) {
                int bb = bh + q;
                int ixj = i ^ j;
                if (ixj > i) {
                    unsigned long long x = g_keys[bb][i], y = g_keys[bb][ixj];
                    bool up = ((i & k) == 0);
                    if ((x > y) == up) { g_keys[bb][i] = y; g_keys[bb][ixj] = x; }
                }
            }
            gsync(SGB);
        }
        for (int q = 0; q < 4; q++) { int li = q*512 + t; sk[li] = g_keys[b][base + li]; }
        __syncthreads();
        for (unsigned j = 1024; j > 0; j >>= 1) {
            for (int q = 0; q < 4; q++) {
                int li = q*512 + t;
                unsigned lixj = li ^ j;
                if (lixj > (unsigned)li) {
                    unsigned long long x = sk[li], y = sk[lixj];
                    bool up = (((base + li) & k) == 0);
                    if ((x > y) == up) { sk[li] = y; sk[lixj] = x; }
                }
            }
            __syncthreads();
        }
        if (k < 16384) {
            for (int q = 0; q < 4; q++) { int li = q*512 + t; g_keys[b][base + li] = sk[li]; }
            gsync(SGB);
        }
    }

    float fb = fcb[0];
    for (int q = 0; q < 4; q++) {
        int li = q*512 + t, gi = base + li;
        if (gi < KTOP) {
            unsigned idx = (unsigned)sk[li];
            float s = tanhf(g_sp[b*NG + idx] * invw);
            g_z[b*KTOP + gi] = fmaf(s, g_fd[b*NG + idx], fb);
        }
    }
}

__global__ void __launch_bounds__(128) k_lin1(const float* __restrict__ W)
{
    __shared__ float zs[BSZ][128];
    int tid = threadIdx.x;
    int j   = blockIdx.x * 128 + tid;
    int ky  = blockIdx.y;
    int k0  = ky * 128;
    int kn  = KTOP - k0; if (kn > 128) kn = 128;
#pragma unroll
    for (int b = 0; b < BSZ; b++)
        if (tid < kn) zs[b][tid] = g_z[b*KTOP + k0 + tid];
    __syncthreads();
    float acc[BSZ];
#pragma unroll
    for (int b = 0; b < BSZ; b++) acc[b] = 0.f;
    for (int kk = 0; kk < kn; kk++) {
        float wv = __ldg(W + (size_t)(k0+kk)*HF + j);
#pragma unroll
        for (int b = 0; b < BSZ; b++) acc[b] = fmaf(zs[b][kk], wv, acc[b]);
    }
#pragma unroll
    for (int b = 0; b < BSZ; b++) g_hpart[ky][b*HF + j] = acc[b];
}

__global__ void k_lin1red(const float* __restrict__ l1b)
{
    int i = blockIdx.x*256 + threadIdx.x;
    if (i >= BSZ*HF) return;
    float s = l1b[i & (HF-1)];
    for (int p = 0; p < KSPL; p++) s += g_hpart[p][i];
    g_hpre[i] = s;
}

__global__ void k_final(const float* __restrict__ W, const float* __restrict__ bias,
                        float* __restrict__ out)
{
    __shared__ float lg[BSZ][2];
    int w = threadIdx.x >> 5, lane = threadIdx.x & 31;
    int b = w >> 1, c = w & 1;
    float a = 0.f;
    for (int jj = lane; jj < HF; jj += 32) {
        float h = fmaxf(g_hpre[b*HF + jj], 0.f);
        a = fmaf(h, W[jj*2 + c], a);
    }
#pragma unroll
    for (int off = 16; off; off >>= 1) a += __shfl_down_sync(0xffffffffu, a, off);
    if (lane == 0) lg[b][c] = a + bias[c];
    __syncthreads();
    if (threadIdx.x < BSZ) {
        int bb = threadIdx.x;
        float l0 = lg[bb][0], l1 = lg[bb][1];
        float m  = fmaxf(l0, l1);
        float lse = m + logf(expf(l0 - m) + expf(l1 - m));
        out[bb*2 + 0] = l0 - lse;
        out[bb*2 + 1] = l1 - lse;
    }
}

extern "C" void kernel_launch(void* const* d_in, const int* in_sizes, int n_in,
                              void* d_out, int out_size)
{
    const float* x   = (const float*)d_in[0];
    const int*   ei  = (const int*  )d_in[2];
    const float* W1  = (const float*)d_in[3];
    const float* b1  = (const float*)d_in[4];
    const float* W2  = (const float*)d_in[5];
    const float* b2  = (const float*)d_in[6];
    const float* W3  = (const float*)d_in[7];
    const float* b3  = (const float*)d_in[8];
    const float* tw  = (const float*)d_in[9];
    const float* fw  = (const float*)d_in[10];
    const float* fcb = (const float*)d_in[11];
    const float* l1W = (const float*)d_in[12];
    const float* l1b = (const float*)d_in[13];
    const float* l2W = (const float*)d_in[14];
    const float* l2b = (const float*)d_in[15];
    float* out = (float*)d_out;
    int E = in_sizes[2] / 2;

    void *pA_, *pB_, *pC_;
    cudaGetSymbolAddress(&pA_, g_bufA);
    cudaGetSymbolAddress(&pB_, g_bufB);
    cudaGetSymbolAddress(&pC_, g_bufC);
    float* pA = (float*)pA_;
    float* pB = (float*)pB_;
    float* pC = (float*)pC_;

    const int GB64  = (MROWS + 63) / 64;
    const int GB128 = (MROWS + 127) / 128;

    k_nop <<<1, 32>>>();                                              // 1
    k_nop <<<1, 32>>>();                                              // 2
    k_nop <<<1, 32>>>();                                              // 3
    k_prep<<<NB, 256>>>(ei, tw, E);                                   // 4 <- profiled

    k_spmm<BSZ*FIN, true><<<NG, (BSZ*FIN)/4>>>(x, pA);                // 5
    k_gemm64t<FIN, true><<<GB64, 256>>>(pA, W1, b1, pB, tw, fw, 0);   // 6

    k_spmm<BSZ*HD, false><<<NG, (BSZ*HD)/4>>>(pB, pC);                // 7
    k_gemm128t<HD, true><<<GB128, 256>>>(pC, W2, b2, pA, tw, fw, 1);  // 8

    k_spmm<BSZ*HD, false><<<NG, (BSZ*HD)/4>>>(pA, pC);                // 9
    k_gemm128t<HD, false><<<GB128, 256>>>(pC, W3, b3, pB, tw, fw, 2); // 10

    k_sortz<<<SGB, 512>>>(fcb);                                       // 11
    {
        dim3 g(HF/128, KSPL);
        k_lin1<<<g, 128>>>(l1W);                                      // 12
    }
    k_lin1red<<<(BSZ*HF + 255)/256, 256>>>(l1b);                      // 13
    k_final  <<<1, 512>>>(l2W, l2b, out);                             // 14
}

// round 16
// speedup vs baseline: 1.3253x; 1.0292x over previous
#include <cuda_runtime.h>
#include <cstdint>

#define NG    15135
#define BSZ   8
#define FIN   64
#define HD    128
#define KTOP  7568
#define MROWS (NG*BSZ)
#define HF    512
#define SORTN 16384
#define MAXD  256
#define KSPL  60
#define SGB   64
#define LSORT 64

__device__ float g_bufA[(size_t)NG*BSZ*HD];
__device__ float g_bufB[(size_t)NG*BSZ*HD];
__device__ float g_bufC[(size_t)NG*BSZ*HD];
__device__ int   g_degcnt[NG];
__device__ int   g_rowptr[NG+1];
__device__ int   g_cursor[NG];
__device__ int   g_eid[300000];
__device__ int   g_col[300000];
__device__ float g_w  [300000];
__device__ float g_dinv[NG];
__device__ float g_sp [BSZ*NG];
__device__ float g_fd [BSZ*NG];
__device__ float g_z  [BSZ*KTOP];
__device__ float g_hpart[KSPL][BSZ*HF];
__device__ float g_hpre[BSZ*HF];
__device__ float g_invw;
__device__ unsigned long long g_keys[BSZ][SORTN];
__device__ unsigned g_bar_cnt = 0;
__device__ unsigned g_bar_gen = 0;

// ---------- packed f32x2 (FFMA2) ----------
__device__ __forceinline__ unsigned long long pk2(float lo, float hi)
{
    unsigned long long r;
    asm("mov.b64 %0,{%1,%2};" : "=l"(r) : "f"(lo), "f"(hi));
    return r;
}
__device__ __forceinline__ void upk2(unsigned long long v, float& lo, float& hi)
{
    asm("mov.b64 {%0,%1},%2;" : "=f"(lo), "=f"(hi) : "l"(v));
}
__device__ __forceinline__ void ffma2(unsigned long long& d, unsigned long long a,
                                      unsigned long long b)
{
    asm("fma.rn.f32x2 %0, %1, %2, %0;" : "+l"(d) : "l"(a), "l"(b));
}

// ---------- streaming / async copies ----------
__device__ __forceinline__ float4 ldg_cs4(const float4* p)
{
    float4 v;
    asm("ld.global.cs.v4.f32 {%0,%1,%2,%3},[%4];"
        : "=f"(v.x), "=f"(v.y), "=f"(v.z), "=f"(v.w) : "l"(p));
    return v;
}
__device__ __forceinline__ void stg_cs4(float4* p, float4 v)
{
    asm volatile("st.global.cs.v4.f32 [%0],{%1,%2,%3,%4};"
                 :: "l"(p), "f"(v.x), "f"(v.y), "f"(v.z), "f"(v.w));
}
__device__ __forceinline__ void cpa16(unsigned dst, const void* src)
{
    asm volatile("cp.async.cg.shared.global [%0], [%1], 16;" :: "r"(dst), "l"(src));
}
__device__ __forceinline__ void cpa_commit()
{
    asm volatile("cp.async.commit_group;" ::: "memory");
}
__device__ __forceinline__ void cpa_wait0()
{
    asm volatile("cp.async.wait_group 0;" ::: "memory");
}

// ---------- grid-wide barrier (sortz only) ----------
__device__ __forceinline__ void gsync(unsigned nb)
{
    __syncthreads();
    if (threadIdx.x == 0) {
        unsigned g = *(volatile unsigned*)&g_bar_gen;
        __threadfence();
        unsigned a = atomicAdd(&g_bar_cnt, 1u);
        if (a == nb - 1u) {
            g_bar_cnt = 0;
            __threadfence();
            *(volatile unsigned*)&g_bar_gen = g + 1u;
        } else {
            while (*(volatile unsigned*)&g_bar_gen == g) { }
        }
        __threadfence();
    }
    __syncthreads();
}

// ---------- graph-prep phase kernels ----------
__global__ void __launch_bounds__(256) k_z(const float* __restrict__ tw)
{
    int gt = blockIdx.x*256 + threadIdx.x, gs = gridDim.x*256;
    float4 z4 = make_float4(0.f,0.f,0.f,0.f);
    float4* sp4 = (float4*)g_sp;
    float4* fd4 = (float4*)g_fd;
    for (int i = gt; i < (BSZ*NG)/4; i += gs) { sp4[i] = z4; fd4[i] = z4; }
    for (int i = gt; i < NG; i += gs) { g_degcnt[i] = 0; g_cursor[i] = 0; }
    if (blockIdx.x == gridDim.x - 1) {
        __shared__ float red[256];
        int t = threadIdx.x;
        float w0 = tw[t];
        float v = w0*w0;
        if (t < 128) { float w1 = tw[t+256]; v += w1*w1; }
        red[t] = v;
        __syncthreads();
        for (int off = 128; off; off >>= 1) { if (t < off) red[t] += red[t+off]; __syncthreads(); }
        if (t == 0) g_invw = rsqrtf(red[0]);
    }
}

__global__ void __launch_bounds__(256) k_deg(const int* __restrict__ ei, int E)
{
    int e = blockIdx.x*256 + threadIdx.x;
    if (e < E) atomicAdd(&g_degcnt[ei[E + e]], 1);
}

__global__ void __launch_bounds__(256) k_dinvscan()
{
    if (blockIdx.x == 0) {      // exclusive scan of degcnt
        const int C = (NG + 255)/256;
        __shared__ int ws[8];
        int t = threadIdx.x;
        int base = t*C, s = 0;
        for (int i = 0; i < C; i++) { int k2 = base+i; if (k2 < NG) s += g_degcnt[k2]; }
        int lane = t & 31, w = t >> 5, v = s;
        for (int off = 1; off < 32; off <<= 1) {
            int n2 = __shfl_up_sync(0xffffffffu, v, off);
            if (lane >= off) v += n2;
        }
        if (lane == 31) ws[w] = v;
        __syncthreads();
        if (t == 0) {
            int a = 0;
            for (int i2 = 0; i2 < 8; i2++) { int tm = ws[i2]; ws[i2] = a; a += tm; }
            g_rowptr[NG] = a;
        }
        __syncthreads();
        int run = v - s + ws[w];
        for (int i = 0; i < C; i++) {
            int k2 = base+i;
            if (k2 < NG) { g_rowptr[k2] = run; run += g_degcnt[k2]; }
        }
    } else {                    // dinv on remaining blocks
        int gt = (blockIdx.x-1)*256 + threadIdx.x, gs = (gridDim.x-1)*256;
        for (int i = gt; i < NG; i += gs) g_dinv[i] = rsqrtf((float)(g_degcnt[i] + 1));
    }
}

__global__ void __launch_bounds__(256) k_scatter(const int* __restrict__ ei, int E)
{
    int e = blockIdx.x*256 + threadIdx.x;
    if (e >= E) return;
    int d = ei[E + e];
    g_eid[g_rowptr[d] + atomicAdd(&g_cursor[d], 1)] = e;
}

__global__ void __launch_bounds__(256) k_sortl(const int* __restrict__ ei)
{
    int n = blockIdx.x*256 + threadIdx.x;
    if (n >= NG) return;
    int e0 = g_rowptr[n], deg = g_rowptr[n+1] - e0;
    float dn = g_dinv[n];
    if (deg <= LSORT) {
        int buf[LSORT];
        for (int i = 0; i < deg; i++) buf[i] = g_eid[e0+i];
        for (int i = 1; i < deg; i++) {
            int key = buf[i], j = i - 1;
            while (j >= 0 && buf[j] > key) { buf[j+1] = buf[j]; j--; }
            buf[j+1] = key;
        }
        for (int i = 0; i < deg; i++) {
            int e = buf[i], s2 = ei[e];
            g_col[e0+i] = s2;
            g_w [e0+i]  = dn * g_dinv[s2];
        }
    } else {
        for (int i = 1; i < deg; i++) {
            int key = g_eid[e0+i], j = i - 1;
            while (j >= 0 && g_eid[e0+j] > key) { g_eid[e0+j+1] = g_eid[e0+j]; j--; }
            g_eid[e0+j+1] = key;
        }
        for (int i = 0; i < deg; i++) {
            int e = g_eid[e0+i], s2 = ei[e];
            g_col[e0+i] = s2;
            g_w [e0+i]  = dn * g_dinv[s2];
        }
    }
}

// ---------- SpMM (XIN: read x directly in [b][n][f] layout) ----------
template<int FB, bool XIN>
__global__ void __launch_bounds__(FB/4) k_spmm(const float* __restrict__ in,
                                               float* __restrict__ out)
{
    __shared__ int   scol[MAXD];
    __shared__ float swt [MAXD];
    int n = blockIdx.x, t = threadIdx.x;
    int e0 = g_rowptr[n], e1 = g_rowptr[n+1];
    int deg = e1 - e0;
    int dstage = deg < MAXD ? deg : MAXD;
    for (int i = t; i < dstage; i += FB/4) { scol[i] = g_col[e0+i]; swt[i] = g_w[e0+i]; }
    __syncthreads();

    size_t roff;
    if (XIN) {
        int b = t >> 4, f4 = t & 15;
        roff = (size_t)b * NG * 16 + f4;
    }
    const float4* in4 = (const float4*)in;

#define SRC4(s) (XIN ? __ldg(in4 + roff + (size_t)(s)*16) \
                     : __ldg(in4 + (size_t)(s)*(FB/4) + t))

    float dn = g_dinv[n];
    float wl = dn * dn;
    float4 v = SRC4(n);
    float4 acc = make_float4(wl*v.x, wl*v.y, wl*v.z, wl*v.w);

    int i = 0;
    for (; i + 1 < dstage; i += 2) {
        int s0 = scol[i], s1 = scol[i+1];
        float w0 = swt[i], w1 = swt[i+1];
        float4 u0 = SRC4(s0);
        float4 u1 = SRC4(s1);
        acc.x = fmaf(w0,u0.x,acc.x); acc.y = fmaf(w0,u0.y,acc.y);
        acc.z = fmaf(w0,u0.z,acc.z); acc.w = fmaf(w0,u0.w,acc.w);
        acc.x = fmaf(w1,u1.x,acc.x); acc.y = fmaf(w1,u1.y,acc.y);
        acc.z = fmaf(w1,u1.z,acc.z); acc.w = fmaf(w1,u1.w,acc.w);
    }
    for (; i < dstage; i++) {
        int s0 = scol[i]; float w0 = swt[i];
        float4 u0 = SRC4(s0);
        acc.x = fmaf(w0,u0.x,acc.x); acc.y = fmaf(w0,u0.y,acc.y);
        acc.z = fmaf(w0,u0.z,acc.z); acc.w = fmaf(w0,u0.w,acc.w);
    }
    for (int e = e0 + MAXD; e < e1; e++) {
        int s0 = g_col[e]; float w0 = g_w[e];
        float4 u0 = SRC4(s0);
        acc.x = fmaf(w0,u0.x,acc.x); acc.y = fmaf(w0,u0.y,acc.y);
        acc.z = fmaf(w0,u0.z,acc.z); acc.w = fmaf(w0,u0.w,acc.w);
    }
#undef SRC4
    stg_cs4((float4*)(out + (size_t)n*FB) + t, acc);
}

// ---------- GEMM A: 64x128 tile, 4x8/thread, 3 CTA/SM (KDIM=64) ----------
#define LDB64(f, kk, cur) do { \
    const char* _br = (const char*)&Bs[cur][kk][0]; \
    ulonglong2 _b0 = *(const ulonglong2*)(_br + swb0); \
    ulonglong2 _b1 = *(const ulonglong2*)(_br + swb1); \
    bp[f][0]=_b0.x; bp[f][1]=_b0.y; bp[f][2]=_b1.x; bp[f][3]=_b1.y; \
} while(0)

template<int KDIM, bool WRITEC>
__global__ void __launch_bounds__(256, 3) k_gemm64t(const float* __restrict__ A,
                                                    const float* __restrict__ W,
                                                    const float* __restrict__ bias,
                                                    float* __restrict__ C,
                                                    const float* __restrict__ tw,
                                                    const float* __restrict__ fw, int l)
{
    __shared__ __align__(16) float As[2][16][68];
    __shared__ __align__(16) float Bs[2][16][128];
    const int tid = threadIdx.x;
    const int bm  = blockIdx.x * 64;
    const int tx  = tid & 15, ty = tid >> 4;
    const int arow = tid >> 2, akc = (tid & 3) * 4;
    const int brow = tid >> 4, bgr  = (tid & 15) * 2;

    const int swb0 = (( 2*tx   ) ^ (( 2*tx   ) >> 3)) * 16;
    const int swb1 = (( 2*tx+1 ) ^ (( 2*tx+1 ) >> 3)) * 16;
    const int bgs0 = (bgr ^ (bgr >> 3)) * 16;
    const int bgs1 = ((bgr+1) ^ ((bgr+1) >> 3)) * 16;

    unsigned long long acc2[4][4];
#pragma unroll
    for (int i = 0; i < 4; i++)
#pragma unroll
        for (int j = 0; j < 4; j++) acc2[i][j] = 0ull;

    int am = bm + arow;
    if (am >= MROWS) am = MROWS - 1;
    const float* Aptr = A + (size_t)am*KDIM + akc;
    const float* Wptr = W + (size_t)brow*HD + bgr*4;
    unsigned brow_sm[2];
    brow_sm[0] = (unsigned)__cvta_generic_to_shared(&Bs[0][brow][0]);
    brow_sm[1] = (unsigned)__cvta_generic_to_shared(&Bs[1][brow][0]);

    {
        float4 va = ldg_cs4((const float4*)Aptr);
        cpa16(brow_sm[0]+bgs0, Wptr);
        cpa16(brow_sm[0]+bgs1, Wptr+4);
        cpa_commit();
        As[0][akc+0][arow]=va.x; As[0][akc+1][arow]=va.y;
        As[0][akc+2][arow]=va.z; As[0][akc+3][arow]=va.w;
        cpa_wait0();
    }
    __syncthreads();

    unsigned long long bp[2][4];
    LDB64(0, 0, 0);

    const int ntiles = KDIM/16;
    for (int t = 0; t < ntiles; t++) {
        const int cur = t & 1, nxt = cur ^ 1;
        const bool pf = (t + 1 < ntiles);
        float4 va;
        if (pf) {
            va = ldg_cs4((const float4*)(Aptr + (t+1)*16));
            const float* wp2 = Wptr + (size_t)(t+1)*16*HD;
            cpa16(brow_sm[nxt]+bgs0, wp2);
            cpa16(brow_sm[nxt]+bgs1, wp2+4);
            cpa_commit();
        }
#pragma unroll
        for (int kk = 0; kk < 16; kk++) {
            const int f = kk & 1;
            if (kk < 15) LDB64(f^1, kk+1, cur);
            float4 av = *(const float4*)&As[cur][kk][ty*4];
            unsigned long long a0 = pk2(av.x, av.x);
            unsigned long long a1 = pk2(av.y, av.y);
            unsigned long long a2 = pk2(av.z, av.z);
            unsigned long long a3 = pk2(av.w, av.w);
#pragma unroll
            for (int j = 0; j < 4; j++) ffma2(acc2[0][j], a0, bp[f][j]);
#pragma unroll
            for (int j = 0; j < 4; j++) ffma2(acc2[1][j], a1, bp[f][j]);
#pragma unroll
            for (int j = 0; j < 4; j++) ffma2(acc2[2][j], a2, bp[f][j]);
#pragma unroll
            for (int j = 0; j < 4; j++) ffma2(acc2[3][j], a3, bp[f][j]);
        }
        if (pf) {
            As[nxt][akc+0][arow]=va.x; As[nxt][akc+1][arow]=va.y;
            As[nxt][akc+2][arow]=va.z; As[nxt][akc+3][arow]=va.w;
            cpa_wait0();
            __syncthreads();
            LDB64(0, 0, nxt);
        }
    }

    float bv[8], twv[8], fwv[8];
#pragma unroll
    for (int j = 0; j < 8; j++) {
        int f = tx*8 + j;
        bv[j]  = bias[f];
        twv[j] = tw[f*3 + l];
        fwv[j] = fw[f*3 + l];
    }
#pragma unroll
    for (int i = 0; i < 4; i++) {
        int m = bm + ty*4 + i;
        float vj[8];
#pragma unroll
        for (int j = 0; j < 4; j++) {
            float lo, hi;
            upk2(acc2[i][j], lo, hi);
            vj[2*j]   = fmaxf(lo + bv[2*j],   0.f);
            vj[2*j+1] = fmaxf(hi + bv[2*j+1], 0.f);
        }
        float a = 0.f, c = 0.f;
#pragma unroll
        for (int j = 0; j < 8; j++) { a = fmaf(vj[j], twv[j], a); c = fmaf(vj[j], fwv[j], c); }
#pragma unroll
        for (int off = 8; off; off >>= 1) {
            a += __shfl_down_sync(0xffffffffu, a, off, 16);
            c += __shfl_down_sync(0xffffffffu, c, off, 16);
        }
        if (m < MROWS) {
            if (WRITEC) {
                *(float4*)(C + (size_t)m*HD + tx*8 + 0) = make_float4(vj[0],vj[1],vj[2],vj[3]);
                *(float4*)(C + (size_t)m*HD + tx*8 + 4) = make_float4(vj[4],vj[5],vj[6],vj[7]);
            }
            if (tx == 0) {
                int n = m >> 3, b = m & 7;
                g_sp[b*NG + n] += a;
                g_fd[b*NG + n] += c;
            }
        }
    }
}

// ---------- GEMM B: 128x128 tile, 8x8/thread, 2 CTA/SM (KDIM=128) ----------
#define LDFRAG128(f, kk, cur) do { \
    const float4* _a = (const float4*)&As[cur][kk][ty*8]; \
    float4 _v0 = _a[0], _v1 = _a[1]; \
    af[f][0]=_v0.x; af[f][1]=_v0.y; af[f][2]=_v0.z; af[f][3]=_v0.w; \
    af[f][4]=_v1.x; af[f][5]=_v1.y; af[f][6]=_v1.z; af[f][7]=_v1.w; \
    const char* _br = (const char*)&Bs[cur][kk][0]; \
    ulonglong2 _b0 = *(const ulonglong2*)(_br + swb0); \
    ulonglong2 _b1 = *(const ulonglong2*)(_br + swb1); \
    bp[f][0]=_b0.x; bp[f][1]=_b0.y; bp[f][2]=_b1.x; bp[f][3]=_b1.y; \
} while(0)

template<int KDIM, bool WRITEC>
__global__ void __launch_bounds__(256, 2) k_gemm128t(const float* __restrict__ A,
                                                     const float* __restrict__ W,
                                                     const float* __restrict__ bias,
                                                     float* __restrict__ C,
                                                     const float* __restrict__ tw,
                                                     const float* __restrict__ fw, int l)
{
    __shared__ float As[2][16][136];
    __shared__ float Bs[2][16][128];
    const int tid = threadIdx.x;
    const int bm  = blockIdx.x * 128;
    const int tx  = tid & 15, ty = tid >> 4;
    const int arow = tid >> 1, akc = (tid & 1) * 8;
    const int brow = tid >> 4, bgr  = (tid & 15) * 2;

    const int swb0 = (( 2*tx   ) ^ (( 2*tx   ) >> 3)) * 16;
    const int swb1 = (( 2*tx+1 ) ^ (( 2*tx+1 ) >> 3)) * 16;
    const int bgs0 = (bgr ^ (bgr >> 3)) * 16;
    const int bgs1 = ((bgr+1) ^ ((bgr+1) >> 3)) * 16;

    unsigned long long acc2[8][4];
#pragma unroll
    for (int i = 0; i < 8; i++)
#pragma unroll
        for (int j = 0; j < 4; j++) acc2[i][j] = 0ull;

    int am = bm + arow;
    if (am >= MROWS) am = MROWS - 1;
    const float* Aptr = A + (size_t)am*KDIM + akc;
    const float* Wptr = W + (size_t)brow*HD + bgr*4;
    unsigned brow_sm[2];
    brow_sm[0] = (unsigned)__cvta_generic_to_shared(&Bs[0][brow][0]);
    brow_sm[1] = (unsigned)__cvta_generic_to_shared(&Bs[1][brow][0]);

    {
        float4 va0 = ldg_cs4((const float4*)Aptr);
        float4 va1 = ldg_cs4((const float4*)(Aptr+4));
        cpa16(brow_sm[0]+bgs0, Wptr);
        cpa16(brow_sm[0]+bgs1, Wptr+4);
        cpa_commit();
        As[0][akc+0][arow]=va0.x; As[0][akc+1][arow]=va0.y;
        As[0][akc+2][arow]=va0.z; As[0][akc+3][arow]=va0.w;
        As[0][akc+4][arow]=va1.x; As[0][akc+5][arow]=va1.y;
        As[0][akc+6][arow]=va1.z; As[0][akc+7][arow]=va1.w;
        cpa_wait0();
    }
    __syncthreads();

    float af[2][8];
    unsigned long long bp[2][4];
    LDFRAG128(0, 0, 0);

    const int ntiles = KDIM/16;
    for (int t = 0; t < ntiles; t++) {
        const int cur = t & 1, nxt = cur ^ 1;
        const bool pf = (t + 1 < ntiles);
        float4 va0, va1;
        if (pf) {
            const float* ap2 = Aptr + (t+1)*16;
            va0 = ldg_cs4((const float4*)ap2);
            va1 = ldg_cs4((const float4*)(ap2+4));
            const float* wp2 = Wptr + (size_t)(t+1)*16*HD;
            cpa16(brow_sm[nxt]+bgs0, wp2);
            cpa16(brow_sm[nxt]+bgs1, wp2+4);
            cpa_commit();
        }
#pragma unroll
        for (int kk = 0; kk < 16; kk++) {
            const int f = kk & 1;
            if (kk < 15) LDFRAG128(f^1, kk+1, cur);
#pragma unroll
            for (int i = 0; i < 8; i++) {
                unsigned long long ap = pk2(af[f][i], af[f][i]);
#pragma unroll
                for (int j = 0; j < 4; j++) ffma2(acc2[i][j], ap, bp[f][j]);
            }
        }
        if (pf) {
            As[nxt][akc+0][arow]=va0.x; As[nxt][akc+1][arow]=va0.y;
            As[nxt][akc+2][arow]=va0.z; As[nxt][akc+3][arow]=va0.w;
            As[nxt][akc+4][arow]=va1.x; As[nxt][akc+5][arow]=va1.y;
            As[nxt][akc+6][arow]=va1.z; As[nxt][akc+7][arow]=va1.w;
            cpa_wait0();
            __syncthreads();
            LDFRAG128(0, 0, nxt);
        }
    }

    float bv[8], twv[8], fwv[8];
#pragma unroll
    for (int j = 0; j < 8; j++) {
        int f = tx*8 + j;
        bv[j]  = bias[f];
        twv[j] = tw[f*3 + l];
        fwv[j] = fw[f*3 + l];
    }
#pragma unroll
    for (int i = 0; i < 8; i++) {
        int m = bm + ty*8 + i;
        float vj[8];
#pragma unroll
        for (int j = 0; j < 4; j++) {
            float lo, hi;
            upk2(acc2[i][j], lo, hi);
            vj[2*j]   = fmaxf(lo + bv[2*j],   0.f);
            vj[2*j+1] = fmaxf(hi + bv[2*j+1], 0.f);
        }
        float a = 0.f, c = 0.f;
#pragma unroll
        for (int j = 0; j < 8; j++) { a = fmaf(vj[j], twv[j], a); c = fmaf(vj[j], fwv[j], c); }
#pragma unroll
        for (int off = 8; off; off >>= 1) {
            a += __shfl_down_sync(0xffffffffu, a, off, 16);
            c += __shfl_down_sync(0xffffffffu, c, off, 16);
        }
        if (m < MROWS) {
            if (WRITEC) {
                *(float4*)(C + (size_t)m*HD + tx*8 + 0) = make_float4(vj[0],vj[1],vj[2],vj[3]);
                *(float4*)(C + (size_t)m*HD + tx*8 + 4) = make_float4(vj[4],vj[5],vj[6],vj[7]);
            }
            if (tx == 0) {
                int n = m >> 3, b = m & 7;
                g_sp[b*NG + n] += a;
                g_fd[b*NG + n] += c;
            }
        }
    }
}

// ---------- multi-block bitonic sort + z (1024 threads/block) ----------
__global__ void __launch_bounds__(1024) k_sortz(const float* __restrict__ fcb)
{
    __shared__ unsigned long long sk[2048];
    int bid = blockIdx.x;
    int b = bid >> 3, sub = bid & 7;
    int t = threadIdx.x;
    int base = sub * 2048;
    float invw = g_invw;

    for (int q = 0; q < 2; q++) {
        int li = q*1024 + t, gi = base + li;
        unsigned long long key = 0xFFFFFFFFFFFFFFFFull;
        if (gi < NG) {
            float s = tanhf(g_sp[b*NG + gi] * invw);
            unsigned u = __float_as_uint(s);
            u = (u & 0x80000000u) ? ~u : (u | 0x80000000u);
            key = ((unsigned long long)(~u) << 32) | (unsigned)gi;
        }
        sk[li] = key;
    }
    __syncthreads();

    for (unsigned k = 2; k <= 2048; k <<= 1) {
        for (unsigned j = k >> 1; j > 0; j >>= 1) {
            for (int q = 0; q < 2; q++) {
                int li = q*1024 + t;
                unsigned lixj = li ^ j;
                if (lixj > (unsigned)li) {
                    unsigned long long x = sk[li], y = sk[lixj];
                    bool up = (((base + li) & k) == 0);
                    if ((x > y) == up) { sk[li] = y; sk[lixj] = x; }
                }
            }
            __syncthreads();
        }
    }
    for (int q = 0; q < 2; q++) { int li = q*1024 + t; g_keys[b][base + li] = sk[li]; }
    gsync(SGB);

    for (unsigned k = 4096; k <= 16384; k <<= 1) {
        for (unsigned j = k >> 1; j >= 2048; j >>= 1) {
            unsigned gtid = bid*1024 + t;        // 0..65535
            unsigned bb = gtid >> 13;            // batch
            unsigned p  = gtid & 8191;           // pair id
            unsigned i  = ((p & ~(j-1)) << 1) | (p & (j-1));
            unsigned ixj = i | j;
            unsigned long long x = g_keys[bb][i], y = g_keys[bb][ixj];
            bool up = ((i & k) == 0);
            if ((x > y) == up) { g_keys[bb][i] = y; g_keys[bb][ixj] = x; }
            gsync(SGB);
        }
        for (int q = 0; q < 2; q++) { int li = q*1024 + t; sk[li] = g_keys[b][base + li]; }
        __syncthreads();
        for (unsigned j = 1024; j > 0; j >>= 1) {
            for (int q = 0; q < 2; q++) {
                int li = q*1024 + t;
                unsigned lixj = li ^ j;
                if (lixj > (unsigned)li) {
                    unsigned long long x = sk[li], y = sk[lixj];
                    bool up = (((base + li) & k) == 0);
                    if ((x > y) == up) { sk[li] = y; sk[lixj] = x; }
                }
            }
            __syncthreads();
        }
        if (k < 16384) {
            for (int q = 0; q < 2; q++) { int li = q*1024 + t; g_keys[b][base + li] = sk[li]; }
            gsync(SGB);
        }
    }

    float fb = fcb[0];
    for (int q = 0; q < 2; q++) {
        int li = q*1024 + t, gi = base + li;
        if (gi < KTOP) {
            unsigned idx = (unsigned)sk[li];
            float s = tanhf(g_sp[b*NG + idx] * invw);
            g_z[b*KTOP + gi] = fmaf(s, g_fd[b*NG + idx], fb);
        }
    }
}

__global__ void __launch_bounds__(128) k_lin1(const float* __restrict__ W)
{
    __shared__ float zs[BSZ][128];
    int tid = threadIdx.x;
    int j   = blockIdx.x * 128 + tid;
    int ky  = blockIdx.y;
    int k0  = ky * 128;
    int kn  = KTOP - k0; if (kn > 128) kn = 128;
#pragma unroll
    for (int b = 0; b < BSZ; b++)
        if (tid < kn) zs[b][tid] = g_z[b*KTOP + k0 + tid];
    __syncthreads();
    float acc[BSZ];
#pragma unroll
    for (int b = 0; b < BSZ; b++) acc[b] = 0.f;
    for (int kk = 0; kk < kn; kk++) {
        float wv = __ldg(W + (size_t)(k0+kk)*HF + j);
#pragma unroll
        for (int b = 0; b < BSZ; b++) acc[b] = fmaf(zs[b][kk], wv, acc[b]);
    }
#pragma unroll
    for (int b = 0; b < BSZ; b++) g_hpart[ky][b*HF + j] = acc[b];
}

__global__ void k_lin1red(const float* __restrict__ l1b)
{
    int i = blockIdx.x*256 + threadIdx.x;
    if (i >= BSZ*HF) return;
    float s = l1b[i & (HF-1)];
    for (int p = 0; p < KSPL; p++) s += g_hpart[p][i];
    g_hpre[i] = s;
}

__global__ void k_final(const float* __restrict__ W, const float* __restrict__ bias,
                        float* __restrict__ out)
{
    __shared__ float lg[BSZ][2];
    int w = threadIdx.x >> 5, lane = threadIdx.x & 31;
    int b = w >> 1, c = w & 1;
    float a = 0.f;
    for (int jj = lane; jj < HF; jj += 32) {
        float h = fmaxf(g_hpre[b*HF + jj], 0.f);
        a = fmaf(h, W[jj*2 + c], a);
    }
#pragma unroll
    for (int off = 16; off; off >>= 1) a += __shfl_down_sync(0xffffffffu, a, off);
    if (lane == 0) lg[b][c] = a + bias[c];
    __syncthreads();
    if (threadIdx.x < BSZ) {
        int bb = threadIdx.x;
        float l0 = lg[bb][0], l1 = lg[bb][1];
        float m  = fmaxf(l0, l1);
        float lse = m + logf(expf(l0 - m) + expf(l1 - m));
        out[bb*2 + 0] = l0 - lse;
        out[bb*2 + 1] = l1 - lse;
    }
}

extern "C" void kernel_launch(void* const* d_in, const int* in_sizes, int n_in,
                              void* d_out, int out_size)
{
    const float* x   = (const float*)d_in[0];
    const int*   ei  = (const int*  )d_in[2];
    const float* W1  = (const float*)d_in[3];
    const float* b1  = (const float*)d_in[4];
    const float* W2  = (const float*)d_in[5];
    const float* b2  = (const float*)d_in[6];
    const float* W3  = (const float*)d_in[7];
    const float* b3  = (const float*)d_in[8];
    const float* tw  = (const float*)d_in[9];
    const float* fw  = (const float*)d_in[10];
    const float* fcb = (const float*)d_in[11];
    const float* l1W = (const float*)d_in[12];
    const float* l1b = (const float*)d_in[13];
    const float* l2W = (const float*)d_in[14];
    const float* l2b = (const float*)d_in[15];
    float* out = (float*)d_out;
    int E = in_sizes[2] / 2;

    void *pA_, *pB_, *pC_;
    cudaGetSymbolAddress(&pA_, g_bufA);
    cudaGetSymbolAddress(&pB_, g_bufB);
    cudaGetSymbolAddress(&pC_, g_bufC);
    float* pA = (float*)pA_;
    float* pB = (float*)pB_;
    float* pC = (float*)pC_;

    const int GB64  = (MROWS + 63) / 64;
    const int GB128 = (MROWS + 127) / 128;
    const int EB    = (E + 255) / 256;
    const int NGB   = (NG + 255) / 256;

    k_z       <<<592, 256>>>(tw);                                     // 1
    k_deg     <<<EB, 256>>>(ei, E);                                   // 2
    k_dinvscan<<<64, 256>>>();                                        // 3
    k_scatter <<<EB, 256>>>(ei, E);                                   // 4 <- profiled
    k_sortl   <<<NGB, 256>>>(ei);                                     // 5

    k_spmm<BSZ*FIN, true><<<NG, (BSZ*FIN)/4>>>(x, pA);                // 6
    k_gemm64t<FIN, true><<<GB64, 256>>>(pA, W1, b1, pB, tw, fw, 0);   // 7

    k_spmm<BSZ*HD, false><<<NG, (BSZ*HD)/4>>>(pB, pC);                // 8
    k_gemm128t<HD, true><<<GB128, 256>>>(pC, W2, b2, pA, tw, fw, 1);  // 9

    k_spmm<BSZ*HD, false><<<NG, (BSZ*HD)/4>>>(pA, pC);                // 10
    k_gemm128t<HD, false><<<GB128, 256>>>(pC, W3, b3, pB, tw, fw, 2); // 11

    k_sortz<<<SGB, 1024>>>(fcb);                                      // 12
    {
        dim3 g(HF/128, KSPL);
        k_lin1<<<g, 128>>>(l1W);                                      // 13
    }
    k_lin1red<<<(BSZ*HF + 255)/256, 256>>>(l1b);                      // 14
    k_final  <<<1, 512>>>(l2W, l2b, out);                             // 15
}

// round 17
// speedup vs baseline: 1.3560x; 1.0232x over previous
#include <cuda_runtime.h>
#include <cstdint>

#define NG    15135
#define BSZ   8
#define HD    128
#define FIN   64
#define KTOP  7568
#define MROWS (NG*BSZ)
#define HF    512
#define SORTN 16384
#define MAXD  256
#define KSPL  60
#define LSORT 64

__device__ float g_bufA[(size_t)NG*BSZ*HD];
__device__ float g_bufB[(size_t)NG*BSZ*HD];
__device__ float g_bufC[(size_t)NG*BSZ*HD];
__device__ int   g_degcnt[NG];
__device__ int   g_rowptr[NG+1];
__device__ int   g_cursor[NG];
__device__ int   g_eid[300000];
__device__ int   g_col[300000];
__device__ float g_w  [300000];
__device__ float g_dinv[NG];
__device__ float g_sp [BSZ*NG];
__device__ float g_fd [BSZ*NG];
__device__ float g_z  [BSZ*KTOP];
__device__ float g_hpart[KSPL][BSZ*HF];
__device__ float g_hpre[BSZ*HF];
__device__ float g_invw;
__device__ unsigned long long g_keys[BSZ][SORTN];

// ---------- packed f32x2 (FFMA2) ----------
__device__ __forceinline__ unsigned long long pk2(float lo, float hi)
{
    unsigned long long r;
    asm("mov.b64 %0,{%1,%2};" : "=l"(r) : "f"(lo), "f"(hi));
    return r;
}
__device__ __forceinline__ void upk2(unsigned long long v, float& lo, float& hi)
{
    asm("mov.b64 {%0,%1},%2;" : "=f"(lo), "=f"(hi) : "l"(v));
}
__device__ __forceinline__ void ffma2(unsigned long long& d, unsigned long long a,
                                      unsigned long long b)
{
    asm("fma.rn.f32x2 %0, %1, %2, %0;" : "+l"(d) : "l"(a), "l"(b));
}

// ---------- streaming / async copies ----------
__device__ __forceinline__ float4 ldg_cs4(const float4* p)
{
    float4 v;
    asm("ld.global.cs.v4.f32 {%0,%1,%2,%3},[%4];"
        : "=f"(v.x), "=f"(v.y), "=f"(v.z), "=f"(v.w) : "l"(p));
    return v;
}
__device__ __forceinline__ void stg_cs4(float4* p, float4 v)
{
    asm volatile("st.global.cs.v4.f32 [%0],{%1,%2,%3,%4};"
                 :: "l"(p), "f"(v.x), "f"(v.y), "f"(v.z), "f"(v.w));
}
__device__ __forceinline__ void cpa16(unsigned dst, const void* src)
{
    asm volatile("cp.async.cg.shared.global [%0], [%1], 16;" :: "r"(dst), "l"(src));
}
__device__ __forceinline__ void cpa_commit()
{
    asm volatile("cp.async.commit_group;" ::: "memory");
}
__device__ __forceinline__ void cpa_wait0()
{
    asm volatile("cp.async.wait_group 0;" ::: "memory");
}

// ---------- graph-prep phase kernels ----------
__global__ void __launch_bounds__(256) k_z(const float* __restrict__ tw)
{
    int gt = blockIdx.x*256 + threadIdx.x, gs = gridDim.x*256;
    float4 z4 = make_float4(0.f,0.f,0.f,0.f);
    float4* sp4 = (float4*)g_sp;
    float4* fd4 = (float4*)g_fd;
    for (int i = gt; i < (BSZ*NG)/4; i += gs) { sp4[i] = z4; fd4[i] = z4; }
    for (int i = gt; i < NG; i += gs) { g_degcnt[i] = 0; g_cursor[i] = 0; }
    if (blockIdx.x == gridDim.x - 1) {
        __shared__ float red[256];
        int t = threadIdx.x;
        float w0 = tw[t];
        float v = w0*w0;
        if (t < 128) { float w1 = tw[t+256]; v += w1*w1; }
        red[t] = v;
        __syncthreads();
        for (int off = 128; off; off >>= 1) { if (t < off) red[t] += red[t+off]; __syncthreads(); }
        if (t == 0) g_invw = rsqrtf(red[0]);
    }
}

__global__ void __launch_bounds__(256) k_deg(const int* __restrict__ ei, int E)
{
    int e = blockIdx.x*256 + threadIdx.x;
    if (e < E) atomicAdd(&g_degcnt[ei[E + e]], 1);
}

__global__ void __launch_bounds__(256) k_dinvscan()
{
    if (blockIdx.x == 0) {
        const int C = (NG + 255)/256;
        __shared__ int ws[8];
        int t = threadIdx.x;
        int base = t*C, s = 0;
        for (int i = 0; i < C; i++) { int k2 = base+i; if (k2 < NG) s += g_degcnt[k2]; }
        int lane = t & 31, w = t >> 5, v = s;
        for (int off = 1; off < 32; off <<= 1) {
            int n2 = __shfl_up_sync(0xffffffffu, v, off);
            if (lane >= off) v += n2;
        }
        if (lane == 31) ws[w] = v;
        __syncthreads();
        if (t == 0) {
            int a = 0;
            for (int i2 = 0; i2 < 8; i2++) { int tm = ws[i2]; ws[i2] = a; a += tm; }
            g_rowptr[NG] = a;
        }
        __syncthreads();
        int run = v - s + ws[w];
        for (int i = 0; i < C; i++) {
            int k2 = base+i;
            if (k2 < NG) { g_rowptr[k2] = run; run += g_degcnt[k2]; }
        }
    } else {
        int gt = (blockIdx.x-1)*256 + threadIdx.x, gs = (gridDim.x-1)*256;
        for (int i = gt; i < NG; i += gs) g_dinv[i] = rsqrtf((float)(g_degcnt[i] + 1));
    }
}

__global__ void __launch_bounds__(256) k_scatter(const int* __restrict__ ei, int E)
{
    int e = blockIdx.x*256 + threadIdx.x;
    if (e >= E) return;
    int d = ei[E + e];
    g_eid[g_rowptr[d] + atomicAdd(&g_cursor[d], 1)] = e;
}

__global__ void __launch_bounds__(256) k_sortl(const int* __restrict__ ei)
{
    int n = blockIdx.x*256 + threadIdx.x;
    if (n >= NG) return;
    int e0 = g_rowptr[n], deg = g_rowptr[n+1] - e0;
    float dn = g_dinv[n];
    if (deg <= LSORT) {
        int buf[LSORT];
        for (int i = 0; i < deg; i++) buf[i] = g_eid[e0+i];
        for (int i = 1; i < deg; i++) {
            int key = buf[i], j = i - 1;
            while (j >= 0 && buf[j] > key) { buf[j+1] = buf[j]; j--; }
            buf[j+1] = key;
        }
        for (int i = 0; i < deg; i++) {
            int e = buf[i], s2 = ei[e];
            g_col[e0+i] = s2;
            g_w [e0+i]  = dn * g_dinv[s2];
        }
    } else {
        for (int i = 1; i < deg; i++) {
            int key = g_eid[e0+i], j = i - 1;
            while (j >= 0 && g_eid[e0+j] > key) { g_eid[e0+j+1] = g_eid[e0+j]; j--; }
            g_eid[e0+j+1] = key;
        }
        for (int i = 0; i < deg; i++) {
            int e = g_eid[e0+i], s2 = ei[e];
            g_col[e0+i] = s2;
            g_w [e0+i]  = dn * g_dinv[s2];
        }
    }
}

// ---------- SpMM ----------
template<int FB, bool XIN>
__global__ void __launch_bounds__(FB/4) k_spmm(const float* __restrict__ in,
                                               float* __restrict__ out)
{
    __shared__ int   scol[MAXD];
    __shared__ float swt [MAXD];
    int n = blockIdx.x, t = threadIdx.x;
    int e0 = g_rowptr[n], e1 = g_rowptr[n+1];
    int deg = e1 - e0;
    int dstage = deg < MAXD ? deg : MAXD;
    for (int i = t; i < dstage; i += FB/4) { scol[i] = g_col[e0+i]; swt[i] = g_w[e0+i]; }
    __syncthreads();

    size_t roff;
    if (XIN) {
        int b = t >> 4, f4 = t & 15;
        roff = (size_t)b * NG * 16 + f4;
    }
    const float4* in4 = (const float4*)in;

#define SRC4(s) (XIN ? __ldg(in4 + roff + (size_t)(s)*16) \
                     : __ldg(in4 + (size_t)(s)*(FB/4) + t))

    float dn = g_dinv[n];
    float wl = dn * dn;
    float4 v = SRC4(n);
    float4 acc = make_float4(wl*v.x, wl*v.y, wl*v.z, wl*v.w);

    int i = 0;
    for (; i + 1 < dstage; i += 2) {
        int s0 = scol[i], s1 = scol[i+1];
        float w0 = swt[i], w1 = swt[i+1];
        float4 u0 = SRC4(s0);
        float4 u1 = SRC4(s1);
        acc.x = fmaf(w0,u0.x,acc.x); acc.y = fmaf(w0,u0.y,acc.y);
        acc.z = fmaf(w0,u0.z,acc.z); acc.w = fmaf(w0,u0.w,acc.w);
        acc.x = fmaf(w1,u1.x,acc.x); acc.y = fmaf(w1,u1.y,acc.y);
        acc.z = fmaf(w1,u1.z,acc.z); acc.w = fmaf(w1,u1.w,acc.w);
    }
    for (; i < dstage; i++) {
        int s0 = scol[i]; float w0 = swt[i];
        float4 u0 = SRC4(s0);
        acc.x = fmaf(w0,u0.x,acc.x); acc.y = fmaf(w0,u0.y,acc.y);
        acc.z = fmaf(w0,u0.z,acc.z); acc.w = fmaf(w0,u0.w,acc.w);
    }
    for (int e = e0 + MAXD; e < e1; e++) {
        int s0 = g_col[e]; float w0 = g_w[e];
        float4 u0 = SRC4(s0);
        acc.x = fmaf(w0,u0.x,acc.x); acc.y = fmaf(w0,u0.y,acc.y);
        acc.z = fmaf(w0,u0.z,acc.z); acc.w = fmaf(w0,u0.w,acc.w);
    }
#undef SRC4
    stg_cs4((float4*)(out + (size_t)n*FB) + t, acc);
}

// ---------- GEMM A: 64x128 tile, 4x8/thread, 3 CTA/SM (KDIM=64) ----------
#define LDB64(f, kk, cur) do { \
    const char* _br = (const char*)&Bs[cur][kk][0]; \
    ulonglong2 _b0 = *(const ulonglong2*)(_br + swb0); \
    ulonglong2 _b1 = *(const ulonglong2*)(_br + swb1); \
    bp[f][0]=_b0.x; bp[f][1]=_b0.y; bp[f][2]=_b1.x; bp[f][3]=_b1.y; \
} while(0)

template<int KDIM, bool WRITEC>
__global__ void __launch_bounds__(256, 3) k_gemm64t(const float* __restrict__ A,
                                                    const float* __restrict__ W,
                                                    const float* __restrict__ bias,
                                                    float* __restrict__ C,
                                                    const float* __restrict__ tw,
                                                    const float* __restrict__ fw, int l)
{
    __shared__ __align__(16) float As[2][16][68];
    __shared__ __align__(16) float Bs[2][16][128];
    const int tid = threadIdx.x;
    const int bm  = blockIdx.x * 64;
    const int tx  = tid & 15, ty = tid >> 4;
    const int arow = tid >> 2, akc = (tid & 3) * 4;
    const int brow = tid >> 4, bgr  = (tid & 15) * 2;

    const int swb0 = (( 2*tx   ) ^ (( 2*tx   ) >> 3)) * 16;
    const int swb1 = (( 2*tx+1 ) ^ (( 2*tx+1 ) >> 3)) * 16;
    const int bgs0 = (bgr ^ (bgr >> 3)) * 16;
    const int bgs1 = ((bgr+1) ^ ((bgr+1) >> 3)) * 16;

    unsigned long long acc2[4][4];
#pragma unroll
    for (int i = 0; i < 4; i++)
#pragma unroll
        for (int j = 0; j < 4; j++) acc2[i][j] = 0ull;

    int am = bm + arow;
    if (am >= MROWS) am = MROWS - 1;
    const float* Aptr = A + (size_t)am*KDIM + akc;
    const float* Wptr = W + (size_t)brow*HD + bgr*4;
    unsigned brow_sm[2];
    brow_sm[0] = (unsigned)__cvta_generic_to_shared(&Bs[0][brow][0]);
    brow_sm[1] = (unsigned)__cvta_generic_to_shared(&Bs[1][brow][0]);

    {
        float4 va = ldg_cs4((const float4*)Aptr);
        cpa16(brow_sm[0]+bgs0, Wptr);
        cpa16(brow_sm[0]+bgs1, Wptr+4);
        cpa_commit();
        As[0][akc+0][arow]=va.x; As[0][akc+1][arow]=va.y;
        As[0][akc+2][arow]=va.z; As[0][akc+3][arow]=va.w;
        cpa_wait0();
    }
    __syncthreads();

    unsigned long long bp[2][4];
    LDB64(0, 0, 0);

    const int ntiles = KDIM/16;
    for (int t = 0; t < ntiles; t++) {
        const int cur = t & 1, nxt = cur ^ 1;
        const bool pf = (t + 1 < ntiles);
        float4 va;
        if (pf) {
            va = ldg_cs4((const float4*)(Aptr + (t+1)*16));
            const float* wp2 = Wptr + (size_t)(t+1)*16*HD;
            cpa16(brow_sm[nxt]+bgs0, wp2);
            cpa16(brow_sm[nxt]+bgs1, wp2+4);
            cpa_commit();
        }
#pragma unroll
        for (int kk = 0; kk < 16; kk++) {
            const int f = kk & 1;
            if (kk < 15) LDB64(f^1, kk+1, cur);
            float4 av = *(const float4*)&As[cur][kk][ty*4];
            unsigned long long a0 = pk2(av.x, av.x);
            unsigned long long a1 = pk2(av.y, av.y);
            unsigned long long a2 = pk2(av.z, av.z);
            unsigned long long a3 = pk2(av.w, av.w);
#pragma unroll
            for (int j = 0; j < 4; j++) ffma2(acc2[0][j], a0, bp[f][j]);
#pragma unroll
            for (int j = 0; j < 4; j++) ffma2(acc2[1][j], a1, bp[f][j]);
#pragma unroll
            for (int j = 0; j < 4; j++) ffma2(acc2[2][j], a2, bp[f][j]);
#pragma unroll
            for (int j = 0; j < 4; j++) ffma2(acc2[3][j], a3, bp[f][j]);
        }
        if (pf) {
            As[nxt][akc+0][arow]=va.x; As[nxt][akc+1][arow]=va.y;
            As[nxt][akc+2][arow]=va.z; As[nxt][akc+3][arow]=va.w;
            cpa_wait0();
            __syncthreads();
            LDB64(0, 0, nxt);
        }
    }

    float bv[8], twv[8], fwv[8];
#pragma unroll
    for (int j = 0; j < 8; j++) {
        int f = tx*8 + j;
        bv[j]  = bias[f];
        twv[j] = tw[f*3 + l];
        fwv[j] = fw[f*3 + l];
    }
#pragma unroll
    for (int i = 0; i < 4; i++) {
        int m = bm + ty*4 + i;
        float vj[8];
#pragma unroll
        for (int j = 0; j < 4; j++) {
            float lo, hi;
            upk2(acc2[i][j], lo, hi);
            vj[2*j]   = fmaxf(lo + bv[2*j],   0.f);
            vj[2*j+1] = fmaxf(hi + bv[2*j+1], 0.f);
        }
        float a = 0.f, c = 0.f;
#pragma unroll
        for (int j = 0; j < 8; j++) { a = fmaf(vj[j], twv[j], a); c = fmaf(vj[j], fwv[j], c); }
#pragma unroll
        for (int off = 8; off; off >>= 1) {
            a += __shfl_down_sync(0xffffffffu, a, off, 16);
            c += __shfl_down_sync(0xffffffffu, c, off, 16);
        }
        if (m < MROWS) {
            if (WRITEC) {
                *(float4*)(C + (size_t)m*HD + tx*8 + 0) = make_float4(vj[0],vj[1],vj[2],vj[3]);
                *(float4*)(C + (size_t)m*HD + tx*8 + 4) = make_float4(vj[4],vj[5],vj[6],vj[7]);
            }
            if (tx == 0) {
                int n = m >> 3, b = m & 7;
                g_sp[b*NG + n] += a;
                g_fd[b*NG + n] += c;
            }
        }
    }
}

// ---------- GEMM B: 128x128 tile, 8x8/thread, 2 CTA/SM (KDIM=128) ----------
#define LDFRAG128(f, kk, cur) do { \
    const float4* _a = (const float4*)&As[cur][kk][ty*8]; \
    float4 _v0 = _a[0], _v1 = _a[1]; \
    af[f][0]=_v0.x; af[f][1]=_v0.y; af[f][2]=_v0.z; af[f][3]=_v0.w; \
    af[f][4]=_v1.x; af[f][5]=_v1.y; af[f][6]=_v1.z; af[f][7]=_v1.w; \
    const char* _br = (const char*)&Bs[cur][kk][0]; \
    ulonglong2 _b0 = *(const ulonglong2*)(_br + swb0); \
    ulonglong2 _b1 = *(const ulonglong2*)(_br + swb1); \
    bp[f][0]=_b0.x; bp[f][1]=_b0.y; bp[f][2]=_b1.x; bp[f][3]=_b1.y; \
} while(0)

template<int KDIM, bool WRITEC>
__global__ void __launch_bounds__(256, 2) k_gemm128t(const float* __restrict__ A,
                                                     const float* __restrict__ W,
                                                     const float* __restrict__ bias,
                                                     float* __restrict__ C,
                                                     const float* __restrict__ tw,
                                                     const float* __restrict__ fw, int l)
{
    __shared__ float As[2][16][136];
    __shared__ float Bs[2][16][128];
    const int tid = threadIdx.x;
    const int bm  = blockIdx.x * 128;
    const int tx  = tid & 15, ty = tid >> 4;
    const int arow = tid >> 1, akc = (tid & 1) * 8;
    const int brow = tid >> 4, bgr  = (tid & 15) * 2;

    const int swb0 = (( 2*tx   ) ^ (( 2*tx   ) >> 3)) * 16;
    const int swb1 = (( 2*tx+1 ) ^ (( 2*tx+1 ) >> 3)) * 16;
    const int bgs0 = (bgr ^ (bgr >> 3)) * 16;
    const int bgs1 = ((bgr+1) ^ ((bgr+1) >> 3)) * 16;

    unsigned long long acc2[8][4];
#pragma unroll
    for (int i = 0; i < 8; i++)
#pragma unroll
        for (int j = 0; j < 4; j++) acc2[i][j] = 0ull;

    int am = bm + arow;
    if (am >= MROWS) am = MROWS - 1;
    const float* Aptr = A + (size_t)am*KDIM + akc;
    const float* Wptr = W + (size_t)brow*HD + bgr*4;
    unsigned brow_sm[2];
    brow_sm[0] = (unsigned)__cvta_generic_to_shared(&Bs[0][brow][0]);
    brow_sm[1] = (unsigned)__cvta_generic_to_shared(&Bs[1][brow][0]);

    {
        float4 va0 = ldg_cs4((const float4*)Aptr);
        float4 va1 = ldg_cs4((const float4*)(Aptr+4));
        cpa16(brow_sm[0]+bgs0, Wptr);
        cpa16(brow_sm[0]+bgs1, Wptr+4);
        cpa_commit();
        As[0][akc+0][arow]=va0.x; As[0][akc+1][arow]=va0.y;
        As[0][akc+2][arow]=va0.z; As[0][akc+3][arow]=va0.w;
        As[0][akc+4][arow]=va1.x; As[0][akc+5][arow]=va1.y;
        As[0][akc+6][arow]=va1.z; As[0][akc+7][arow]=va1.w;
        cpa_wait0();
    }
    __syncthreads();

    float af[2][8];
    unsigned long long bp[2][4];
    LDFRAG128(0, 0, 0);

    const int ntiles = KDIM/16;
    for (int t = 0; t < ntiles; t++) {
        const int cur = t & 1, nxt = cur ^ 1;
        const bool pf = (t + 1 < ntiles);
        float4 va0, va1;
        if (pf) {
            const float* ap2 = Aptr + (t+1)*16;
            va0 = ldg_cs4((const float4*)ap2);
            va1 = ldg_cs4((const float4*)(ap2+4));
            const float* wp2 = Wptr + (size_t)(t+1)*16*HD;
            cpa16(brow_sm[nxt]+bgs0, wp2);
            cpa16(brow_sm[nxt]+bgs1, wp2+4);
            cpa_commit();
        }
#pragma unroll
        for (int kk = 0; kk < 16; kk++) {
            const int f = kk & 1;
            if (kk < 15) LDFRAG128(f^1, kk+1, cur);
#pragma unroll
            for (int i = 0; i < 8; i++) {
                unsigned long long ap = pk2(af[f][i], af[f][i]);
#pragma unroll
                for (int j = 0; j < 4; j++) ffma2(acc2[i][j], ap, bp[f][j]);
            }
        }
        if (pf) {
            As[nxt][akc+0][arow]=va0.x; As[nxt][akc+1][arow]=va0.y;
            As[nxt][akc+2][arow]=va0.z; As[nxt][akc+3][arow]=va0.w;
            As[nxt][akc+4][arow]=va1.x; As[nxt][akc+5][arow]=va1.y;
            As[nxt][akc+6][arow]=va1.z; As[nxt][akc+7][arow]=va1.w;
            cpa_wait0();
            __syncthreads();
            LDFRAG128(0, 0, nxt);
        }
    }

    float bv[8], twv[8], fwv[8];
#pragma unroll
    for (int j = 0; j < 8; j++) {
        int f = tx*8 + j;
        bv[j]  = bias[f];
        twv[j] = tw[f*3 + l];
        fwv[j] = fw[f*3 + l];
    }
#pragma unroll
    for (int i = 0; i < 8; i++) {
        int m = bm + ty*8 + i;
        float vj[8];
#pragma unroll
        for (int j = 0; j < 4; j++) {
            float lo, hi;
            upk2(acc2[i][j], lo, hi);
            vj[2*j]   = fmaxf(lo + bv[2*j],   0.f);
            vj[2*j+1] = fmaxf(hi + bv[2*j+1], 0.f);
        }
        float a = 0.f, c = 0.f;
#pragma unroll
        for (int j = 0; j < 8; j++) { a = fmaf(vj[j], twv[j], a); c = fmaf(vj[j], fwv[j], c); }
#pragma unroll
        for (int off = 8; off; off >>= 1) {
            a += __shfl_down_sync(0xffffffffu, a, off, 16);
            c += __shfl_down_sync(0xffffffffu, c, off, 16);
        }
        if (m < MROWS) {
            if (WRITEC) {
                *(float4*)(C + (size_t)m*HD + tx*8 + 0) = make_float4(vj[0],vj[1],vj[2],vj[3]);
                *(float4*)(C + (size_t)m*HD + tx*8 + 4) = make_float4(vj[4],vj[5],vj[6],vj[7]);
            }
            if (tx == 0) {
                int n = m >> 3, b = m & 7;
                g_sp[b*NG + n] += a;
                g_fd[b*NG + n] += c;
            }
        }
    }
}

// ---------- top-k sort: local + per-step kernels (no device barriers) ----------
__global__ void __launch_bounds__(1024) k_sloc()
{
    __shared__ unsigned long long sk[2048];
    int bid = blockIdx.x;
    int b = bid >> 3, sub = bid & 7;
    int t = threadIdx.x;
    int base = sub * 2048;
    float invw = g_invw;

    for (int q = 0; q < 2; q++) {
        int li = q*1024 + t, gi = base + li;
        unsigned long long key = 0xFFFFFFFFFFFFFFFFull;
        if (gi < NG) {
            float s = tanhf(g_sp[b*NG + gi] * invw);
            unsigned u = __float_as_uint(s);
            u = (u & 0x80000000u) ? ~u : (u | 0x80000000u);
            key = ((unsigned long long)(~u) << 32) | (unsigned)gi;
        }
        sk[li] = key;
    }
    __syncthreads();

    for (unsigned k = 2; k <= 2048; k <<= 1) {
        for (unsigned j = k >> 1; j > 0; j >>= 1) {
            for (int q = 0; q < 2; q++) {
                int li = q*1024 + t;
                unsigned lixj = li ^ j;
                if (lixj > (unsigned)li) {
                    unsigned long long x = sk[li], y = sk[lixj];
                    bool up = (((base + li) & k) == 0);
                    if ((x > y) == up) { sk[li] = y; sk[lixj] = x; }
                }
            }
            __syncthreads();
        }
    }
    for (int q = 0; q < 2; q++) { int li = q*1024 + t; g_keys[b][base + li] = sk[li]; }
}

__global__ void __launch_bounds__(256) k_gstep(unsigned k, unsigned j)
{
    unsigned gtid = blockIdx.x*256 + threadIdx.x;   // 0..65535
    unsigned bb = gtid >> 13;
    unsigned p  = gtid & 8191;
    unsigned i  = ((p & ~(j-1)) << 1) | (p & (j-1));
    unsigned ixj = i | j;
    unsigned long long x = g_keys[bb][i], y = g_keys[bb][ixj];
    bool up = ((i & k) == 0);
    if ((x > y) == up) { g_keys[bb][i] = y; g_keys[bb][ixj] = x; }
}

template<bool FINAL>
__global__ void __launch_bounds__(1024) k_stail(unsigned k, const float* __restrict__ fcb)
{
    __shared__ unsigned long long sk[2048];
    int bid = blockIdx.x;
    int b = bid >> 3, sub = bid & 7;
    int t = threadIdx.x;
    int base = sub * 2048;

    for (int q = 0; q < 2; q++) { int li = q*1024 + t; sk[li] = g_keys[b][base + li]; }
    __syncthreads();
    for (unsigned j = 1024; j > 0; j >>= 1) {
        for (int q = 0; q < 2; q++) {
            int li = q*1024 + t;
            unsigned lixj = li ^ j;
            if (lixj > (unsigned)li) {
                unsigned long long x = sk[li], y = sk[lixj];
                bool up = (((base + li) & k) == 0);
                if ((x > y) == up) { sk[li] = y; sk[lixj] = x; }
            }
        }
        __syncthreads();
    }
    if (FINAL) {
        float invw = g_invw;
        float fb = fcb[0];
        for (int q = 0; q < 2; q++) {
            int li = q*1024 + t, gi = base + li;
            if (gi < KTOP) {
                unsigned idx = (unsigned)sk[li];
                float s = tanhf(g_sp[b*NG + idx] * invw);
                g_z[b*KTOP + gi] = fmaf(s, g_fd[b*NG + idx], fb);
            }
        }
    } else {
        for (int q = 0; q < 2; q++) { int li = q*1024 + t; g_keys[b][base + li] = sk[li]; }
    }
}

__global__ void __launch_bounds__(128) k_lin1(const float* __restrict__ W)
{
    __shared__ float zs[BSZ][128];
    int tid = threadIdx.x;
    int j   = blockIdx.x * 128 + tid;
    int ky  = blockIdx.y;
    int k0  = ky * 128;
    int kn  = KTOP - k0; if (kn > 128) kn = 128;
#pragma unroll
    for (int b = 0; b < BSZ; b++)
        if (tid < kn) zs[b][tid] = g_z[b*KTOP + k0 + tid];
    __syncthreads();
    float acc[BSZ];
#pragma unroll
    for (int b = 0; b < BSZ; b++) acc[b] = 0.f;
    for (int kk = 0; kk < kn; kk++) {
        float wv = __ldg(W + (size_t)(k0+kk)*HF + j);
#pragma unroll
        for (int b = 0; b < BSZ; b++) acc[b] = fmaf(zs[b][kk], wv, acc[b]);
    }
#pragma unroll
    for (int b = 0; b < BSZ; b++) g_hpart[ky][b*HF + j] = acc[b];
}

__global__ void k_lin1red(const float* __restrict__ l1b)
{
    int i = blockIdx.x*256 + threadIdx.x;
    if (i >= BSZ*HF) return;
    float s = l1b[i & (HF-1)];
    for (int p = 0; p < KSPL; p++) s += g_hpart[p][i];
    g_hpre[i] = s;
}

__global__ void k_final(const float* __restrict__ W, const float* __restrict__ bias,
                        float* __restrict__ out)
{
    __shared__ float lg[BSZ][2];
    int w = threadIdx.x >> 5, lane = threadIdx.x & 31;
    int b = w >> 1, c = w & 1;
    float a = 0.f;
    for (int jj = lane; jj < HF; jj += 32) {
        float h = fmaxf(g_hpre[b*HF + jj], 0.f);
        a = fmaf(h, W[jj*2 + c], a);
    }
#pragma unroll
    for (int off = 16; off; off >>= 1) a += __shfl_down_sync(0xffffffffu, a, off);
    if (lane == 0) lg[b][c] = a + bias[c];
    __syncthreads();
    if (threadIdx.x < BSZ) {
        int bb = threadIdx.x;
        float l0 = lg[bb][0], l1 = lg[bb][1];
        float m  = fmaxf(l0, l1);
        float lse = m + logf(expf(l0 - m) + expf(l1 - m));
        out[bb*2 + 0] = l0 - lse;
        out[bb*2 + 1] = l1 - lse;
    }
}

extern "C" void kernel_launch(void* const* d_in, const int* in_sizes, int n_in,
                              void* d_out, int out_size)
{
    const float* x   = (const float*)d_in[0];
    const int*   ei  = (const int*  )d_in[2];
    const float* W1  = (const float*)d_in[3];
    const float* b1  = (const float*)d_in[4];
    const float* W2  = (const float*)d_in[5];
    const float* b2  = (const float*)d_in[6];
    const float* W3  = (const float*)d_in[7];
    const float* b3  = (const float*)d_in[8];
    const float* tw  = (const float*)d_in[9];
    const float* fw  = (const float*)d_in[10];
    const float* fcb = (const float*)d_in[11];
    const float* l1W = (const float*)d_in[12];
    const float* l1b = (const float*)d_in[13];
    const float* l2W = (const float*)d_in[14];
    const float* l2b = (const float*)d_in[15];
    float* out = (float*)d_out;
    int E = in_sizes[2] / 2;

    void *pA_, *pB_, *pC_;
    cudaGetSymbolAddress(&pA_, g_bufA);
    cudaGetSymbolAddress(&pB_, g_bufB);
    cudaGetSymbolAddress(&pC_, g_bufC);
    float* pA = (float*)pA_;
    float* pB = (float*)pB_;
    float* pC = (float*)pC_;

    const int GB64  = (MROWS + 63) / 64;
    const int GB128 = (MROWS + 127) / 128;
    const int EB    = (E + 255) / 256;
    const int NGB   = (NG + 255) / 256;

    k_z       <<<592, 256>>>(tw);
    k_deg     <<<EB, 256>>>(ei, E);
    k_dinvscan<<<64, 256>>>();
    k_scatter <<<EB, 256>>>(ei, E);
    k_sortl   <<<NGB, 256>>>(ei);

    k_spmm<BSZ*FIN, true><<<NG, (BSZ*FIN)/4>>>(x, pA);
    k_gemm64t<FIN, true><<<GB64, 256>>>(pA, W1, b1, pB, tw, fw, 0);

    k_spmm<BSZ*HD, false><<<NG, (BSZ*HD)/4>>>(pB, pC);
    k_gemm128t<HD, true><<<GB128, 256>>>(pC, W2, b2, pA, tw, fw, 1);

    k_spmm<BSZ*HD, false><<<NG, (BSZ*HD)/4>>>(pA, pC);
    k_gemm128t<HD, false><<<GB128, 256>>>(pC, W3, b3, pB, tw, fw, 2);

    // top-k: local sort, then explicit global bitonic steps as kernels
    k_sloc<<<64, 1024>>>();
    k_gstep<<<256, 256>>>(4096, 2048);
    k_stail<false><<<64, 1024>>>(4096, fcb);
    k_gstep<<<256, 256>>>(8192, 4096);
    k_gstep<<<256, 256>>>(8192, 2048);
    k_stail<false><<<64, 1024>>>(8192, fcb);
    k_gstep<<<256, 256>>>(16384, 8192);
    k_gstep<<<256, 256>>>(16384, 4096);
    k_gstep<<<256, 256>>>(16384, 2048);
    k_stail<true><<<64, 1024>>>(16384, fcb);

    {
        dim3 g(HF/128, KSPL);
        k_lin1<<<g, 128>>>(l1W);
    }
    k_lin1red<<<(BSZ*HF + 255)/256, 256>>>(l1b);
    k_final  <<<1, 512>>>(l2W, l2b, out);
}